// round 10
// baseline (speedup 1.0000x reference)
#include <cuda_runtime.h>
#include <cstdint>
#include <cstddef>

#define NMAX 100000
#define NEMAX 600000
#define FDIM 128

// ---- static device scratch (no allocations allowed) ----
__device__ int   g_deg[NMAX];
__device__ int   g_off[NMAX + 1];
__device__ int   g_pos[NMAX];
__device__ int   g_cum[256];
__device__ int   g_flag[256];
__device__ int   g_csrc[NEMAX];
__device__ float g_dinv[NMAX];
__device__ float g_b0[NMAX * FDIM];   // y (layer1 out / residual)
__device__ float g_b1[NMAX * FDIM];   // G0 / reuse
__device__ float g_b2[NMAX * FDIM];   // G1
__device__ float g_b3[NMAX * FDIM];   // m1
__device__ float g_w1t[128 * 384];
__device__ float g_w3t[128 * 384];

__device__ __forceinline__ uint32_t f2tf32(float x) {
    uint32_t r;
    asm("cvt.rna.tf32.f32 %0, %1;" : "=r"(r) : "f"(x));
    return r;
}

// ======================= CSR build =======================
__global__ void k_degi(const int* __restrict__ dst, int ne, int* __restrict__ deg) {
    int i = blockIdx.x * blockDim.x + threadIdx.x;
    if (i < ne) atomicAdd(&deg[dst[i]], 1);
}

// single-kernel chained scan: off (exclusive), pos copy, dinv, total.
// flags are zeroed by a memset node before this launch; all 196 blocks co-resident.
__global__ void __launch_bounds__(512)
k_scan_chain(const int* __restrict__ deg, int n,
             int* __restrict__ off, int* __restrict__ pos,
             float* __restrict__ dinv,
             int* __restrict__ cum, int* __restrict__ flag) {
    __shared__ int sh[512];
    __shared__ int s_prefix;
    const int tid = threadIdx.x;
    const int b = blockIdx.x;
    const int i = b * 512 + tid;
    int v = (i < n) ? deg[i] : 0;
    if (i < n) dinv[i] = rsqrtf((float)(v > 1 ? v : 1));
    sh[tid] = v;
    __syncthreads();
    #pragma unroll
    for (int ofs = 1; ofs < 512; ofs <<= 1) {
        int t = (tid >= ofs) ? sh[tid - ofs] : 0;
        __syncthreads();
        sh[tid] += t;
        __syncthreads();
    }
    const int incl = sh[tid];
    const int total = sh[511];
    if (tid == 0) {
        int prefix = 0;
        if (b > 0) {
            while (((volatile int*)flag)[b - 1] == 0) { }
            prefix = ((volatile int*)cum)[b - 1];
        }
        s_prefix = prefix;
        ((volatile int*)cum)[b] = prefix + total;
        __threadfence();
        ((volatile int*)flag)[b] = 1;
    }
    __syncthreads();
    const int p = s_prefix;
    if (i < n) {
        int e = incl - v + p;
        off[i] = e;
        pos[i] = e;
        if (i == n - 1) off[n] = incl + p;
    }
}

__global__ void k_bucket(const int* __restrict__ src, const int* __restrict__ dst, int ne,
                         int* __restrict__ pos, int* __restrict__ csrc) {
    int e = blockIdx.x * blockDim.x + threadIdx.x;
    if (e < ne) {
        int p = atomicAdd(&pos[dst[e]], 1);
        csrc[p] = src[e];
    }
}

// ======================= weight transform (both layers in one launch) =======================
// W [128,384] = [W0|W1|W2] -> W' = [W0-W1+W2 | W1-4W2 | 2W2]
__global__ void k_wt2(const float* __restrict__ WA, float* __restrict__ WtA,
                      const float* __restrict__ WB, float* __restrict__ WtB) {
    int i = blockIdx.x * blockDim.x + threadIdx.x;
    if (i >= 2 * 128 * 128) return;
    const float* W = (i < 128 * 128) ? WA : WB;
    float* Wt      = (i < 128 * 128) ? WtA : WtB;
    i &= (128 * 128 - 1);
    int o = i >> 7, k = i & 127;
    float w0 = W[o * 384 + k];
    float w1 = W[o * 384 + 128 + k];
    float w2 = W[o * 384 + 256 + k];
    Wt[o * 384 + k]       = w0 - w1 + w2;
    Wt[o * 384 + 128 + k] = w1 - 4.0f * w2;
    Wt[o * 384 + 256 + k] = 2.0f * w2;
}

// ======================= pure A_hat application =======================
// Xout[v] = (sum_{s in N(v)} Xin[s]*dinv[s]) * dinv[v]   — warp per node, 4-way unrolled
__global__ void __launch_bounds__(512)
k_ahat(const float* __restrict__ Xin,
       const float* __restrict__ dinv,
       const int* __restrict__ off, const int* __restrict__ csrc,
       float* __restrict__ Xout, int n) {
    int v = blockIdx.x * 16 + (threadIdx.x >> 5);
    if (v >= n) return;
    int lane = threadIdx.x & 31;
    int beg = __ldg(&off[v]);
    int end = __ldg(&off[v + 1]);

    float4 acc = make_float4(0.f, 0.f, 0.f, 0.f);
    int j = beg;
    for (; j + 4 <= end; j += 4) {
        int s0 = __ldg(&csrc[j]);
        int s1 = __ldg(&csrc[j + 1]);
        int s2 = __ldg(&csrc[j + 2]);
        int s3 = __ldg(&csrc[j + 3]);
        float c0 = __ldg(&dinv[s0]);
        float c1 = __ldg(&dinv[s1]);
        float c2 = __ldg(&dinv[s2]);
        float c3 = __ldg(&dinv[s3]);
        float4 x0 = *(const float4*)(Xin + (size_t)s0 * FDIM + lane * 4);
        float4 x1 = *(const float4*)(Xin + (size_t)s1 * FDIM + lane * 4);
        float4 x2 = *(const float4*)(Xin + (size_t)s2 * FDIM + lane * 4);
        float4 x3 = *(const float4*)(Xin + (size_t)s3 * FDIM + lane * 4);
        acc.x += x0.x * c0 + x1.x * c1 + x2.x * c2 + x3.x * c3;
        acc.y += x0.y * c0 + x1.y * c1 + x2.y * c2 + x3.y * c3;
        acc.z += x0.z * c0 + x1.z * c1 + x2.z * c2 + x3.z * c3;
        acc.w += x0.w * c0 + x1.w * c1 + x2.w * c2 + x3.w * c3;
    }
    for (; j < end; j++) {
        int s = __ldg(&csrc[j]);
        float c = __ldg(&dinv[s]);
        float4 x = *(const float4*)(Xin + (size_t)s * FDIM + lane * 4);
        acc.x += x.x * c;
        acc.y += x.y * c;
        acc.z += x.z * c;
        acc.w += x.w * c;
    }
    float dv = __ldg(&dinv[v]);
    float4 r = make_float4(acc.x * dv, acc.y * dv, acc.z * dv, acc.w * dv);
    *(float4*)(Xout + (size_t)v * FDIM + lane * 4) = r;
}

// ============== tf32 mma.sync GEMM: C[256-tile, NT] = [A0|A1|A2] @ W[NT,K]^T + epilogue ==============
#define EPI_BIAS     0
#define EPI_RELU_BN  1
#define EPI_RELU_RES 2
#define EPI_RELU     3

__device__ __forceinline__ void mma8(float c[4], const uint32_t a[4], uint32_t b0, uint32_t b1) {
    asm volatile(
        "mma.sync.aligned.m16n8k8.row.col.f32.tf32.tf32.f32 "
        "{%0,%1,%2,%3}, {%4,%5,%6,%7}, {%8,%9}, {%0,%1,%2,%3};"
        : "+f"(c[0]), "+f"(c[1]), "+f"(c[2]), "+f"(c[3])
        : "r"(a[0]), "r"(a[1]), "r"(a[2]), "r"(a[3]), "r"(b0), "r"(b1));
}

template<int NT, int EPI>
__global__ void __launch_bounds__(256, 1)
k_gemm_tc(const float* __restrict__ A0, const float* __restrict__ A1, const float* __restrict__ A2,
          int M, int K,
          const float* __restrict__ W,
          const float* __restrict__ bias,
          const float* __restrict__ gmm, const float* __restrict__ bet,
          const float* __restrict__ mu,  const float* __restrict__ var,
          const float* __restrict__ res,
          float* __restrict__ C, int ldc) {
    extern __shared__ float sm[];
    float* const AsBase = sm;                     // 2 * 256 * 36
    float* const BsBase = sm + 2 * 256 * 36;      // 2 * NT * 36

    const int tid  = threadIdx.x;
    const int wid  = tid >> 5;
    const int lane = tid & 31;
    const int gID  = lane >> 2;
    const int tig  = lane & 3;
    const int m0   = blockIdx.x * 256;

    const int wm = (wid & 3) * 64;
    const int wn = (wid >> 2) * (NT / 2);
    constexpr int NTILES = NT / 16;
    constexpr int BITER  = NT / 32;

    float c[4][NTILES][4];
    #pragma unroll
    for (int i = 0; i < 4; i++)
        #pragma unroll
        for (int j = 0; j < NTILES; j++)
            #pragma unroll
            for (int q = 0; q < 4; q++) c[i][j][q] = 0.0f;

    const int nch = K >> 5;

    float4 ra[8];
    float4 rb[BITER];

    auto load_regs = [&](int kt) {
        const float* Ap = (kt < 128) ? A0 : ((kt < 256) ? A1 : A2);
        const int kk = kt & 127;
        #pragma unroll
        for (int it = 0; it < 8; it++) {
            int i = tid + it * 256;
            int row = i >> 3, q = i & 7;
            int gm = m0 + row;
            ra[it] = (gm < M) ? *(const float4*)(Ap + (size_t)gm * FDIM + kk + q * 4)
                              : make_float4(0.f, 0.f, 0.f, 0.f);
        }
        #pragma unroll
        for (int it = 0; it < BITER; it++) {
            int i = tid + it * 256;
            int row = i >> 3, q = i & 7;
            rb[it] = *(const float4*)(W + (size_t)row * K + kt + q * 4);
        }
    };
    auto store_tiles = [&](int buf) {
        float* As = AsBase + buf * (256 * 36);
        float* Bs = BsBase + buf * (NT * 36);
        #pragma unroll
        for (int it = 0; it < 8; it++) {
            int i = tid + it * 256;
            int row = i >> 3, q = i & 7;
            uint4 t = make_uint4(f2tf32(ra[it].x), f2tf32(ra[it].y), f2tf32(ra[it].z), f2tf32(ra[it].w));
            *(uint4*)(As + row * 36 + q * 4) = t;
        }
        #pragma unroll
        for (int it = 0; it < BITER; it++) {
            int i = tid + it * 256;
            int row = i >> 3, q = i & 7;
            uint4 t = make_uint4(f2tf32(rb[it].x), f2tf32(rb[it].y), f2tf32(rb[it].z), f2tf32(rb[it].w));
            *(uint4*)(Bs + row * 36 + q * 4) = t;
        }
    };

    load_regs(0);
    store_tiles(0);
    __syncthreads();

    for (int ch = 0; ch < nch; ch++) {
        const int buf = ch & 1;
        const bool more = (ch + 1 < nch);
        if (more) load_regs((ch + 1) << 5);

        const float* As = AsBase + buf * (256 * 36);
        const float* Bs = BsBase + buf * (NT * 36);

        #pragma unroll
        for (int ks = 0; ks < 32; ks += 8) {
            uint32_t a[4][4];
            #pragma unroll
            for (int mt = 0; mt < 4; mt++) {
                const int r = wm + mt * 16 + gID;
                a[mt][0] = __float_as_uint(As[r * 36 + ks + tig]);
                a[mt][1] = __float_as_uint(As[(r + 8) * 36 + ks + tig]);
                a[mt][2] = __float_as_uint(As[r * 36 + ks + tig + 4]);
                a[mt][3] = __float_as_uint(As[(r + 8) * 36 + ks + tig + 4]);
            }
            #pragma unroll
            for (int nt = 0; nt < NTILES; nt++) {
                const int nr = wn + nt * 8 + gID;
                uint32_t b0 = __float_as_uint(Bs[nr * 36 + ks + tig]);
                uint32_t b1 = __float_as_uint(Bs[nr * 36 + ks + tig + 4]);
                #pragma unroll
                for (int mt = 0; mt < 4; mt++)
                    mma8(c[mt][nt], a[mt], b0, b1);
            }
        }
        if (more) store_tiles(buf ^ 1);
        __syncthreads();
    }

    // ---- epilogue ----
    #pragma unroll
    for (int mt = 0; mt < 4; mt++) {
        #pragma unroll
        for (int nt = 0; nt < NTILES; nt++) {
            const int col = wn + nt * 8 + tig * 2;
            #pragma unroll
            for (int half = 0; half < 2; half++) {
                const int m = m0 + wm + mt * 16 + gID + half * 8;
                if (m >= M) continue;
                float v0 = c[mt][nt][half * 2 + 0];
                float v1 = c[mt][nt][half * 2 + 1];
                v0 += __ldg(&bias[col]);
                v1 += __ldg(&bias[col + 1]);
                if (EPI == EPI_RELU_BN) {
                    v0 = fmaxf(v0, 0.0f);
                    v1 = fmaxf(v1, 0.0f);
                    v0 = (v0 - __ldg(&mu[col]))     * rsqrtf(__ldg(&var[col])     + 1e-5f) * __ldg(&gmm[col])     + __ldg(&bet[col]);
                    v1 = (v1 - __ldg(&mu[col + 1])) * rsqrtf(__ldg(&var[col + 1]) + 1e-5f) * __ldg(&gmm[col + 1]) + __ldg(&bet[col + 1]);
                } else if (EPI == EPI_RELU_RES) {
                    float2 rr = *(const float2*)(res + (size_t)m * FDIM + col);
                    v0 = fmaxf(v0, 0.0f) + rr.x;
                    v1 = fmaxf(v1, 0.0f) + rr.y;
                } else if (EPI == EPI_RELU) {
                    v0 = fmaxf(v0, 0.0f);
                    v1 = fmaxf(v1, 0.0f);
                }
                *(float2*)(C + (size_t)m * ldc + col) = make_float2(v0, v1);
            }
        }
    }
}

// ======================= launch =======================
extern "C" void kernel_launch(void* const* d_in, const int* in_sizes, int n_in,
                              void* d_out, int out_size) {
    const float* feat  = (const float*)d_in[0];
    const int*   esrc  = (const int*)d_in[1];
    const int*   edst  = (const int*)d_in[2];
    const float* W1    = (const float*)d_in[3];
    const float* b1    = (const float*)d_in[4];
    const float* gamma = (const float*)d_in[5];
    const float* beta  = (const float*)d_in[6];
    const float* mean  = (const float*)d_in[7];
    const float* var   = (const float*)d_in[8];
    const float* W3    = (const float*)d_in[9];
    const float* b3    = (const float*)d_in[10];
    const float* Wm1   = (const float*)d_in[11];
    const float* bm1   = (const float*)d_in[12];
    const float* Wm2   = (const float*)d_in[13];
    const float* bm2   = (const float*)d_in[14];

    const int n  = in_sizes[0] / FDIM;
    const int ne = in_sizes[1];

    int *deg, *off, *pos, *cum, *flag, *csrc;
    float *dinv, *b0, *bb1, *b2, *b3buf, *w1t, *w3t;
    cudaGetSymbolAddress((void**)&deg,  g_deg);
    cudaGetSymbolAddress((void**)&off,  g_off);
    cudaGetSymbolAddress((void**)&pos,  g_pos);
    cudaGetSymbolAddress((void**)&cum,  g_cum);
    cudaGetSymbolAddress((void**)&flag, g_flag);
    cudaGetSymbolAddress((void**)&csrc, g_csrc);
    cudaGetSymbolAddress((void**)&dinv, g_dinv);
    cudaGetSymbolAddress((void**)&b0,   g_b0);
    cudaGetSymbolAddress((void**)&bb1,  g_b1);
    cudaGetSymbolAddress((void**)&b2,   g_b2);
    cudaGetSymbolAddress((void**)&b3buf, g_b3);
    cudaGetSymbolAddress((void**)&w1t,  g_w1t);
    cudaGetSymbolAddress((void**)&w3t,  g_w3t);

    const int nb    = (n + 511) / 512;
    const int agrid = (n + 15) / 16;
    const int ggrid = (n + 255) / 256;

    const int SMEM_N128 = (2 * 256 * 36 + 2 * 128 * 36) * 4;  // 110592
    const int SMEM_N64  = (2 * 256 * 36 + 2 * 64  * 36) * 4;  // 92160
    cudaFuncSetAttribute(k_gemm_tc<128, EPI_RELU_BN>,  cudaFuncAttributeMaxDynamicSharedMemorySize, SMEM_N128);
    cudaFuncSetAttribute(k_gemm_tc<128, EPI_RELU_RES>, cudaFuncAttributeMaxDynamicSharedMemorySize, SMEM_N128);
    cudaFuncSetAttribute(k_gemm_tc<128, EPI_RELU>,     cudaFuncAttributeMaxDynamicSharedMemorySize, SMEM_N128);
    cudaFuncSetAttribute(k_gemm_tc<64,  EPI_BIAS>,     cudaFuncAttributeMaxDynamicSharedMemorySize, SMEM_N64);

    // ---- CSR build + weight transforms ----
    cudaMemsetAsync(deg, 0, (size_t)n * sizeof(int));
    cudaMemsetAsync(flag, 0, 256 * sizeof(int));
    k_degi<<<(ne + 255) / 256, 256>>>(edst, ne, deg);
    k_scan_chain<<<nb, 512>>>(deg, n, off, pos, dinv, cum, flag);
    k_bucket<<<(ne + 255) / 256, 256>>>(esrc, edst, ne, pos, csrc);
    k_wt2<<<(2 * 128 * 128 + 255) / 256, 256>>>(W1, w1t, W3, w3t);

    // ---- Cheb layer 1: G0 = Ahat(feat), G1 = Ahat(G0) ----
    k_ahat<<<agrid, 512>>>(feat, dinv, off, csrc, bb1, n);
    k_ahat<<<agrid, 512>>>(bb1,  dinv, off, csrc, b2,  n);
    k_gemm_tc<128, EPI_RELU_BN><<<ggrid, 256, SMEM_N128>>>(feat, bb1, b2, n, 384, w1t, b1,
                                                           gamma, beta, mean, var,
                                                           (const float*)nullptr, b0, 128);

    // ---- Cheb layer 2 ----
    k_ahat<<<agrid, 512>>>(b0,  dinv, off, csrc, bb1, n);
    k_ahat<<<agrid, 512>>>(bb1, dinv, off, csrc, b2,  n);
    k_gemm_tc<128, EPI_RELU_RES><<<ggrid, 256, SMEM_N128>>>(b0, bb1, b2, n, 384, w3t, b3,
                                                            (const float*)nullptr, (const float*)nullptr,
                                                            (const float*)nullptr, (const float*)nullptr,
                                                            b0, b3buf, 128);

    // ---- MLP head ----
    k_gemm_tc<128, EPI_RELU><<<ggrid, 256, SMEM_N128>>>(b3buf, (const float*)nullptr, (const float*)nullptr,
                                                        n, 128, Wm1, bm1,
                                                        (const float*)nullptr, (const float*)nullptr,
                                                        (const float*)nullptr, (const float*)nullptr,
                                                        (const float*)nullptr, bb1, 128);
    k_gemm_tc<64, EPI_BIAS><<<ggrid, 256, SMEM_N64>>>(bb1, (const float*)nullptr, (const float*)nullptr,
                                                      n, 128, Wm2, bm2,
                                                      (const float*)nullptr, (const float*)nullptr,
                                                      (const float*)nullptr, (const float*)nullptr,
                                                      (const float*)nullptr, (float*)d_out, 64);
}

// round 11
// speedup vs baseline: 1.4839x; 1.4839x over previous
#include <cuda_runtime.h>
#include <cstdint>
#include <cstddef>

#define NMAX 100000
#define NEMAX 600000
#define FDIM 128

// ---- static device scratch (no allocations allowed) ----
__device__ int   g_deg[NMAX];
__device__ int   g_off[NMAX + 1];
__device__ int   g_pos[NMAX];
__device__ int   g_blk[256];
__device__ int   g_csrc[NEMAX];
__device__ float g_dinv[NMAX];
__device__ float g_b0[NMAX * FDIM];   // y (layer1 out / residual)
__device__ float g_b1[NMAX * FDIM];   // G0 / reuse
__device__ float g_b2[NMAX * FDIM];   // G1
__device__ float g_b3[NMAX * FDIM];   // m1
__device__ float g_w1t[128 * 384];
__device__ float g_w3t[128 * 384];

__device__ __forceinline__ uint32_t f2tf32(float x) {
    uint32_t r;
    asm("cvt.rna.tf32.f32 %0, %1;" : "=r"(r) : "f"(x));
    return r;
}

// ======================= CSR build =======================
__global__ void k_degi(const int* __restrict__ dst, int ne, int* __restrict__ deg) {
    int i = blockIdx.x * blockDim.x + threadIdx.x;
    if (i < ne) atomicAdd(&deg[dst[i]], 1);
}

// block-local inclusive scan + dinv computation fused
__global__ void k_scan1(const int* __restrict__ deg, int n,
                        int* __restrict__ excl, int* __restrict__ blk,
                        float* __restrict__ dinv) {
    __shared__ int sh[512];
    int tid = threadIdx.x;
    int i = blockIdx.x * 512 + tid;
    int v = (i < n) ? deg[i] : 0;
    if (i < n) dinv[i] = rsqrtf((float)(v > 1 ? v : 1));
    sh[tid] = v;
    __syncthreads();
    #pragma unroll
    for (int ofs = 1; ofs < 512; ofs <<= 1) {
        int t = (tid >= ofs) ? sh[tid - ofs] : 0;
        __syncthreads();
        sh[tid] += t;
        __syncthreads();
    }
    if (i < n) excl[i] = sh[tid] - v;
    if (tid == 511) blk[blockIdx.x] = sh[511];
}

// parallel exclusive scan of block totals (nb <= 256)
__global__ void k_scan2p(int* __restrict__ blk, int nb, int* __restrict__ off_n) {
    __shared__ int sh[256];
    int tid = threadIdx.x;
    int v = (tid < nb) ? blk[tid] : 0;
    sh[tid] = v;
    __syncthreads();
    #pragma unroll
    for (int ofs = 1; ofs < 256; ofs <<= 1) {
        int t = (tid >= ofs) ? sh[tid - ofs] : 0;
        __syncthreads();
        sh[tid] += t;
        __syncthreads();
    }
    if (tid < nb) blk[tid] = sh[tid] - v;
    if (tid == 255) *off_n = sh[255];
}

__global__ void k_scan3(int* __restrict__ off, int* __restrict__ pos,
                        const int* __restrict__ blk, int n) {
    int i = blockIdx.x * 512 + threadIdx.x;
    if (i < n) {
        int o = off[i] + blk[blockIdx.x];
        off[i] = o;
        pos[i] = o;
    }
}

__global__ void k_bucket(const int* __restrict__ src, const int* __restrict__ dst, int ne,
                         int* __restrict__ pos, int* __restrict__ csrc) {
    int e = blockIdx.x * blockDim.x + threadIdx.x;
    if (e < ne) {
        int p = atomicAdd(&pos[dst[e]], 1);
        csrc[p] = src[e];
    }
}

// ======================= weight transform (both layers in one launch) =======================
// W [128,384] = [W0|W1|W2] -> W' = [W0-W1+W2 | W1-4W2 | 2W2]
__global__ void k_wt2(const float* __restrict__ WA, float* __restrict__ WtA,
                      const float* __restrict__ WB, float* __restrict__ WtB) {
    int i = blockIdx.x * blockDim.x + threadIdx.x;
    if (i >= 2 * 128 * 128) return;
    const float* W = (i < 128 * 128) ? WA : WB;
    float* Wt      = (i < 128 * 128) ? WtA : WtB;
    i &= (128 * 128 - 1);
    int o = i >> 7, k = i & 127;
    float w0 = W[o * 384 + k];
    float w1 = W[o * 384 + 128 + k];
    float w2 = W[o * 384 + 256 + k];
    Wt[o * 384 + k]       = w0 - w1 + w2;
    Wt[o * 384 + 128 + k] = w1 - 4.0f * w2;
    Wt[o * 384 + 256 + k] = 2.0f * w2;
}

// ======================= pure A_hat application =======================
// Xout[v] = (sum_{s in N(v)} Xin[s]*dinv[s]) * dinv[v]   — warp per node, 2-way unrolled
__global__ void __launch_bounds__(256)
k_ahat(const float* __restrict__ Xin,
       const float* __restrict__ dinv,
       const int* __restrict__ off, const int* __restrict__ csrc,
       float* __restrict__ Xout, int n) {
    int v = blockIdx.x * 8 + (threadIdx.x >> 5);
    if (v >= n) return;
    int lane = threadIdx.x & 31;
    int beg = __ldg(&off[v]);
    int end = __ldg(&off[v + 1]);

    float4 acc = make_float4(0.f, 0.f, 0.f, 0.f);
    int j = beg;
    for (; j + 2 <= end; j += 2) {
        int s0 = __ldg(&csrc[j]);
        int s1 = __ldg(&csrc[j + 1]);
        float c0 = __ldg(&dinv[s0]);
        float c1 = __ldg(&dinv[s1]);
        float4 x0 = *(const float4*)(Xin + (size_t)s0 * FDIM + lane * 4);
        float4 x1 = *(const float4*)(Xin + (size_t)s1 * FDIM + lane * 4);
        acc.x += x0.x * c0 + x1.x * c1;
        acc.y += x0.y * c0 + x1.y * c1;
        acc.z += x0.z * c0 + x1.z * c1;
        acc.w += x0.w * c0 + x1.w * c1;
    }
    if (j < end) {
        int s = __ldg(&csrc[j]);
        float c = __ldg(&dinv[s]);
        float4 x = *(const float4*)(Xin + (size_t)s * FDIM + lane * 4);
        acc.x += x.x * c;
        acc.y += x.y * c;
        acc.z += x.z * c;
        acc.w += x.w * c;
    }
    float dv = __ldg(&dinv[v]);
    float4 r = make_float4(acc.x * dv, acc.y * dv, acc.z * dv, acc.w * dv);
    *(float4*)(Xout + (size_t)v * FDIM + lane * 4) = r;
}

// ============== tf32 mma.sync GEMM: C[256-tile, NT] = [A0|A1|A2] @ W[NT,K]^T + epilogue ==============
// CTA tile 256 x NT, BK=32, 256 threads (8 warps), warp tile 64 x (NT/2), 1 CTA/SM.
// Software-pipelined: global loads staged in registers across the mma block.
#define EPI_BIAS     0
#define EPI_RELU_BN  1
#define EPI_RELU_RES 2
#define EPI_RELU     3

__device__ __forceinline__ void mma8(float c[4], const uint32_t a[4], uint32_t b0, uint32_t b1) {
    asm volatile(
        "mma.sync.aligned.m16n8k8.row.col.f32.tf32.tf32.f32 "
        "{%0,%1,%2,%3}, {%4,%5,%6,%7}, {%8,%9}, {%0,%1,%2,%3};"
        : "+f"(c[0]), "+f"(c[1]), "+f"(c[2]), "+f"(c[3])
        : "r"(a[0]), "r"(a[1]), "r"(a[2]), "r"(a[3]), "r"(b0), "r"(b1));
}

template<int NT, int EPI>
__global__ void __launch_bounds__(256, 1)
k_gemm_tc(const float* __restrict__ A0, const float* __restrict__ A1, const float* __restrict__ A2,
          int M, int K,
          const float* __restrict__ W,
          const float* __restrict__ bias,
          const float* __restrict__ gmm, const float* __restrict__ bet,
          const float* __restrict__ mu,  const float* __restrict__ var,
          const float* __restrict__ res,
          float* __restrict__ C, int ldc) {
    extern __shared__ float sm[];
    float* const AsBase = sm;                     // 2 * 256 * 36
    float* const BsBase = sm + 2 * 256 * 36;      // 2 * NT * 36

    const int tid  = threadIdx.x;
    const int wid  = tid >> 5;
    const int lane = tid & 31;
    const int gID  = lane >> 2;
    const int tig  = lane & 3;
    const int m0   = blockIdx.x * 256;

    const int wm = (wid & 3) * 64;
    const int wn = (wid >> 2) * (NT / 2);
    constexpr int NTILES = NT / 16;
    constexpr int BITER  = NT / 32;

    float c[4][NTILES][4];
    #pragma unroll
    for (int i = 0; i < 4; i++)
        #pragma unroll
        for (int j = 0; j < NTILES; j++)
            #pragma unroll
            for (int q = 0; q < 4; q++) c[i][j][q] = 0.0f;

    const int nch = K >> 5;

    float4 ra[8];
    float4 rb[BITER];

    auto load_regs = [&](int kt) {
        const float* Ap = (kt < 128) ? A0 : ((kt < 256) ? A1 : A2);
        const int kk = kt & 127;
        #pragma unroll
        for (int it = 0; it < 8; it++) {
            int i = tid + it * 256;
            int row = i >> 3, q = i & 7;
            int gm = m0 + row;
            ra[it] = (gm < M) ? *(const float4*)(Ap + (size_t)gm * FDIM + kk + q * 4)
                              : make_float4(0.f, 0.f, 0.f, 0.f);
        }
        #pragma unroll
        for (int it = 0; it < BITER; it++) {
            int i = tid + it * 256;
            int row = i >> 3, q = i & 7;
            rb[it] = *(const float4*)(W + (size_t)row * K + kt + q * 4);
        }
    };
    auto store_tiles = [&](int buf) {
        float* As = AsBase + buf * (256 * 36);
        float* Bs = BsBase + buf * (NT * 36);
        #pragma unroll
        for (int it = 0; it < 8; it++) {
            int i = tid + it * 256;
            int row = i >> 3, q = i & 7;
            uint4 t = make_uint4(f2tf32(ra[it].x), f2tf32(ra[it].y), f2tf32(ra[it].z), f2tf32(ra[it].w));
            *(uint4*)(As + row * 36 + q * 4) = t;
        }
        #pragma unroll
        for (int it = 0; it < BITER; it++) {
            int i = tid + it * 256;
            int row = i >> 3, q = i & 7;
            uint4 t = make_uint4(f2tf32(rb[it].x), f2tf32(rb[it].y), f2tf32(rb[it].z), f2tf32(rb[it].w));
            *(uint4*)(Bs + row * 36 + q * 4) = t;
        }
    };

    load_regs(0);
    store_tiles(0);
    __syncthreads();

    for (int ch = 0; ch < nch; ch++) {
        const int buf = ch & 1;
        const bool more = (ch + 1 < nch);
        if (more) load_regs((ch + 1) << 5);

        const float* As = AsBase + buf * (256 * 36);
        const float* Bs = BsBase + buf * (NT * 36);

        #pragma unroll
        for (int ks = 0; ks < 32; ks += 8) {
            uint32_t a[4][4];
            #pragma unroll
            for (int mt = 0; mt < 4; mt++) {
                const int r = wm + mt * 16 + gID;
                a[mt][0] = __float_as_uint(As[r * 36 + ks + tig]);
                a[mt][1] = __float_as_uint(As[(r + 8) * 36 + ks + tig]);
                a[mt][2] = __float_as_uint(As[r * 36 + ks + tig + 4]);
                a[mt][3] = __float_as_uint(As[(r + 8) * 36 + ks + tig + 4]);
            }
            #pragma unroll
            for (int nt = 0; nt < NTILES; nt++) {
                const int nr = wn + nt * 8 + gID;
                uint32_t b0 = __float_as_uint(Bs[nr * 36 + ks + tig]);
                uint32_t b1 = __float_as_uint(Bs[nr * 36 + ks + tig + 4]);
                #pragma unroll
                for (int mt = 0; mt < 4; mt++)
                    mma8(c[mt][nt], a[mt], b0, b1);
            }
        }
        if (more) store_tiles(buf ^ 1);
        __syncthreads();
    }

    // ---- epilogue ----
    #pragma unroll
    for (int mt = 0; mt < 4; mt++) {
        #pragma unroll
        for (int nt = 0; nt < NTILES; nt++) {
            const int col = wn + nt * 8 + tig * 2;
            #pragma unroll
            for (int half = 0; half < 2; half++) {
                const int m = m0 + wm + mt * 16 + gID + half * 8;
                if (m >= M) continue;
                float v0 = c[mt][nt][half * 2 + 0];
                float v1 = c[mt][nt][half * 2 + 1];
                v0 += __ldg(&bias[col]);
                v1 += __ldg(&bias[col + 1]);
                if (EPI == EPI_RELU_BN) {
                    v0 = fmaxf(v0, 0.0f);
                    v1 = fmaxf(v1, 0.0f);
                    v0 = (v0 - __ldg(&mu[col]))     * rsqrtf(__ldg(&var[col])     + 1e-5f) * __ldg(&gmm[col])     + __ldg(&bet[col]);
                    v1 = (v1 - __ldg(&mu[col + 1])) * rsqrtf(__ldg(&var[col + 1]) + 1e-5f) * __ldg(&gmm[col + 1]) + __ldg(&bet[col + 1]);
                } else if (EPI == EPI_RELU_RES) {
                    float2 rr = *(const float2*)(res + (size_t)m * FDIM + col);
                    v0 = fmaxf(v0, 0.0f) + rr.x;
                    v1 = fmaxf(v1, 0.0f) + rr.y;
                } else if (EPI == EPI_RELU) {
                    v0 = fmaxf(v0, 0.0f);
                    v1 = fmaxf(v1, 0.0f);
                }
                *(float2*)(C + (size_t)m * ldc + col) = make_float2(v0, v1);
            }
        }
    }
}

// ======================= launch =======================
extern "C" void kernel_launch(void* const* d_in, const int* in_sizes, int n_in,
                              void* d_out, int out_size) {
    const float* feat  = (const float*)d_in[0];
    const int*   esrc  = (const int*)d_in[1];
    const int*   edst  = (const int*)d_in[2];
    const float* W1    = (const float*)d_in[3];
    const float* b1    = (const float*)d_in[4];
    const float* gamma = (const float*)d_in[5];
    const float* beta  = (const float*)d_in[6];
    const float* mean  = (const float*)d_in[7];
    const float* var   = (const float*)d_in[8];
    const float* W3    = (const float*)d_in[9];
    const float* b3    = (const float*)d_in[10];
    const float* Wm1   = (const float*)d_in[11];
    const float* bm1   = (const float*)d_in[12];
    const float* Wm2   = (const float*)d_in[13];
    const float* bm2   = (const float*)d_in[14];

    const int n  = in_sizes[0] / FDIM;
    const int ne = in_sizes[1];

    int *deg, *off, *pos, *blk, *csrc;
    float *dinv, *b0, *bb1, *b2, *b3buf, *w1t, *w3t;
    cudaGetSymbolAddress((void**)&deg,  g_deg);
    cudaGetSymbolAddress((void**)&off,  g_off);
    cudaGetSymbolAddress((void**)&pos,  g_pos);
    cudaGetSymbolAddress((void**)&blk,  g_blk);
    cudaGetSymbolAddress((void**)&csrc, g_csrc);
    cudaGetSymbolAddress((void**)&dinv, g_dinv);
    cudaGetSymbolAddress((void**)&b0,   g_b0);
    cudaGetSymbolAddress((void**)&bb1,  g_b1);
    cudaGetSymbolAddress((void**)&b2,   g_b2);
    cudaGetSymbolAddress((void**)&b3buf, g_b3);
    cudaGetSymbolAddress((void**)&w1t,  g_w1t);
    cudaGetSymbolAddress((void**)&w3t,  g_w3t);

    const int nb    = (n + 511) / 512;
    const int agrid = (n + 7) / 8;
    const int ggrid = (n + 255) / 256;

    const int SMEM_N128 = (2 * 256 * 36 + 2 * 128 * 36) * 4;  // 110592
    const int SMEM_N64  = (2 * 256 * 36 + 2 * 64  * 36) * 4;  // 92160
    cudaFuncSetAttribute(k_gemm_tc<128, EPI_RELU_BN>,  cudaFuncAttributeMaxDynamicSharedMemorySize, SMEM_N128);
    cudaFuncSetAttribute(k_gemm_tc<128, EPI_RELU_RES>, cudaFuncAttributeMaxDynamicSharedMemorySize, SMEM_N128);
    cudaFuncSetAttribute(k_gemm_tc<128, EPI_RELU>,     cudaFuncAttributeMaxDynamicSharedMemorySize, SMEM_N128);
    cudaFuncSetAttribute(k_gemm_tc<64,  EPI_BIAS>,     cudaFuncAttributeMaxDynamicSharedMemorySize, SMEM_N64);

    // ---- CSR build + weight transforms ----
    cudaMemsetAsync(deg, 0, (size_t)n * sizeof(int));
    k_degi<<<(ne + 255) / 256, 256>>>(edst, ne, deg);
    k_scan1<<<nb, 512>>>(deg, n, off, blk, dinv);
    k_scan2p<<<1, 256>>>(blk, nb, off + n);
    k_scan3<<<nb, 512>>>(off, pos, blk, n);
    k_bucket<<<(ne + 255) / 256, 256>>>(esrc, edst, ne, pos, csrc);
    k_wt2<<<(2 * 128 * 128 + 255) / 256, 256>>>(W1, w1t, W3, w3t);

    // ---- Cheb layer 1: G0 = Ahat(feat), G1 = Ahat(G0) ----
    k_ahat<<<agrid, 256>>>(feat, dinv, off, csrc, bb1, n);
    k_ahat<<<agrid, 256>>>(bb1,  dinv, off, csrc, b2,  n);
    k_gemm_tc<128, EPI_RELU_BN><<<ggrid, 256, SMEM_N128>>>(feat, bb1, b2, n, 384, w1t, b1,
                                                           gamma, beta, mean, var,
                                                           (const float*)nullptr, b0, 128);

    // ---- Cheb layer 2 ----
    k_ahat<<<agrid, 256>>>(b0,  dinv, off, csrc, bb1, n);
    k_ahat<<<agrid, 256>>>(bb1, dinv, off, csrc, b2,  n);
    k_gemm_tc<128, EPI_RELU_RES><<<ggrid, 256, SMEM_N128>>>(b0, bb1, b2, n, 384, w3t, b3,
                                                            (const float*)nullptr, (const float*)nullptr,
                                                            (const float*)nullptr, (const float*)nullptr,
                                                            b0, b3buf, 128);

    // ---- MLP head ----
    k_gemm_tc<128, EPI_RELU><<<ggrid, 256, SMEM_N128>>>(b3buf, (const float*)nullptr, (const float*)nullptr,
                                                        n, 128, Wm1, bm1,
                                                        (const float*)nullptr, (const float*)nullptr,
                                                        (const float*)nullptr, (const float*)nullptr,
                                                        (const float*)nullptr, bb1, 128);
    k_gemm_tc<64, EPI_BIAS><<<ggrid, 256, SMEM_N64>>>(bb1, (const float*)nullptr, (const float*)nullptr,
                                                      n, 128, Wm2, bm2,
                                                      (const float*)nullptr, (const float*)nullptr,
                                                      (const float*)nullptr, (const float*)nullptr,
                                                      (const float*)nullptr, (float*)d_out, 64);
}

// round 12
// speedup vs baseline: 1.5342x; 1.0339x over previous
#include <cuda_runtime.h>
#include <cstdint>
#include <cstddef>

#define NMAX 100000
#define NEMAX 600000
#define FDIM 128

// ---- static device scratch (no allocations allowed) ----
__device__ int   g_deg[NMAX];
__device__ int   g_off[NMAX + 1];
__device__ int   g_pos[NMAX];
__device__ int   g_blk[256];
__device__ int   g_csrc[NEMAX];
__device__ float g_dinv[NMAX];
__device__ float g_b0[NMAX * FDIM];   // y (layer1 out / residual)
__device__ float g_b1[NMAX * FDIM];   // G0 / reuse
__device__ float g_b2[NMAX * FDIM];   // G1
__device__ float g_b3[NMAX * FDIM];   // m1
__device__ float g_w1t[128 * 384];
__device__ float g_w3t[128 * 384];

__device__ __forceinline__ uint32_t f2tf32(float x) {
    uint32_t r;
    asm("cvt.rna.tf32.f32 %0, %1;" : "=r"(r) : "f"(x));
    return r;
}

// ======================= CSR build =======================
__global__ void k_degi(const int* __restrict__ dst, int ne, int* __restrict__ deg) {
    int i = blockIdx.x * blockDim.x + threadIdx.x;
    if (i < ne) atomicAdd(&deg[dst[i]], 1);
}

// block-local inclusive scan + dinv computation fused
__global__ void k_scan1(const int* __restrict__ deg, int n,
                        int* __restrict__ excl, int* __restrict__ blk,
                        float* __restrict__ dinv) {
    __shared__ int sh[512];
    int tid = threadIdx.x;
    int i = blockIdx.x * 512 + tid;
    int v = (i < n) ? deg[i] : 0;
    if (i < n) dinv[i] = rsqrtf((float)(v > 1 ? v : 1));
    sh[tid] = v;
    __syncthreads();
    #pragma unroll
    for (int ofs = 1; ofs < 512; ofs <<= 1) {
        int t = (tid >= ofs) ? sh[tid - ofs] : 0;
        __syncthreads();
        sh[tid] += t;
        __syncthreads();
    }
    if (i < n) excl[i] = sh[tid] - v;
    if (tid == 511) blk[blockIdx.x] = sh[511];
}

// parallel exclusive scan of block totals (nb <= 256)
__global__ void k_scan2p(int* __restrict__ blk, int nb, int* __restrict__ off_n) {
    __shared__ int sh[256];
    int tid = threadIdx.x;
    int v = (tid < nb) ? blk[tid] : 0;
    sh[tid] = v;
    __syncthreads();
    #pragma unroll
    for (int ofs = 1; ofs < 256; ofs <<= 1) {
        int t = (tid >= ofs) ? sh[tid - ofs] : 0;
        __syncthreads();
        sh[tid] += t;
        __syncthreads();
    }
    if (tid < nb) blk[tid] = sh[tid] - v;
    if (tid == 255) *off_n = sh[255];
}

__global__ void k_scan3(int* __restrict__ off, int* __restrict__ pos,
                        const int* __restrict__ blk, int n) {
    int i = blockIdx.x * 512 + threadIdx.x;
    if (i < n) {
        int o = off[i] + blk[blockIdx.x];
        off[i] = o;
        pos[i] = o;
    }
}

__global__ void k_bucket(const int* __restrict__ src, const int* __restrict__ dst, int ne,
                         int* __restrict__ pos, int* __restrict__ csrc) {
    int e = blockIdx.x * blockDim.x + threadIdx.x;
    if (e < ne) {
        int p = atomicAdd(&pos[dst[e]], 1);
        csrc[p] = src[e];
    }
}

// ======================= weight transform (both layers in one launch) =======================
// W [128,384] = [W0|W1|W2] -> W' = [W0-W1+W2 | W1-4W2 | 2W2]
__global__ void k_wt2(const float* __restrict__ WA, float* __restrict__ WtA,
                      const float* __restrict__ WB, float* __restrict__ WtB) {
    int i = blockIdx.x * blockDim.x + threadIdx.x;
    if (i >= 2 * 128 * 128) return;
    const float* W = (i < 128 * 128) ? WA : WB;
    float* Wt      = (i < 128 * 128) ? WtA : WtB;
    i &= (128 * 128 - 1);
    int o = i >> 7, k = i & 127;
    float w0 = W[o * 384 + k];
    float w1 = W[o * 384 + 128 + k];
    float w2 = W[o * 384 + 256 + k];
    Wt[o * 384 + k]       = w0 - w1 + w2;
    Wt[o * 384 + 128 + k] = w1 - 4.0f * w2;
    Wt[o * 384 + 256 + k] = 2.0f * w2;
}

// ======================= pure A_hat application =======================
// Xout[v] = (sum_{s in N(v)} Xin[s]*dinv[s]) * dinv[v]   — warp per node, 2-way unrolled
__global__ void __launch_bounds__(256)
k_ahat(const float* __restrict__ Xin,
       const float* __restrict__ dinv,
       const int* __restrict__ off, const int* __restrict__ csrc,
       float* __restrict__ Xout, int n) {
    int v = blockIdx.x * 8 + (threadIdx.x >> 5);
    if (v >= n) return;
    int lane = threadIdx.x & 31;
    int beg = __ldg(&off[v]);
    int end = __ldg(&off[v + 1]);

    float4 acc = make_float4(0.f, 0.f, 0.f, 0.f);
    int j = beg;
    for (; j + 2 <= end; j += 2) {
        int s0 = __ldg(&csrc[j]);
        int s1 = __ldg(&csrc[j + 1]);
        float c0 = __ldg(&dinv[s0]);
        float c1 = __ldg(&dinv[s1]);
        float4 x0 = *(const float4*)(Xin + (size_t)s0 * FDIM + lane * 4);
        float4 x1 = *(const float4*)(Xin + (size_t)s1 * FDIM + lane * 4);
        acc.x += x0.x * c0 + x1.x * c1;
        acc.y += x0.y * c0 + x1.y * c1;
        acc.z += x0.z * c0 + x1.z * c1;
        acc.w += x0.w * c0 + x1.w * c1;
    }
    if (j < end) {
        int s = __ldg(&csrc[j]);
        float c = __ldg(&dinv[s]);
        float4 x = *(const float4*)(Xin + (size_t)s * FDIM + lane * 4);
        acc.x += x.x * c;
        acc.y += x.y * c;
        acc.z += x.z * c;
        acc.w += x.w * c;
    }
    float dv = __ldg(&dinv[v]);
    float4 r = make_float4(acc.x * dv, acc.y * dv, acc.z * dv, acc.w * dv);
    *(float4*)(Xout + (size_t)v * FDIM + lane * 4) = r;
}

// ============== tf32 mma.sync GEMM: C[256-tile, NT] = [A0|A1|A2] @ W[NT,K]^T + epilogue ==============
#define EPI_BIAS     0
#define EPI_RELU_BN  1
#define EPI_RELU_RES 2
#define EPI_RELU     3

__device__ __forceinline__ void mma8(float c[4], const uint32_t a[4], uint32_t b0, uint32_t b1) {
    asm volatile(
        "mma.sync.aligned.m16n8k8.row.col.f32.tf32.tf32.f32 "
        "{%0,%1,%2,%3}, {%4,%5,%6,%7}, {%8,%9}, {%0,%1,%2,%3};"
        : "+f"(c[0]), "+f"(c[1]), "+f"(c[2]), "+f"(c[3])
        : "r"(a[0]), "r"(a[1]), "r"(a[2]), "r"(a[3]), "r"(b0), "r"(b1));
}

template<int NT, int EPI>
__global__ void __launch_bounds__(256, 1)
k_gemm_tc(const float* __restrict__ A0, const float* __restrict__ A1, const float* __restrict__ A2,
          int M, int K,
          const float* __restrict__ W,
          const float* __restrict__ bias,
          const float* __restrict__ gmm, const float* __restrict__ bet,
          const float* __restrict__ mu,  const float* __restrict__ var,
          const float* __restrict__ res,
          float* __restrict__ C, int ldc) {
    extern __shared__ float sm[];
    float* const AsBase = sm;                     // 2 * 256 * 36
    float* const BsBase = sm + 2 * 256 * 36;      // 2 * NT * 36

    const int tid  = threadIdx.x;
    const int wid  = tid >> 5;
    const int lane = tid & 31;
    const int gID  = lane >> 2;
    const int tig  = lane & 3;
    const int m0   = blockIdx.x * 256;

    const int wm = (wid & 3) * 64;
    const int wn = (wid >> 2) * (NT / 2);
    constexpr int NTILES = NT / 16;
    constexpr int BITER  = NT / 32;

    float c[4][NTILES][4];
    #pragma unroll
    for (int i = 0; i < 4; i++)
        #pragma unroll
        for (int j = 0; j < NTILES; j++)
            #pragma unroll
            for (int q = 0; q < 4; q++) c[i][j][q] = 0.0f;

    const int nch = K >> 5;

    float4 ra[8];
    float4 rb[BITER];

    auto load_regs = [&](int kt) {
        const float* Ap = (kt < 128) ? A0 : ((kt < 256) ? A1 : A2);
        const int kk = kt & 127;
        #pragma unroll
        for (int it = 0; it < 8; it++) {
            int i = tid + it * 256;
            int row = i >> 3, q = i & 7;
            int gm = m0 + row;
            ra[it] = (gm < M) ? *(const float4*)(Ap + (size_t)gm * FDIM + kk + q * 4)
                              : make_float4(0.f, 0.f, 0.f, 0.f);
        }
        #pragma unroll
        for (int it = 0; it < BITER; it++) {
            int i = tid + it * 256;
            int row = i >> 3, q = i & 7;
            rb[it] = *(const float4*)(W + (size_t)row * K + kt + q * 4);
        }
    };
    auto store_tiles = [&](int buf) {
        float* As = AsBase + buf * (256 * 36);
        float* Bs = BsBase + buf * (NT * 36);
        #pragma unroll
        for (int it = 0; it < 8; it++) {
            int i = tid + it * 256;
            int row = i >> 3, q = i & 7;
            uint4 t = make_uint4(f2tf32(ra[it].x), f2tf32(ra[it].y), f2tf32(ra[it].z), f2tf32(ra[it].w));
            *(uint4*)(As + row * 36 + q * 4) = t;
        }
        #pragma unroll
        for (int it = 0; it < BITER; it++) {
            int i = tid + it * 256;
            int row = i >> 3, q = i & 7;
            uint4 t = make_uint4(f2tf32(rb[it].x), f2tf32(rb[it].y), f2tf32(rb[it].z), f2tf32(rb[it].w));
            *(uint4*)(Bs + row * 36 + q * 4) = t;
        }
    };

    load_regs(0);
    store_tiles(0);
    __syncthreads();

    for (int ch = 0; ch < nch; ch++) {
        const int buf = ch & 1;
        const bool more = (ch + 1 < nch);
        if (more) load_regs((ch + 1) << 5);

        const float* As = AsBase + buf * (256 * 36);
        const float* Bs = BsBase + buf * (NT * 36);

        #pragma unroll
        for (int ks = 0; ks < 32; ks += 8) {
            uint32_t a[4][4];
            #pragma unroll
            for (int mt = 0; mt < 4; mt++) {
                const int r = wm + mt * 16 + gID;
                a[mt][0] = __float_as_uint(As[r * 36 + ks + tig]);
                a[mt][1] = __float_as_uint(As[(r + 8) * 36 + ks + tig]);
                a[mt][2] = __float_as_uint(As[r * 36 + ks + tig + 4]);
                a[mt][3] = __float_as_uint(As[(r + 8) * 36 + ks + tig + 4]);
            }
            #pragma unroll
            for (int nt = 0; nt < NTILES; nt++) {
                const int nr = wn + nt * 8 + gID;
                uint32_t b0 = __float_as_uint(Bs[nr * 36 + ks + tig]);
                uint32_t b1 = __float_as_uint(Bs[nr * 36 + ks + tig + 4]);
                #pragma unroll
                for (int mt = 0; mt < 4; mt++)
                    mma8(c[mt][nt], a[mt], b0, b1);
            }
        }
        if (more) store_tiles(buf ^ 1);
        __syncthreads();
    }

    // ---- epilogue ----
    #pragma unroll
    for (int mt = 0; mt < 4; mt++) {
        #pragma unroll
        for (int nt = 0; nt < NTILES; nt++) {
            const int col = wn + nt * 8 + tig * 2;
            #pragma unroll
            for (int half = 0; half < 2; half++) {
                const int m = m0 + wm + mt * 16 + gID + half * 8;
                if (m >= M) continue;
                float v0 = c[mt][nt][half * 2 + 0];
                float v1 = c[mt][nt][half * 2 + 1];
                v0 += __ldg(&bias[col]);
                v1 += __ldg(&bias[col + 1]);
                if (EPI == EPI_RELU_BN) {
                    v0 = fmaxf(v0, 0.0f);
                    v1 = fmaxf(v1, 0.0f);
                    v0 = (v0 - __ldg(&mu[col]))     * rsqrtf(__ldg(&var[col])     + 1e-5f) * __ldg(&gmm[col])     + __ldg(&bet[col]);
                    v1 = (v1 - __ldg(&mu[col + 1])) * rsqrtf(__ldg(&var[col + 1]) + 1e-5f) * __ldg(&gmm[col + 1]) + __ldg(&bet[col + 1]);
                } else if (EPI == EPI_RELU_RES) {
                    float2 rr = *(const float2*)(res + (size_t)m * FDIM + col);
                    v0 = fmaxf(v0, 0.0f) + rr.x;
                    v1 = fmaxf(v1, 0.0f) + rr.y;
                } else if (EPI == EPI_RELU) {
                    v0 = fmaxf(v0, 0.0f);
                    v1 = fmaxf(v1, 0.0f);
                }
                *(float2*)(C + (size_t)m * ldc + col) = make_float2(v0, v1);
            }
        }
    }
}

// ============== fused MLP head: out[M,64] = relu(A@Wm1^T + bm1) @ Wm2^T + bm2 ==============
// Phase 1: C tile 256x128 (identical partitioning to k_gemm_tc<128>), K=128.
// Hidden tile stored as tf32 in SMEM (stride 132 -> bank (4m+k)%32, fragment reads conflict-free).
// Phase 2: K=128 from SMEM, N=64, writes d_out directly.
__global__ void __launch_bounds__(256, 1)
k_gemm_head(const float* __restrict__ A, int M,
            const float* __restrict__ Wm1, const float* __restrict__ bm1,
            const float* __restrict__ Wm2, const float* __restrict__ bm2,
            float* __restrict__ out) {
    extern __shared__ float sm[];
    float* const AsBase = sm;                       // phase1: 2 * 256 * 36
    float* const BsBase = sm + 2 * 256 * 36;        // phase1: 2 * 128 * 36  (ends at float 27648)
    float* const Hs     = sm;                       // phase2: 256 * 132 = 33792 floats (aliases As/Bs)
    float* const Ws     = sm + 256 * 132;           // phase2: 64 * 132 = 8448 floats (disjoint)

    const int tid  = threadIdx.x;
    const int wid  = tid >> 5;
    const int lane = tid & 31;
    const int gID  = lane >> 2;
    const int tig  = lane & 3;
    const int m0   = blockIdx.x * 256;

    const int wm = (wid & 3) * 64;
    const int wn = (wid >> 2) * 64;    // phase1 NT=128

    // ---- stage Wm2 into Ws (disjoint from phase-1 buffers; no sync needed yet) ----
    #pragma unroll
    for (int it = 0; it < 8; it++) {
        int i = tid + it * 256;
        int row = i >> 5, q = i & 31;           // 64 rows x 32 float4
        float4 v = *(const float4*)(Wm2 + (size_t)row * 128 + q * 4);
        uint4 t = make_uint4(f2tf32(v.x), f2tf32(v.y), f2tf32(v.z), f2tf32(v.w));
        *(uint4*)(Ws + row * 132 + q * 4) = t;
    }

    // ================= phase 1: H = relu(A @ Wm1^T + bm1) =================
    float c[4][8][4];
    #pragma unroll
    for (int i = 0; i < 4; i++)
        #pragma unroll
        for (int j = 0; j < 8; j++)
            #pragma unroll
            for (int q = 0; q < 4; q++) c[i][j][q] = 0.0f;

    float4 ra[8];
    float4 rb[4];
    auto load_regs = [&](int kt) {
        #pragma unroll
        for (int it = 0; it < 8; it++) {
            int i = tid + it * 256;
            int row = i >> 3, q = i & 7;
            int gm = m0 + row;
            ra[it] = (gm < M) ? *(const float4*)(A + (size_t)gm * FDIM + kt + q * 4)
                              : make_float4(0.f, 0.f, 0.f, 0.f);
        }
        #pragma unroll
        for (int it = 0; it < 4; it++) {
            int i = tid + it * 256;
            int row = i >> 3, q = i & 7;
            rb[it] = *(const float4*)(Wm1 + (size_t)row * 128 + kt + q * 4);
        }
    };
    auto store_tiles = [&](int buf) {
        float* As = AsBase + buf * (256 * 36);
        float* Bs = BsBase + buf * (128 * 36);
        #pragma unroll
        for (int it = 0; it < 8; it++) {
            int i = tid + it * 256;
            int row = i >> 3, q = i & 7;
            uint4 t = make_uint4(f2tf32(ra[it].x), f2tf32(ra[it].y), f2tf32(ra[it].z), f2tf32(ra[it].w));
            *(uint4*)(As + row * 36 + q * 4) = t;
        }
        #pragma unroll
        for (int it = 0; it < 4; it++) {
            int i = tid + it * 256;
            int row = i >> 3, q = i & 7;
            uint4 t = make_uint4(f2tf32(rb[it].x), f2tf32(rb[it].y), f2tf32(rb[it].z), f2tf32(rb[it].w));
            *(uint4*)(Bs + row * 36 + q * 4) = t;
        }
    };

    load_regs(0);
    store_tiles(0);
    __syncthreads();

    #pragma unroll
    for (int ch = 0; ch < 4; ch++) {
        const int buf = ch & 1;
        const bool more = (ch < 3);
        if (more) load_regs((ch + 1) << 5);

        const float* As = AsBase + buf * (256 * 36);
        const float* Bs = BsBase + buf * (128 * 36);

        #pragma unroll
        for (int ks = 0; ks < 32; ks += 8) {
            uint32_t a[4][4];
            #pragma unroll
            for (int mt = 0; mt < 4; mt++) {
                const int r = wm + mt * 16 + gID;
                a[mt][0] = __float_as_uint(As[r * 36 + ks + tig]);
                a[mt][1] = __float_as_uint(As[(r + 8) * 36 + ks + tig]);
                a[mt][2] = __float_as_uint(As[r * 36 + ks + tig + 4]);
                a[mt][3] = __float_as_uint(As[(r + 8) * 36 + ks + tig + 4]);
            }
            #pragma unroll
            for (int nt = 0; nt < 8; nt++) {
                const int nr = wn + nt * 8 + gID;
                uint32_t b0 = __float_as_uint(Bs[nr * 36 + ks + tig]);
                uint32_t b1 = __float_as_uint(Bs[nr * 36 + ks + tig + 4]);
                #pragma unroll
                for (int mt = 0; mt < 4; mt++)
                    mma8(c[mt][nt], a[mt], b0, b1);
            }
        }
        if (more) store_tiles(buf ^ 1);
        __syncthreads();
    }

    // ---- epilogue 1: relu+bias, write tf32 hidden tile to Hs ----
    #pragma unroll
    for (int mt = 0; mt < 4; mt++) {
        #pragma unroll
        for (int nt = 0; nt < 8; nt++) {
            const int col = wn + nt * 8 + tig * 2;
            #pragma unroll
            for (int half = 0; half < 2; half++) {
                const int ml = wm + mt * 16 + gID + half * 8;
                float v0 = fmaxf(c[mt][nt][half * 2 + 0] + __ldg(&bm1[col]),     0.0f);
                float v1 = fmaxf(c[mt][nt][half * 2 + 1] + __ldg(&bm1[col + 1]), 0.0f);
                Hs[ml * 132 + col]     = __uint_as_float(f2tf32(v0));
                Hs[ml * 132 + col + 1] = __uint_as_float(f2tf32(v1));
            }
        }
    }
    __syncthreads();

    // ================= phase 2: out = H @ Wm2^T + bm2 =================
    const int wn2 = (wid >> 2) * 32;   // NT=64
    float c2[4][4][4];
    #pragma unroll
    for (int i = 0; i < 4; i++)
        #pragma unroll
        for (int j = 0; j < 4; j++)
            #pragma unroll
            for (int q = 0; q < 4; q++) c2[i][j][q] = 0.0f;

    #pragma unroll
    for (int ks = 0; ks < 128; ks += 8) {
        uint32_t a[4][4];
        #pragma unroll
        for (int mt = 0; mt < 4; mt++) {
            const int r = wm + mt * 16 + gID;
            a[mt][0] = __float_as_uint(Hs[r * 132 + ks + tig]);
            a[mt][1] = __float_as_uint(Hs[(r + 8) * 132 + ks + tig]);
            a[mt][2] = __float_as_uint(Hs[r * 132 + ks + tig + 4]);
            a[mt][3] = __float_as_uint(Hs[(r + 8) * 132 + ks + tig + 4]);
        }
        #pragma unroll
        for (int nt = 0; nt < 4; nt++) {
            const int nr = wn2 + nt * 8 + gID;
            uint32_t b0 = __float_as_uint(Ws[nr * 132 + ks + tig]);
            uint32_t b1 = __float_as_uint(Ws[nr * 132 + ks + tig + 4]);
            #pragma unroll
            for (int mt = 0; mt < 4; mt++)
                mma8(c2[mt][nt], a[mt], b0, b1);
        }
    }

    // ---- epilogue 2: bias, write to out ----
    #pragma unroll
    for (int mt = 0; mt < 4; mt++) {
        #pragma unroll
        for (int nt = 0; nt < 4; nt++) {
            const int col = wn2 + nt * 8 + tig * 2;
            #pragma unroll
            for (int half = 0; half < 2; half++) {
                const int m = m0 + wm + mt * 16 + gID + half * 8;
                if (m >= M) continue;
                float v0 = c2[mt][nt][half * 2 + 0] + __ldg(&bm2[col]);
                float v1 = c2[mt][nt][half * 2 + 1] + __ldg(&bm2[col + 1]);
                *(float2*)(out + (size_t)m * 64 + col) = make_float2(v0, v1);
            }
        }
    }
}

// ======================= launch =======================
extern "C" void kernel_launch(void* const* d_in, const int* in_sizes, int n_in,
                              void* d_out, int out_size) {
    const float* feat  = (const float*)d_in[0];
    const int*   esrc  = (const int*)d_in[1];
    const int*   edst  = (const int*)d_in[2];
    const float* W1    = (const float*)d_in[3];
    const float* b1    = (const float*)d_in[4];
    const float* gamma = (const float*)d_in[5];
    const float* beta  = (const float*)d_in[6];
    const float* mean  = (const float*)d_in[7];
    const float* var   = (const float*)d_in[8];
    const float* W3    = (const float*)d_in[9];
    const float* b3    = (const float*)d_in[10];
    const float* Wm1   = (const float*)d_in[11];
    const float* bm1   = (const float*)d_in[12];
    const float* Wm2   = (const float*)d_in[13];
    const float* bm2   = (const float*)d_in[14];

    const int n  = in_sizes[0] / FDIM;
    const int ne = in_sizes[1];

    int *deg, *off, *pos, *blk, *csrc;
    float *dinv, *b0, *bb1, *b2, *b3buf, *w1t, *w3t;
    cudaGetSymbolAddress((void**)&deg,  g_deg);
    cudaGetSymbolAddress((void**)&off,  g_off);
    cudaGetSymbolAddress((void**)&pos,  g_pos);
    cudaGetSymbolAddress((void**)&blk,  g_blk);
    cudaGetSymbolAddress((void**)&csrc, g_csrc);
    cudaGetSymbolAddress((void**)&dinv, g_dinv);
    cudaGetSymbolAddress((void**)&b0,   g_b0);
    cudaGetSymbolAddress((void**)&bb1,  g_b1);
    cudaGetSymbolAddress((void**)&b2,   g_b2);
    cudaGetSymbolAddress((void**)&b3buf, g_b3);
    cudaGetSymbolAddress((void**)&w1t,  g_w1t);
    cudaGetSymbolAddress((void**)&w3t,  g_w3t);

    const int nb    = (n + 511) / 512;
    const int agrid = (n + 7) / 8;
    const int ggrid = (n + 255) / 256;

    const int SMEM_N128 = (2 * 256 * 36 + 2 * 128 * 36) * 4;  // 110592
    const int SMEM_HEAD = (256 * 132 + 64 * 132) * 4;          // 168960
    cudaFuncSetAttribute(k_gemm_tc<128, EPI_RELU_BN>,  cudaFuncAttributeMaxDynamicSharedMemorySize, SMEM_N128);
    cudaFuncSetAttribute(k_gemm_tc<128, EPI_RELU_RES>, cudaFuncAttributeMaxDynamicSharedMemorySize, SMEM_N128);
    cudaFuncSetAttribute(k_gemm_head,                  cudaFuncAttributeMaxDynamicSharedMemorySize, SMEM_HEAD);

    // ---- CSR build + weight transforms ----
    cudaMemsetAsync(deg, 0, (size_t)n * sizeof(int));
    k_degi<<<(ne + 255) / 256, 256>>>(edst, ne, deg);
    k_scan1<<<nb, 512>>>(deg, n, off, blk, dinv);
    k_scan2p<<<1, 256>>>(blk, nb, off + n);
    k_scan3<<<nb, 512>>>(off, pos, blk, n);
    k_bucket<<<(ne + 255) / 256, 256>>>(esrc, edst, ne, pos, csrc);
    k_wt2<<<(2 * 128 * 128 + 255) / 256, 256>>>(W1, w1t, W3, w3t);

    // ---- Cheb layer 1: G0 = Ahat(feat), G1 = Ahat(G0) ----
    k_ahat<<<agrid, 256>>>(feat, dinv, off, csrc, bb1, n);
    k_ahat<<<agrid, 256>>>(bb1,  dinv, off, csrc, b2,  n);
    k_gemm_tc<128, EPI_RELU_BN><<<ggrid, 256, SMEM_N128>>>(feat, bb1, b2, n, 384, w1t, b1,
                                                           gamma, beta, mean, var,
                                                           (const float*)nullptr, b0, 128);

    // ---- Cheb layer 2 ----
    k_ahat<<<agrid, 256>>>(b0,  dinv, off, csrc, bb1, n);
    k_ahat<<<agrid, 256>>>(bb1, dinv, off, csrc, b2,  n);
    k_gemm_tc<128, EPI_RELU_RES><<<ggrid, 256, SMEM_N128>>>(b0, bb1, b2, n, 384, w3t, b3,
                                                            (const float*)nullptr, (const float*)nullptr,
                                                            (const float*)nullptr, (const float*)nullptr,
                                                            b0, b3buf, 128);

    // ---- fused MLP head ----
    k_gemm_head<<<ggrid, 256, SMEM_HEAD>>>(b3buf, n, Wm1, bm1, Wm2, bm2, (float*)d_out);
}

// round 13
// speedup vs baseline: 1.5417x; 1.0049x over previous
#include <cuda_runtime.h>
#include <cstdint>
#include <cstddef>

#define NMAX 100000
#define NEMAX 600000
#define FDIM 128

// ---- static device scratch (no allocations allowed) ----
__device__ int   g_deg[NMAX];
__device__ int   g_off[NMAX + 1];
__device__ int   g_pos[NMAX];
__device__ int   g_blk[256];
__device__ int   g_csrc[NEMAX];
__device__ float g_dinv[NMAX];
__device__ float g_b0[NMAX * FDIM];   // y (layer1 out / residual)
__device__ float g_b1[NMAX * FDIM];   // G0 / reuse
__device__ float g_b2[NMAX * FDIM];   // G1
__device__ float g_b3[NMAX * FDIM];   // m1
__device__ float g_w1t[128 * 384];
__device__ float g_w3t[128 * 384];

__device__ __forceinline__ uint32_t f2tf32(float x) {
    uint32_t r;
    asm("cvt.rna.tf32.f32 %0, %1;" : "=r"(r) : "f"(x));
    return r;
}

// ======================= CSR build =======================
__global__ void k_degi(const int* __restrict__ dst, int ne, int* __restrict__ deg) {
    int i = blockIdx.x * blockDim.x + threadIdx.x;
    if (i < ne) atomicAdd(&deg[dst[i]], 1);
}

// block-local inclusive scan + dinv computation fused
__global__ void k_scan1(const int* __restrict__ deg, int n,
                        int* __restrict__ excl, int* __restrict__ blk,
                        float* __restrict__ dinv) {
    __shared__ int sh[512];
    int tid = threadIdx.x;
    int i = blockIdx.x * 512 + tid;
    int v = (i < n) ? deg[i] : 0;
    if (i < n) dinv[i] = rsqrtf((float)(v > 1 ? v : 1));
    sh[tid] = v;
    __syncthreads();
    #pragma unroll
    for (int ofs = 1; ofs < 512; ofs <<= 1) {
        int t = (tid >= ofs) ? sh[tid - ofs] : 0;
        __syncthreads();
        sh[tid] += t;
        __syncthreads();
    }
    if (i < n) excl[i] = sh[tid] - v;
    if (tid == 511) blk[blockIdx.x] = sh[511];
}

// parallel exclusive scan of block totals (nb <= 256)
__global__ void k_scan2p(int* __restrict__ blk, int nb, int* __restrict__ off_n) {
    __shared__ int sh[256];
    int tid = threadIdx.x;
    int v = (tid < nb) ? blk[tid] : 0;
    sh[tid] = v;
    __syncthreads();
    #pragma unroll
    for (int ofs = 1; ofs < 256; ofs <<= 1) {
        int t = (tid >= ofs) ? sh[tid - ofs] : 0;
        __syncthreads();
        sh[tid] += t;
        __syncthreads();
    }
    if (tid < nb) blk[tid] = sh[tid] - v;
    if (tid == 255) *off_n = sh[255];
}

__global__ void k_scan3(int* __restrict__ off, int* __restrict__ pos,
                        const int* __restrict__ blk, int n) {
    int i = blockIdx.x * 512 + threadIdx.x;
    if (i < n) {
        int o = off[i] + blk[blockIdx.x];
        off[i] = o;
        pos[i] = o;
    }
}

__global__ void k_bucket(const int* __restrict__ src, const int* __restrict__ dst, int ne,
                         int* __restrict__ pos, int* __restrict__ csrc) {
    int e = blockIdx.x * blockDim.x + threadIdx.x;
    if (e < ne) {
        int p = atomicAdd(&pos[dst[e]], 1);
        csrc[p] = src[e];
    }
}

// ======================= weight transform (both layers in one launch) =======================
// W [128,384] = [W0|W1|W2] -> W' = [W0-W1+W2 | W1-4W2 | 2W2]
__global__ void k_wt2(const float* __restrict__ WA, float* __restrict__ WtA,
                      const float* __restrict__ WB, float* __restrict__ WtB) {
    int i = blockIdx.x * blockDim.x + threadIdx.x;
    if (i >= 2 * 128 * 128) return;
    const float* W = (i < 128 * 128) ? WA : WB;
    float* Wt      = (i < 128 * 128) ? WtA : WtB;
    i &= (128 * 128 - 1);
    int o = i >> 7, k = i & 127;
    float w0 = W[o * 384 + k];
    float w1 = W[o * 384 + 128 + k];
    float w2 = W[o * 384 + 256 + k];
    Wt[o * 384 + k]       = w0 - w1 + w2;
    Wt[o * 384 + 128 + k] = w1 - 4.0f * w2;
    Wt[o * 384 + 256 + k] = 2.0f * w2;
}

// ======================= pure A_hat application =======================
// Xout[v] = (sum_{s in N(v)} Xin[s]*dinv[s]) * dinv[v]   — warp per node, 4-way unrolled (MLP=4)
__global__ void __launch_bounds__(256)
k_ahat(const float* __restrict__ Xin,
       const float* __restrict__ dinv,
       const int* __restrict__ off, const int* __restrict__ csrc,
       float* __restrict__ Xout, int n) {
    int v = blockIdx.x * 8 + (threadIdx.x >> 5);
    if (v >= n) return;
    int lane = threadIdx.x & 31;
    int beg = __ldg(&off[v]);
    int end = __ldg(&off[v + 1]);

    float4 acc = make_float4(0.f, 0.f, 0.f, 0.f);
    int j = beg;
    for (; j + 4 <= end; j += 4) {
        int s0 = __ldg(&csrc[j]);
        int s1 = __ldg(&csrc[j + 1]);
        int s2 = __ldg(&csrc[j + 2]);
        int s3 = __ldg(&csrc[j + 3]);
        float c0 = __ldg(&dinv[s0]);
        float c1 = __ldg(&dinv[s1]);
        float c2 = __ldg(&dinv[s2]);
        float c3 = __ldg(&dinv[s3]);
        float4 x0 = *(const float4*)(Xin + (size_t)s0 * FDIM + lane * 4);
        float4 x1 = *(const float4*)(Xin + (size_t)s1 * FDIM + lane * 4);
        float4 x2 = *(const float4*)(Xin + (size_t)s2 * FDIM + lane * 4);
        float4 x3 = *(const float4*)(Xin + (size_t)s3 * FDIM + lane * 4);
        acc.x += x0.x * c0 + x1.x * c1 + x2.x * c2 + x3.x * c3;
        acc.y += x0.y * c0 + x1.y * c1 + x2.y * c2 + x3.y * c3;
        acc.z += x0.z * c0 + x1.z * c1 + x2.z * c2 + x3.z * c3;
        acc.w += x0.w * c0 + x1.w * c1 + x2.w * c2 + x3.w * c3;
    }
    if (j + 2 <= end) {
        int s0 = __ldg(&csrc[j]);
        int s1 = __ldg(&csrc[j + 1]);
        float c0 = __ldg(&dinv[s0]);
        float c1 = __ldg(&dinv[s1]);
        float4 x0 = *(const float4*)(Xin + (size_t)s0 * FDIM + lane * 4);
        float4 x1 = *(const float4*)(Xin + (size_t)s1 * FDIM + lane * 4);
        acc.x += x0.x * c0 + x1.x * c1;
        acc.y += x0.y * c0 + x1.y * c1;
        acc.z += x0.z * c0 + x1.z * c1;
        acc.w += x0.w * c0 + x1.w * c1;
        j += 2;
    }
    if (j < end) {
        int s = __ldg(&csrc[j]);
        float c = __ldg(&dinv[s]);
        float4 x = *(const float4*)(Xin + (size_t)s * FDIM + lane * 4);
        acc.x += x.x * c;
        acc.y += x.y * c;
        acc.z += x.z * c;
        acc.w += x.w * c;
    }
    float dv = __ldg(&dinv[v]);
    float4 r = make_float4(acc.x * dv, acc.y * dv, acc.z * dv, acc.w * dv);
    *(float4*)(Xout + (size_t)v * FDIM + lane * 4) = r;
}

// ============== tf32 mma.sync GEMM: C[256-tile, NT] = [A0|A1|A2] @ W[NT,K]^T + epilogue ==============
#define EPI_BIAS     0
#define EPI_RELU_BN  1
#define EPI_RELU_RES 2
#define EPI_RELU     3

__device__ __forceinline__ void mma8(float c[4], const uint32_t a[4], uint32_t b0, uint32_t b1) {
    asm volatile(
        "mma.sync.aligned.m16n8k8.row.col.f32.tf32.tf32.f32 "
        "{%0,%1,%2,%3}, {%4,%5,%6,%7}, {%8,%9}, {%0,%1,%2,%3};"
        : "+f"(c[0]), "+f"(c[1]), "+f"(c[2]), "+f"(c[3])
        : "r"(a[0]), "r"(a[1]), "r"(a[2]), "r"(a[3]), "r"(b0), "r"(b1));
}

template<int NT, int EPI>
__global__ void __launch_bounds__(256, 1)
k_gemm_tc(const float* __restrict__ A0, const float* __restrict__ A1, const float* __restrict__ A2,
          int M, int K,
          const float* __restrict__ W,
          const float* __restrict__ bias,
          const float* __restrict__ gmm, const float* __restrict__ bet,
          const float* __restrict__ mu,  const float* __restrict__ var,
          const float* __restrict__ res,
          float* __restrict__ C, int ldc) {
    extern __shared__ float sm[];
    float* const AsBase = sm;                     // 2 * 256 * 36
    float* const BsBase = sm + 2 * 256 * 36;      // 2 * NT * 36

    const int tid  = threadIdx.x;
    const int wid  = tid >> 5;
    const int lane = tid & 31;
    const int gID  = lane >> 2;
    const int tig  = lane & 3;
    const int m0   = blockIdx.x * 256;

    const int wm = (wid & 3) * 64;
    const int wn = (wid >> 2) * (NT / 2);
    constexpr int NTILES = NT / 16;
    constexpr int BITER  = NT / 32;

    float c[4][NTILES][4];
    #pragma unroll
    for (int i = 0; i < 4; i++)
        #pragma unroll
        for (int j = 0; j < NTILES; j++)
            #pragma unroll
            for (int q = 0; q < 4; q++) c[i][j][q] = 0.0f;

    const int nch = K >> 5;

    float4 ra[8];
    float4 rb[BITER];

    auto load_regs = [&](int kt) {
        const float* Ap = (kt < 128) ? A0 : ((kt < 256) ? A1 : A2);
        const int kk = kt & 127;
        #pragma unroll
        for (int it = 0; it < 8; it++) {
            int i = tid + it * 256;
            int row = i >> 3, q = i & 7;
            int gm = m0 + row;
            ra[it] = (gm < M) ? *(const float4*)(Ap + (size_t)gm * FDIM + kk + q * 4)
                              : make_float4(0.f, 0.f, 0.f, 0.f);
        }
        #pragma unroll
        for (int it = 0; it < BITER; it++) {
            int i = tid + it * 256;
            int row = i >> 3, q = i & 7;
            rb[it] = *(const float4*)(W + (size_t)row * K + kt + q * 4);
        }
    };
    auto store_tiles = [&](int buf) {
        float* As = AsBase + buf * (256 * 36);
        float* Bs = BsBase + buf * (NT * 36);
        #pragma unroll
        for (int it = 0; it < 8; it++) {
            int i = tid + it * 256;
            int row = i >> 3, q = i & 7;
            uint4 t = make_uint4(f2tf32(ra[it].x), f2tf32(ra[it].y), f2tf32(ra[it].z), f2tf32(ra[it].w));
            *(uint4*)(As + row * 36 + q * 4) = t;
        }
        #pragma unroll
        for (int it = 0; it < BITER; it++) {
            int i = tid + it * 256;
            int row = i >> 3, q = i & 7;
            uint4 t = make_uint4(f2tf32(rb[it].x), f2tf32(rb[it].y), f2tf32(rb[it].z), f2tf32(rb[it].w));
            *(uint4*)(Bs + row * 36 + q * 4) = t;
        }
    };

    load_regs(0);
    store_tiles(0);
    __syncthreads();

    for (int ch = 0; ch < nch; ch++) {
        const int buf = ch & 1;
        const bool more = (ch + 1 < nch);
        if (more) load_regs((ch + 1) << 5);

        const float* As = AsBase + buf * (256 * 36);
        const float* Bs = BsBase + buf * (NT * 36);

        #pragma unroll
        for (int ks = 0; ks < 32; ks += 8) {
            uint32_t a[4][4];
            #pragma unroll
            for (int mt = 0; mt < 4; mt++) {
                const int r = wm + mt * 16 + gID;
                a[mt][0] = __float_as_uint(As[r * 36 + ks + tig]);
                a[mt][1] = __float_as_uint(As[(r + 8) * 36 + ks + tig]);
                a[mt][2] = __float_as_uint(As[r * 36 + ks + tig + 4]);
                a[mt][3] = __float_as_uint(As[(r + 8) * 36 + ks + tig + 4]);
            }
            #pragma unroll
            for (int nt = 0; nt < NTILES; nt++) {
                const int nr = wn + nt * 8 + gID;
                uint32_t b0 = __float_as_uint(Bs[nr * 36 + ks + tig]);
                uint32_t b1 = __float_as_uint(Bs[nr * 36 + ks + tig + 4]);
                #pragma unroll
                for (int mt = 0; mt < 4; mt++)
                    mma8(c[mt][nt], a[mt], b0, b1);
            }
        }
        if (more) store_tiles(buf ^ 1);
        __syncthreads();
    }

    // ---- epilogue ----
    #pragma unroll
    for (int mt = 0; mt < 4; mt++) {
        #pragma unroll
        for (int nt = 0; nt < NTILES; nt++) {
            const int col = wn + nt * 8 + tig * 2;
            #pragma unroll
            for (int half = 0; half < 2; half++) {
                const int m = m0 + wm + mt * 16 + gID + half * 8;
                if (m >= M) continue;
                float v0 = c[mt][nt][half * 2 + 0];
                float v1 = c[mt][nt][half * 2 + 1];
                v0 += __ldg(&bias[col]);
                v1 += __ldg(&bias[col + 1]);
                if (EPI == EPI_RELU_BN) {
                    v0 = fmaxf(v0, 0.0f);
                    v1 = fmaxf(v1, 0.0f);
                    v0 = (v0 - __ldg(&mu[col]))     * rsqrtf(__ldg(&var[col])     + 1e-5f) * __ldg(&gmm[col])     + __ldg(&bet[col]);
                    v1 = (v1 - __ldg(&mu[col + 1])) * rsqrtf(__ldg(&var[col + 1]) + 1e-5f) * __ldg(&gmm[col + 1]) + __ldg(&bet[col + 1]);
                } else if (EPI == EPI_RELU_RES) {
                    float2 rr = *(const float2*)(res + (size_t)m * FDIM + col);
                    v0 = fmaxf(v0, 0.0f) + rr.x;
                    v1 = fmaxf(v1, 0.0f) + rr.y;
                } else if (EPI == EPI_RELU) {
                    v0 = fmaxf(v0, 0.0f);
                    v1 = fmaxf(v1, 0.0f);
                }
                *(float2*)(C + (size_t)m * ldc + col) = make_float2(v0, v1);
            }
        }
    }
}

// ============== fused MLP head: out[M,64] = relu(A@Wm1^T + bm1) @ Wm2^T + bm2 ==============
__global__ void __launch_bounds__(256, 1)
k_gemm_head(const float* __restrict__ A, int M,
            const float* __restrict__ Wm1, const float* __restrict__ bm1,
            const float* __restrict__ Wm2, const float* __restrict__ bm2,
            float* __restrict__ out) {
    extern __shared__ float sm[];
    float* const AsBase = sm;                       // phase1: 2 * 256 * 36
    float* const BsBase = sm + 2 * 256 * 36;        // phase1: 2 * 128 * 36
    float* const Hs     = sm;                       // phase2: 256 * 132 (aliases As/Bs)
    float* const Ws     = sm + 256 * 132;           // phase2: 64 * 132 (disjoint)

    const int tid  = threadIdx.x;
    const int wid  = tid >> 5;
    const int lane = tid & 31;
    const int gID  = lane >> 2;
    const int tig  = lane & 3;
    const int m0   = blockIdx.x * 256;

    const int wm = (wid & 3) * 64;
    const int wn = (wid >> 2) * 64;    // phase1 NT=128

    // ---- stage Wm2 into Ws ----
    #pragma unroll
    for (int it = 0; it < 8; it++) {
        int i = tid + it * 256;
        int row = i >> 5, q = i & 31;
        float4 v = *(const float4*)(Wm2 + (size_t)row * 128 + q * 4);
        uint4 t = make_uint4(f2tf32(v.x), f2tf32(v.y), f2tf32(v.z), f2tf32(v.w));
        *(uint4*)(Ws + row * 132 + q * 4) = t;
    }

    // ================= phase 1: H = relu(A @ Wm1^T + bm1) =================
    float c[4][8][4];
    #pragma unroll
    for (int i = 0; i < 4; i++)
        #pragma unroll
        for (int j = 0; j < 8; j++)
            #pragma unroll
            for (int q = 0; q < 4; q++) c[i][j][q] = 0.0f;

    float4 ra[8];
    float4 rb[4];
    auto load_regs = [&](int kt) {
        #pragma unroll
        for (int it = 0; it < 8; it++) {
            int i = tid + it * 256;
            int row = i >> 3, q = i & 7;
            int gm = m0 + row;
            ra[it] = (gm < M) ? *(const float4*)(A + (size_t)gm * FDIM + kt + q * 4)
                              : make_float4(0.f, 0.f, 0.f, 0.f);
        }
        #pragma unroll
        for (int it = 0; it < 4; it++) {
            int i = tid + it * 256;
            int row = i >> 3, q = i & 7;
            rb[it] = *(const float4*)(Wm1 + (size_t)row * 128 + kt + q * 4);
        }
    };
    auto store_tiles = [&](int buf) {
        float* As = AsBase + buf * (256 * 36);
        float* Bs = BsBase + buf * (128 * 36);
        #pragma unroll
        for (int it = 0; it < 8; it++) {
            int i = tid + it * 256;
            int row = i >> 3, q = i & 7;
            uint4 t = make_uint4(f2tf32(ra[it].x), f2tf32(ra[it].y), f2tf32(ra[it].z), f2tf32(ra[it].w));
            *(uint4*)(As + row * 36 + q * 4) = t;
        }
        #pragma unroll
        for (int it = 0; it < 4; it++) {
            int i = tid + it * 256;
            int row = i >> 3, q = i & 7;
            uint4 t = make_uint4(f2tf32(rb[it].x), f2tf32(rb[it].y), f2tf32(rb[it].z), f2tf32(rb[it].w));
            *(uint4*)(Bs + row * 36 + q * 4) = t;
        }
    };

    load_regs(0);
    store_tiles(0);
    __syncthreads();

    #pragma unroll
    for (int ch = 0; ch < 4; ch++) {
        const int buf = ch & 1;
        const bool more = (ch < 3);
        if (more) load_regs((ch + 1) << 5);

        const float* As = AsBase + buf * (256 * 36);
        const float* Bs = BsBase + buf * (128 * 36);

        #pragma unroll
        for (int ks = 0; ks < 32; ks += 8) {
            uint32_t a[4][4];
            #pragma unroll
            for (int mt = 0; mt < 4; mt++) {
                const int r = wm + mt * 16 + gID;
                a[mt][0] = __float_as_uint(As[r * 36 + ks + tig]);
                a[mt][1] = __float_as_uint(As[(r + 8) * 36 + ks + tig]);
                a[mt][2] = __float_as_uint(As[r * 36 + ks + tig + 4]);
                a[mt][3] = __float_as_uint(As[(r + 8) * 36 + ks + tig + 4]);
            }
            #pragma unroll
            for (int nt = 0; nt < 8; nt++) {
                const int nr = wn + nt * 8 + gID;
                uint32_t b0 = __float_as_uint(Bs[nr * 36 + ks + tig]);
                uint32_t b1 = __float_as_uint(Bs[nr * 36 + ks + tig + 4]);
                #pragma unroll
                for (int mt = 0; mt < 4; mt++)
                    mma8(c[mt][nt], a[mt], b0, b1);
            }
        }
        if (more) store_tiles(buf ^ 1);
        __syncthreads();
    }

    // ---- epilogue 1: relu+bias, write tf32 hidden tile to Hs ----
    #pragma unroll
    for (int mt = 0; mt < 4; mt++) {
        #pragma unroll
        for (int nt = 0; nt < 8; nt++) {
            const int col = wn + nt * 8 + tig * 2;
            #pragma unroll
            for (int half = 0; half < 2; half++) {
                const int ml = wm + mt * 16 + gID + half * 8;
                float v0 = fmaxf(c[mt][nt][half * 2 + 0] + __ldg(&bm1[col]),     0.0f);
                float v1 = fmaxf(c[mt][nt][half * 2 + 1] + __ldg(&bm1[col + 1]), 0.0f);
                Hs[ml * 132 + col]     = __uint_as_float(f2tf32(v0));
                Hs[ml * 132 + col + 1] = __uint_as_float(f2tf32(v1));
            }
        }
    }
    __syncthreads();

    // ================= phase 2: out = H @ Wm2^T + bm2 =================
    const int wn2 = (wid >> 2) * 32;   // NT=64
    float c2[4][4][4];
    #pragma unroll
    for (int i = 0; i < 4; i++)
        #pragma unroll
        for (int j = 0; j < 4; j++)
            #pragma unroll
            for (int q = 0; q < 4; q++) c2[i][j][q] = 0.0f;

    #pragma unroll
    for (int ks = 0; ks < 128; ks += 8) {
        uint32_t a[4][4];
        #pragma unroll
        for (int mt = 0; mt < 4; mt++) {
            const int r = wm + mt * 16 + gID;
            a[mt][0] = __float_as_uint(Hs[r * 132 + ks + tig]);
            a[mt][1] = __float_as_uint(Hs[(r + 8) * 132 + ks + tig]);
            a[mt][2] = __float_as_uint(Hs[r * 132 + ks + tig + 4]);
            a[mt][3] = __float_as_uint(Hs[(r + 8) * 132 + ks + tig + 4]);
        }
        #pragma unroll
        for (int nt = 0; nt < 4; nt++) {
            const int nr = wn2 + nt * 8 + gID;
            uint32_t b0 = __float_as_uint(Ws[nr * 132 + ks + tig]);
            uint32_t b1 = __float_as_uint(Ws[nr * 132 + ks + tig + 4]);
            #pragma unroll
            for (int mt = 0; mt < 4; mt++)
                mma8(c2[mt][nt], a[mt], b0, b1);
        }
    }

    // ---- epilogue 2: bias, write to out ----
    #pragma unroll
    for (int mt = 0; mt < 4; mt++) {
        #pragma unroll
        for (int nt = 0; nt < 4; nt++) {
            const int col = wn2 + nt * 8 + tig * 2;
            #pragma unroll
            for (int half = 0; half < 2; half++) {
                const int m = m0 + wm + mt * 16 + gID + half * 8;
                if (m >= M) continue;
                float v0 = c2[mt][nt][half * 2 + 0] + __ldg(&bm2[col]);
                float v1 = c2[mt][nt][half * 2 + 1] + __ldg(&bm2[col + 1]);
                *(float2*)(out + (size_t)m * 64 + col) = make_float2(v0, v1);
            }
        }
    }
}

// ======================= launch =======================
extern "C" void kernel_launch(void* const* d_in, const int* in_sizes, int n_in,
                              void* d_out, int out_size) {
    const float* feat  = (const float*)d_in[0];
    const int*   esrc  = (const int*)d_in[1];
    const int*   edst  = (const int*)d_in[2];
    const float* W1    = (const float*)d_in[3];
    const float* b1    = (const float*)d_in[4];
    const float* gamma = (const float*)d_in[5];
    const float* beta  = (const float*)d_in[6];
    const float* mean  = (const float*)d_in[7];
    const float* var   = (const float*)d_in[8];
    const float* W3    = (const float*)d_in[9];
    const float* b3    = (const float*)d_in[10];
    const float* Wm1   = (const float*)d_in[11];
    const float* bm1   = (const float*)d_in[12];
    const float* Wm2   = (const float*)d_in[13];
    const float* bm2   = (const float*)d_in[14];

    const int n  = in_sizes[0] / FDIM;
    const int ne = in_sizes[1];

    int *deg, *off, *pos, *blk, *csrc;
    float *dinv, *b0, *bb1, *b2, *b3buf, *w1t, *w3t;
    cudaGetSymbolAddress((void**)&deg,  g_deg);
    cudaGetSymbolAddress((void**)&off,  g_off);
    cudaGetSymbolAddress((void**)&pos,  g_pos);
    cudaGetSymbolAddress((void**)&blk,  g_blk);
    cudaGetSymbolAddress((void**)&csrc, g_csrc);
    cudaGetSymbolAddress((void**)&dinv, g_dinv);
    cudaGetSymbolAddress((void**)&b0,   g_b0);
    cudaGetSymbolAddress((void**)&bb1,  g_b1);
    cudaGetSymbolAddress((void**)&b2,   g_b2);
    cudaGetSymbolAddress((void**)&b3buf, g_b3);
    cudaGetSymbolAddress((void**)&w1t,  g_w1t);
    cudaGetSymbolAddress((void**)&w3t,  g_w3t);

    const int nb    = (n + 511) / 512;
    const int agrid = (n + 7) / 8;
    const int ggrid = (n + 255) / 256;

    const int SMEM_N128 = (2 * 256 * 36 + 2 * 128 * 36) * 4;  // 110592
    const int SMEM_HEAD = (256 * 132 + 64 * 132) * 4;          // 168960
    cudaFuncSetAttribute(k_gemm_tc<128, EPI_RELU_BN>,  cudaFuncAttributeMaxDynamicSharedMemorySize, SMEM_N128);
    cudaFuncSetAttribute(k_gemm_tc<128, EPI_RELU_RES>, cudaFuncAttributeMaxDynamicSharedMemorySize, SMEM_N128);
    cudaFuncSetAttribute(k_gemm_head,                  cudaFuncAttributeMaxDynamicSharedMemorySize, SMEM_HEAD);

    // ---- CSR build + weight transforms ----
    cudaMemsetAsync(deg, 0, (size_t)n * sizeof(int));
    k_degi<<<(ne + 255) / 256, 256>>>(edst, ne, deg);
    k_scan1<<<nb, 512>>>(deg, n, off, blk, dinv);
    k_scan2p<<<1, 256>>>(blk, nb, off + n);
    k_scan3<<<nb, 512>>>(off, pos, blk, n);
    k_bucket<<<(ne + 255) / 256, 256>>>(esrc, edst, ne, pos, csrc);
    k_wt2<<<(2 * 128 * 128 + 255) / 256, 256>>>(W1, w1t, W3, w3t);

    // ---- Cheb layer 1: G0 = Ahat(feat), G1 = Ahat(G0) ----
    k_ahat<<<agrid, 256>>>(feat, dinv, off, csrc, bb1, n);
    k_ahat<<<agrid, 256>>>(bb1,  dinv, off, csrc, b2,  n);
    k_gemm_tc<128, EPI_RELU_BN><<<ggrid, 256, SMEM_N128>>>(feat, bb1, b2, n, 384, w1t, b1,
                                                           gamma, beta, mean, var,
                                                           (const float*)nullptr, b0, 128);

    // ---- Cheb layer 2 ----
    k_ahat<<<agrid, 256>>>(b0,  dinv, off, csrc, bb1, n);
    k_ahat<<<agrid, 256>>>(bb1, dinv, off, csrc, b2,  n);
    k_gemm_tc<128, EPI_RELU_RES><<<ggrid, 256, SMEM_N128>>>(b0, bb1, b2, n, 384, w3t, b3,
                                                            (const float*)nullptr, (const float*)nullptr,
                                                            (const float*)nullptr, (const float*)nullptr,
                                                            b0, b3buf, 128);

    // ---- fused MLP head ----
    k_gemm_head<<<ggrid, 256, SMEM_HEAD>>>(b3buf, n, Wm1, bm1, Wm2, bm2, (float*)d_out);
}

// round 14
// speedup vs baseline: 1.5490x; 1.0047x over previous
#include <cuda_runtime.h>
#include <cstdint>
#include <cstddef>

#define NMAX 100000
#define NEMAX 600000
#define FDIM 128

// ---- static device scratch (no allocations allowed) ----
__device__ int   g_deg[NMAX];
__device__ int   g_off[NMAX + 1];
__device__ int   g_pos[NMAX];
__device__ int   g_blk[256];
__device__ int   g_csrc[NEMAX];
__device__ float g_dinv[NMAX];
__device__ float g_b0[NMAX * FDIM];   // y (layer1 out / residual)
__device__ float g_b1[NMAX * FDIM];   // G0 / reuse
__device__ float g_b2[NMAX * FDIM];   // G1
__device__ float g_b3[NMAX * FDIM];   // m1
__device__ float g_w1t[128 * 384];
__device__ float g_w3t[128 * 384];

__device__ __forceinline__ uint32_t f2tf32(float x) {
    uint32_t r;
    asm("cvt.rna.tf32.f32 %0, %1;" : "=r"(r) : "f"(x));
    return r;
}

// ======================= CSR build =======================
__global__ void k_degi(const int* __restrict__ dst, int ne, int* __restrict__ deg) {
    int i = blockIdx.x * blockDim.x + threadIdx.x;
    if (i < ne) atomicAdd(&deg[dst[i]], 1);
}

// block-local inclusive scan + dinv  PLUS  weight transform in extra blocks.
// Blocks [0, nb): scan work. Blocks [nb, nb+64): W' transform (1 elem/thread).
__global__ void __launch_bounds__(512)
k_scan1_wt(const int* __restrict__ deg, int n, int nb,
           int* __restrict__ excl, int* __restrict__ blk,
           float* __restrict__ dinv,
           const float* __restrict__ WA, float* __restrict__ WtA,
           const float* __restrict__ WB, float* __restrict__ WtB) {
    if (blockIdx.x >= (unsigned)nb) {
        // ---- weight transform: [W0|W1|W2] -> [W0-W1+W2 | W1-4W2 | 2W2] ----
        int i = (blockIdx.x - nb) * 512 + threadIdx.x;   // 0 .. 32767
        const float* W = (i < 128 * 128) ? WA : WB;
        float* Wt      = (i < 128 * 128) ? WtA : WtB;
        i &= (128 * 128 - 1);
        int o = i >> 7, k = i & 127;
        float w0 = W[o * 384 + k];
        float w1 = W[o * 384 + 128 + k];
        float w2 = W[o * 384 + 256 + k];
        Wt[o * 384 + k]       = w0 - w1 + w2;
        Wt[o * 384 + 128 + k] = w1 - 4.0f * w2;
        Wt[o * 384 + 256 + k] = 2.0f * w2;
        return;
    }
    __shared__ int sh[512];
    int tid = threadIdx.x;
    int i = blockIdx.x * 512 + tid;
    int v = (i < n) ? deg[i] : 0;
    if (i < n) dinv[i] = rsqrtf((float)(v > 1 ? v : 1));
    sh[tid] = v;
    __syncthreads();
    #pragma unroll
    for (int ofs = 1; ofs < 512; ofs <<= 1) {
        int t = (tid >= ofs) ? sh[tid - ofs] : 0;
        __syncthreads();
        sh[tid] += t;
        __syncthreads();
    }
    if (i < n) excl[i] = sh[tid] - v;
    if (tid == 511) blk[blockIdx.x] = sh[511];
}

// scan3 with the block-total scan fused in: every block redundantly scans
// the (<=256-entry) block-sum array in shared, then applies its own prefix.
__global__ void __launch_bounds__(512)
k_scan3b(int* __restrict__ off, int* __restrict__ pos,
         const int* __restrict__ blk, int nb, int n) {
    __shared__ int sh[256];
    __shared__ int sh_ex[256];
    int tid = threadIdx.x;
    if (tid < 256) {
        int v = (tid < nb) ? blk[tid] : 0;
        sh[tid] = v;
        sh_ex[tid] = v;   // stash own value for exclusive computation
    }
    __syncthreads();
    #pragma unroll
    for (int ofs = 1; ofs < 256; ofs <<= 1) {
        int t = 0;
        if (tid < 256 && tid >= ofs) t = sh[tid - ofs];
        __syncthreads();
        if (tid < 256) sh[tid] += t;
        __syncthreads();
    }
    if (tid < 256) sh_ex[tid] = sh[tid] - sh_ex[tid];   // exclusive prefix
    __syncthreads();

    int i = blockIdx.x * 512 + tid;
    if (i < n) {
        int o = off[i] + sh_ex[blockIdx.x];
        off[i] = o;
        pos[i] = o;
    }
    if (blockIdx.x == 0 && tid == 0) off[n] = sh[255];  // grand total
}

__global__ void k_bucket(const int* __restrict__ src, const int* __restrict__ dst, int ne,
                         int* __restrict__ pos, int* __restrict__ csrc) {
    int e = blockIdx.x * blockDim.x + threadIdx.x;
    if (e < ne) {
        int p = atomicAdd(&pos[dst[e]], 1);
        csrc[p] = src[e];
    }
}

// ======================= pure A_hat application =======================
// Xout[v] = (sum_{s in N(v)} Xin[s]*dinv[s]) * dinv[v]   — warp per node, 4-way unrolled
__global__ void __launch_bounds__(256)
k_ahat(const float* __restrict__ Xin,
       const float* __restrict__ dinv,
       const int* __restrict__ off, const int* __restrict__ csrc,
       float* __restrict__ Xout, int n) {
    int v = blockIdx.x * 8 + (threadIdx.x >> 5);
    if (v >= n) return;
    int lane = threadIdx.x & 31;
    int beg = __ldg(&off[v]);
    int end = __ldg(&off[v + 1]);

    float4 acc = make_float4(0.f, 0.f, 0.f, 0.f);
    int j = beg;
    for (; j + 4 <= end; j += 4) {
        int s0 = __ldg(&csrc[j]);
        int s1 = __ldg(&csrc[j + 1]);
        int s2 = __ldg(&csrc[j + 2]);
        int s3 = __ldg(&csrc[j + 3]);
        float c0 = __ldg(&dinv[s0]);
        float c1 = __ldg(&dinv[s1]);
        float c2 = __ldg(&dinv[s2]);
        float c3 = __ldg(&dinv[s3]);
        float4 x0 = *(const float4*)(Xin + (size_t)s0 * FDIM + lane * 4);
        float4 x1 = *(const float4*)(Xin + (size_t)s1 * FDIM + lane * 4);
        float4 x2 = *(const float4*)(Xin + (size_t)s2 * FDIM + lane * 4);
        float4 x3 = *(const float4*)(Xin + (size_t)s3 * FDIM + lane * 4);
        acc.x += x0.x * c0 + x1.x * c1 + x2.x * c2 + x3.x * c3;
        acc.y += x0.y * c0 + x1.y * c1 + x2.y * c2 + x3.y * c3;
        acc.z += x0.z * c0 + x1.z * c1 + x2.z * c2 + x3.z * c3;
        acc.w += x0.w * c0 + x1.w * c1 + x2.w * c2 + x3.w * c3;
    }
    if (j + 2 <= end) {
        int s0 = __ldg(&csrc[j]);
        int s1 = __ldg(&csrc[j + 1]);
        float c0 = __ldg(&dinv[s0]);
        float c1 = __ldg(&dinv[s1]);
        float4 x0 = *(const float4*)(Xin + (size_t)s0 * FDIM + lane * 4);
        float4 x1 = *(const float4*)(Xin + (size_t)s1 * FDIM + lane * 4);
        acc.x += x0.x * c0 + x1.x * c1;
        acc.y += x0.y * c0 + x1.y * c1;
        acc.z += x0.z * c0 + x1.z * c1;
        acc.w += x0.w * c0 + x1.w * c1;
        j += 2;
    }
    if (j < end) {
        int s = __ldg(&csrc[j]);
        float c = __ldg(&dinv[s]);
        float4 x = *(const float4*)(Xin + (size_t)s * FDIM + lane * 4);
        acc.x += x.x * c;
        acc.y += x.y * c;
        acc.z += x.z * c;
        acc.w += x.w * c;
    }
    float dv = __ldg(&dinv[v]);
    float4 r = make_float4(acc.x * dv, acc.y * dv, acc.z * dv, acc.w * dv);
    *(float4*)(Xout + (size_t)v * FDIM + lane * 4) = r;
}

// ============== tf32 mma.sync GEMM: C[256-tile, NT] = [A0|A1|A2] @ W[NT,K]^T + epilogue ==============
#define EPI_BIAS     0
#define EPI_RELU_BN  1
#define EPI_RELU_RES 2
#define EPI_RELU     3

__device__ __forceinline__ void mma8(float c[4], const uint32_t a[4], uint32_t b0, uint32_t b1) {
    asm volatile(
        "mma.sync.aligned.m16n8k8.row.col.f32.tf32.tf32.f32 "
        "{%0,%1,%2,%3}, {%4,%5,%6,%7}, {%8,%9}, {%0,%1,%2,%3};"
        : "+f"(c[0]), "+f"(c[1]), "+f"(c[2]), "+f"(c[3])
        : "r"(a[0]), "r"(a[1]), "r"(a[2]), "r"(a[3]), "r"(b0), "r"(b1));
}

template<int NT, int EPI>
__global__ void __launch_bounds__(256, 1)
k_gemm_tc(const float* __restrict__ A0, const float* __restrict__ A1, const float* __restrict__ A2,
          int M, int K,
          const float* __restrict__ W,
          const float* __restrict__ bias,
          const float* __restrict__ gmm, const float* __restrict__ bet,
          const float* __restrict__ mu,  const float* __restrict__ var,
          const float* __restrict__ res,
          float* __restrict__ C, int ldc) {
    extern __shared__ float sm[];
    float* const AsBase = sm;                     // 2 * 256 * 36
    float* const BsBase = sm + 2 * 256 * 36;      // 2 * NT * 36

    const int tid  = threadIdx.x;
    const int wid  = tid >> 5;
    const int lane = tid & 31;
    const int gID  = lane >> 2;
    const int tig  = lane & 3;
    const int m0   = blockIdx.x * 256;

    const int wm = (wid & 3) * 64;
    const int wn = (wid >> 2) * (NT / 2);
    constexpr int NTILES = NT / 16;
    constexpr int BITER  = NT / 32;

    float c[4][NTILES][4];
    #pragma unroll
    for (int i = 0; i < 4; i++)
        #pragma unroll
        for (int j = 0; j < NTILES; j++)
            #pragma unroll
            for (int q = 0; q < 4; q++) c[i][j][q] = 0.0f;

    const int nch = K >> 5;

    float4 ra[8];
    float4 rb[BITER];

    auto load_regs = [&](int kt) {
        const float* Ap = (kt < 128) ? A0 : ((kt < 256) ? A1 : A2);
        const int kk = kt & 127;
        #pragma unroll
        for (int it = 0; it < 8; it++) {
            int i = tid + it * 256;
            int row = i >> 3, q = i & 7;
            int gm = m0 + row;
            ra[it] = (gm < M) ? *(const float4*)(Ap + (size_t)gm * FDIM + kk + q * 4)
                              : make_float4(0.f, 0.f, 0.f, 0.f);
        }
        #pragma unroll
        for (int it = 0; it < BITER; it++) {
            int i = tid + it * 256;
            int row = i >> 3, q = i & 7;
            rb[it] = *(const float4*)(W + (size_t)row * K + kt + q * 4);
        }
    };
    auto store_tiles = [&](int buf) {
        float* As = AsBase + buf * (256 * 36);
        float* Bs = BsBase + buf * (NT * 36);
        #pragma unroll
        for (int it = 0; it < 8; it++) {
            int i = tid + it * 256;
            int row = i >> 3, q = i & 7;
            uint4 t = make_uint4(f2tf32(ra[it].x), f2tf32(ra[it].y), f2tf32(ra[it].z), f2tf32(ra[it].w));
            *(uint4*)(As + row * 36 + q * 4) = t;
        }
        #pragma unroll
        for (int it = 0; it < BITER; it++) {
            int i = tid + it * 256;
            int row = i >> 3, q = i & 7;
            uint4 t = make_uint4(f2tf32(rb[it].x), f2tf32(rb[it].y), f2tf32(rb[it].z), f2tf32(rb[it].w));
            *(uint4*)(Bs + row * 36 + q * 4) = t;
        }
    };

    load_regs(0);
    store_tiles(0);
    __syncthreads();

    for (int ch = 0; ch < nch; ch++) {
        const int buf = ch & 1;
        const bool more = (ch + 1 < nch);
        if (more) load_regs((ch + 1) << 5);

        const float* As = AsBase + buf * (256 * 36);
        const float* Bs = BsBase + buf * (NT * 36);

        #pragma unroll
        for (int ks = 0; ks < 32; ks += 8) {
            uint32_t a[4][4];
            #pragma unroll
            for (int mt = 0; mt < 4; mt++) {
                const int r = wm + mt * 16 + gID;
                a[mt][0] = __float_as_uint(As[r * 36 + ks + tig]);
                a[mt][1] = __float_as_uint(As[(r + 8) * 36 + ks + tig]);
                a[mt][2] = __float_as_uint(As[r * 36 + ks + tig + 4]);
                a[mt][3] = __float_as_uint(As[(r + 8) * 36 + ks + tig + 4]);
            }
            #pragma unroll
            for (int nt = 0; nt < NTILES; nt++) {
                const int nr = wn + nt * 8 + gID;
                uint32_t b0 = __float_as_uint(Bs[nr * 36 + ks + tig]);
                uint32_t b1 = __float_as_uint(Bs[nr * 36 + ks + tig + 4]);
                #pragma unroll
                for (int mt = 0; mt < 4; mt++)
                    mma8(c[mt][nt], a[mt], b0, b1);
            }
        }
        if (more) store_tiles(buf ^ 1);
        __syncthreads();
    }

    // ---- epilogue ----
    #pragma unroll
    for (int mt = 0; mt < 4; mt++) {
        #pragma unroll
        for (int nt = 0; nt < NTILES; nt++) {
            const int col = wn + nt * 8 + tig * 2;
            #pragma unroll
            for (int half = 0; half < 2; half++) {
                const int m = m0 + wm + mt * 16 + gID + half * 8;
                if (m >= M) continue;
                float v0 = c[mt][nt][half * 2 + 0];
                float v1 = c[mt][nt][half * 2 + 1];
                v0 += __ldg(&bias[col]);
                v1 += __ldg(&bias[col + 1]);
                if (EPI == EPI_RELU_BN) {
                    v0 = fmaxf(v0, 0.0f);
                    v1 = fmaxf(v1, 0.0f);
                    v0 = (v0 - __ldg(&mu[col]))     * rsqrtf(__ldg(&var[col])     + 1e-5f) * __ldg(&gmm[col])     + __ldg(&bet[col]);
                    v1 = (v1 - __ldg(&mu[col + 1])) * rsqrtf(__ldg(&var[col + 1]) + 1e-5f) * __ldg(&gmm[col + 1]) + __ldg(&bet[col + 1]);
                } else if (EPI == EPI_RELU_RES) {
                    float2 rr = *(const float2*)(res + (size_t)m * FDIM + col);
                    v0 = fmaxf(v0, 0.0f) + rr.x;
                    v1 = fmaxf(v1, 0.0f) + rr.y;
                } else if (EPI == EPI_RELU) {
                    v0 = fmaxf(v0, 0.0f);
                    v1 = fmaxf(v1, 0.0f);
                }
                *(float2*)(C + (size_t)m * ldc + col) = make_float2(v0, v1);
            }
        }
    }
}

// ============== fused MLP head: out[M,64] = relu(A@Wm1^T + bm1) @ Wm2^T + bm2 ==============
__global__ void __launch_bounds__(256, 1)
k_gemm_head(const float* __restrict__ A, int M,
            const float* __restrict__ Wm1, const float* __restrict__ bm1,
            const float* __restrict__ Wm2, const float* __restrict__ bm2,
            float* __restrict__ out) {
    extern __shared__ float sm[];
    float* const AsBase = sm;                       // phase1: 2 * 256 * 36
    float* const BsBase = sm + 2 * 256 * 36;        // phase1: 2 * 128 * 36
    float* const Hs     = sm;                       // phase2: 256 * 132 (aliases As/Bs)
    float* const Ws     = sm + 256 * 132;           // phase2: 64 * 132 (disjoint)

    const int tid  = threadIdx.x;
    const int wid  = tid >> 5;
    const int lane = tid & 31;
    const int gID  = lane >> 2;
    const int tig  = lane & 3;
    const int m0   = blockIdx.x * 256;

    const int wm = (wid & 3) * 64;
    const int wn = (wid >> 2) * 64;    // phase1 NT=128

    // ---- stage Wm2 into Ws ----
    #pragma unroll
    for (int it = 0; it < 8; it++) {
        int i = tid + it * 256;
        int row = i >> 5, q = i & 31;
        float4 v = *(const float4*)(Wm2 + (size_t)row * 128 + q * 4);
        uint4 t = make_uint4(f2tf32(v.x), f2tf32(v.y), f2tf32(v.z), f2tf32(v.w));
        *(uint4*)(Ws + row * 132 + q * 4) = t;
    }

    // ================= phase 1: H = relu(A @ Wm1^T + bm1) =================
    float c[4][8][4];
    #pragma unroll
    for (int i = 0; i < 4; i++)
        #pragma unroll
        for (int j = 0; j < 8; j++)
            #pragma unroll
            for (int q = 0; q < 4; q++) c[i][j][q] = 0.0f;

    float4 ra[8];
    float4 rb[4];
    auto load_regs = [&](int kt) {
        #pragma unroll
        for (int it = 0; it < 8; it++) {
            int i = tid + it * 256;
            int row = i >> 3, q = i & 7;
            int gm = m0 + row;
            ra[it] = (gm < M) ? *(const float4*)(A + (size_t)gm * FDIM + kt + q * 4)
                              : make_float4(0.f, 0.f, 0.f, 0.f);
        }
        #pragma unroll
        for (int it = 0; it < 4; it++) {
            int i = tid + it * 256;
            int row = i >> 3, q = i & 7;
            rb[it] = *(const float4*)(Wm1 + (size_t)row * 128 + kt + q * 4);
        }
    };
    auto store_tiles = [&](int buf) {
        float* As = AsBase + buf * (256 * 36);
        float* Bs = BsBase + buf * (128 * 36);
        #pragma unroll
        for (int it = 0; it < 8; it++) {
            int i = tid + it * 256;
            int row = i >> 3, q = i & 7;
            uint4 t = make_uint4(f2tf32(ra[it].x), f2tf32(ra[it].y), f2tf32(ra[it].z), f2tf32(ra[it].w));
            *(uint4*)(As + row * 36 + q * 4) = t;
        }
        #pragma unroll
        for (int it = 0; it < 4; it++) {
            int i = tid + it * 256;
            int row = i >> 3, q = i & 7;
            uint4 t = make_uint4(f2tf32(rb[it].x), f2tf32(rb[it].y), f2tf32(rb[it].z), f2tf32(rb[it].w));
            *(uint4*)(Bs + row * 36 + q * 4) = t;
        }
    };

    load_regs(0);
    store_tiles(0);
    __syncthreads();

    #pragma unroll
    for (int ch = 0; ch < 4; ch++) {
        const int buf = ch & 1;
        const bool more = (ch < 3);
        if (more) load_regs((ch + 1) << 5);

        const float* As = AsBase + buf * (256 * 36);
        const float* Bs = BsBase + buf * (128 * 36);

        #pragma unroll
        for (int ks = 0; ks < 32; ks += 8) {
            uint32_t a[4][4];
            #pragma unroll
            for (int mt = 0; mt < 4; mt++) {
                const int r = wm + mt * 16 + gID;
                a[mt][0] = __float_as_uint(As[r * 36 + ks + tig]);
                a[mt][1] = __float_as_uint(As[(r + 8) * 36 + ks + tig]);
                a[mt][2] = __float_as_uint(As[r * 36 + ks + tig + 4]);
                a[mt][3] = __float_as_uint(As[(r + 8) * 36 + ks + tig + 4]);
            }
            #pragma unroll
            for (int nt = 0; nt < 8; nt++) {
                const int nr = wn + nt * 8 + gID;
                uint32_t b0 = __float_as_uint(Bs[nr * 36 + ks + tig]);
                uint32_t b1 = __float_as_uint(Bs[nr * 36 + ks + tig + 4]);
                #pragma unroll
                for (int mt = 0; mt < 4; mt++)
                    mma8(c[mt][nt], a[mt], b0, b1);
            }
        }
        if (more) store_tiles(buf ^ 1);
        __syncthreads();
    }

    // ---- epilogue 1: relu+bias, write tf32 hidden tile to Hs ----
    #pragma unroll
    for (int mt = 0; mt < 4; mt++) {
        #pragma unroll
        for (int nt = 0; nt < 8; nt++) {
            const int col = wn + nt * 8 + tig * 2;
            #pragma unroll
            for (int half = 0; half < 2; half++) {
                const int ml = wm + mt * 16 + gID + half * 8;
                float v0 = fmaxf(c[mt][nt][half * 2 + 0] + __ldg(&bm1[col]),     0.0f);
                float v1 = fmaxf(c[mt][nt][half * 2 + 1] + __ldg(&bm1[col + 1]), 0.0f);
                Hs[ml * 132 + col]     = __uint_as_float(f2tf32(v0));
                Hs[ml * 132 + col + 1] = __uint_as_float(f2tf32(v1));
            }
        }
    }
    __syncthreads();

    // ================= phase 2: out = H @ Wm2^T + bm2 =================
    const int wn2 = (wid >> 2) * 32;   // NT=64
    float c2[4][4][4];
    #pragma unroll
    for (int i = 0; i < 4; i++)
        #pragma unroll
        for (int j = 0; j < 4; j++)
            #pragma unroll
            for (int q = 0; q < 4; q++) c2[i][j][q] = 0.0f;

    #pragma unroll
    for (int ks = 0; ks < 128; ks += 8) {
        uint32_t a[4][4];
        #pragma unroll
        for (int mt = 0; mt < 4; mt++) {
            const int r = wm + mt * 16 + gID;
            a[mt][0] = __float_as_uint(Hs[r * 132 + ks + tig]);
            a[mt][1] = __float_as_uint(Hs[(r + 8) * 132 + ks + tig]);
            a[mt][2] = __float_as_uint(Hs[r * 132 + ks + tig + 4]);
            a[mt][3] = __float_as_uint(Hs[(r + 8) * 132 + ks + tig + 4]);
        }
        #pragma unroll
        for (int nt = 0; nt < 4; nt++) {
            const int nr = wn2 + nt * 8 + gID;
            uint32_t b0 = __float_as_uint(Ws[nr * 132 + ks + tig]);
            uint32_t b1 = __float_as_uint(Ws[nr * 132 + ks + tig + 4]);
            #pragma unroll
            for (int mt = 0; mt < 4; mt++)
                mma8(c2[mt][nt], a[mt], b0, b1);
        }
    }

    // ---- epilogue 2: bias, write to out ----
    #pragma unroll
    for (int mt = 0; mt < 4; mt++) {
        #pragma unroll
        for (int nt = 0; nt < 4; nt++) {
            const int col = wn2 + nt * 8 + tig * 2;
            #pragma unroll
            for (int half = 0; half < 2; half++) {
                const int m = m0 + wm + mt * 16 + gID + half * 8;
                if (m >= M) continue;
                float v0 = c2[mt][nt][half * 2 + 0] + __ldg(&bm2[col]);
                float v1 = c2[mt][nt][half * 2 + 1] + __ldg(&bm2[col + 1]);
                *(float2*)(out + (size_t)m * 64 + col) = make_float2(v0, v1);
            }
        }
    }
}

// ======================= launch =======================
extern "C" void kernel_launch(void* const* d_in, const int* in_sizes, int n_in,
                              void* d_out, int out_size) {
    const float* feat  = (const float*)d_in[0];
    const int*   esrc  = (const int*)d_in[1];
    const int*   edst  = (const int*)d_in[2];
    const float* W1    = (const float*)d_in[3];
    const float* b1    = (const float*)d_in[4];
    const float* gamma = (const float*)d_in[5];
    const float* beta  = (const float*)d_in[6];
    const float* mean  = (const float*)d_in[7];
    const float* var   = (const float*)d_in[8];
    const float* W3    = (const float*)d_in[9];
    const float* b3    = (const float*)d_in[10];
    const float* Wm1   = (const float*)d_in[11];
    const float* bm1   = (const float*)d_in[12];
    const float* Wm2   = (const float*)d_in[13];
    const float* bm2   = (const float*)d_in[14];

    const int n  = in_sizes[0] / FDIM;
    const int ne = in_sizes[1];

    int *deg, *off, *pos, *blk, *csrc;
    float *dinv, *b0, *bb1, *b2, *b3buf, *w1t, *w3t;
    cudaGetSymbolAddress((void**)&deg,  g_deg);
    cudaGetSymbolAddress((void**)&off,  g_off);
    cudaGetSymbolAddress((void**)&pos,  g_pos);
    cudaGetSymbolAddress((void**)&blk,  g_blk);
    cudaGetSymbolAddress((void**)&csrc, g_csrc);
    cudaGetSymbolAddress((void**)&dinv, g_dinv);
    cudaGetSymbolAddress((void**)&b0,   g_b0);
    cudaGetSymbolAddress((void**)&bb1,  g_b1);
    cudaGetSymbolAddress((void**)&b2,   g_b2);
    cudaGetSymbolAddress((void**)&b3buf, g_b3);
    cudaGetSymbolAddress((void**)&w1t,  g_w1t);
    cudaGetSymbolAddress((void**)&w3t,  g_w3t);

    const int nb    = (n + 511) / 512;
    const int agrid = (n + 7) / 8;
    const int ggrid = (n + 255) / 256;

    const int SMEM_N128 = (2 * 256 * 36 + 2 * 128 * 36) * 4;  // 110592
    const int SMEM_HEAD = (256 * 132 + 64 * 132) * 4;          // 168960
    cudaFuncSetAttribute(k_gemm_tc<128, EPI_RELU_BN>,  cudaFuncAttributeMaxDynamicSharedMemorySize, SMEM_N128);
    cudaFuncSetAttribute(k_gemm_tc<128, EPI_RELU_RES>, cudaFuncAttributeMaxDynamicSharedMemorySize, SMEM_N128);
    cudaFuncSetAttribute(k_gemm_head,                  cudaFuncAttributeMaxDynamicSharedMemorySize, SMEM_HEAD);

    // ---- CSR build + weight transforms (fused; 4 kernels + 1 memset) ----
    cudaMemsetAsync(deg, 0, (size_t)n * sizeof(int));
    k_degi<<<(ne + 255) / 256, 256>>>(edst, ne, deg);
    k_scan1_wt<<<nb + 64, 512>>>(deg, n, nb, off, blk, dinv, W1, w1t, W3, w3t);
    k_scan3b<<<nb, 512>>>(off, pos, blk, nb, n);
    k_bucket<<<(ne + 255) / 256, 256>>>(esrc, edst, ne, pos, csrc);

    // ---- Cheb layer 1: G0 = Ahat(feat), G1 = Ahat(G0) ----
    k_ahat<<<agrid, 256>>>(feat, dinv, off, csrc, bb1, n);
    k_ahat<<<agrid, 256>>>(bb1,  dinv, off, csrc, b2,  n);
    k_gemm_tc<128, EPI_RELU_BN><<<ggrid, 256, SMEM_N128>>>(feat, bb1, b2, n, 384, w1t, b1,
                                                           gamma, beta, mean, var,
                                                           (const float*)nullptr, b0, 128);

    // ---- Cheb layer 2 ----
    k_ahat<<<agrid, 256>>>(b0,  dinv, off, csrc, bb1, n);
    k_ahat<<<agrid, 256>>>(bb1, dinv, off, csrc, b2,  n);
    k_gemm_tc<128, EPI_RELU_RES><<<ggrid, 256, SMEM_N128>>>(b0, bb1, b2, n, 384, w3t, b3,
                                                            (const float*)nullptr, (const float*)nullptr,
                                                            (const float*)nullptr, (const float*)nullptr,
                                                            b0, b3buf, 128);

    // ---- fused MLP head ----
    k_gemm_head<<<ggrid, 256, SMEM_HEAD>>>(b3buf, n, Wm1, bm1, Wm2, bm2, (float*)d_out);
}

// round 15
// speedup vs baseline: 1.5558x; 1.0044x over previous
#include <cuda_runtime.h>
#include <cstdint>
#include <cstddef>

#define NMAX 100000
#define NEMAX 600000
#define FDIM 128

// ---- static device scratch (no allocations allowed) ----
__device__ int   g_deg[NMAX];        // zero-initialized at load; re-zeroed by k_scan3b each run
__device__ int   g_off[NMAX + 1];
__device__ int   g_pos[NMAX];
__device__ int   g_blk[256];
__device__ int   g_csrc[NEMAX];
__device__ float g_dinv[NMAX];
__device__ float g_b0[NMAX * FDIM];   // y (layer1 out / residual)
__device__ float g_b1[NMAX * FDIM];   // G0 / reuse
__device__ float g_b2[NMAX * FDIM];   // G1
__device__ float g_b3[NMAX * FDIM];   // m1
__device__ float g_w1t[128 * 384];
__device__ float g_w3t[128 * 384];

__device__ __forceinline__ uint32_t f2tf32(float x) {
    uint32_t r;
    asm("cvt.rna.tf32.f32 %0, %1;" : "=r"(r) : "f"(x));
    return r;
}

// ======================= CSR build =======================
__global__ void k_degi(const int* __restrict__ dst, int ne, int* __restrict__ deg) {
    int i = blockIdx.x * blockDim.x + threadIdx.x;
    if (i < ne) atomicAdd(&deg[dst[i]], 1);
}

// block-local inclusive scan + dinv  PLUS  weight transform in extra blocks.
__global__ void __launch_bounds__(512)
k_scan1_wt(const int* __restrict__ deg, int n, int nb,
           int* __restrict__ excl, int* __restrict__ blk,
           float* __restrict__ dinv,
           const float* __restrict__ WA, float* __restrict__ WtA,
           const float* __restrict__ WB, float* __restrict__ WtB) {
    if (blockIdx.x >= (unsigned)nb) {
        int i = (blockIdx.x - nb) * 512 + threadIdx.x;   // 0 .. 32767
        const float* W = (i < 128 * 128) ? WA : WB;
        float* Wt      = (i < 128 * 128) ? WtA : WtB;
        i &= (128 * 128 - 1);
        int o = i >> 7, k = i & 127;
        float w0 = W[o * 384 + k];
        float w1 = W[o * 384 + 128 + k];
        float w2 = W[o * 384 + 256 + k];
        Wt[o * 384 + k]       = w0 - w1 + w2;
        Wt[o * 384 + 128 + k] = w1 - 4.0f * w2;
        Wt[o * 384 + 256 + k] = 2.0f * w2;
        return;
    }
    __shared__ int sh[512];
    int tid = threadIdx.x;
    int i = blockIdx.x * 512 + tid;
    int v = (i < n) ? deg[i] : 0;
    if (i < n) dinv[i] = rsqrtf((float)(v > 1 ? v : 1));
    sh[tid] = v;
    __syncthreads();
    #pragma unroll
    for (int ofs = 1; ofs < 512; ofs <<= 1) {
        int t = (tid >= ofs) ? sh[tid - ofs] : 0;
        __syncthreads();
        sh[tid] += t;
        __syncthreads();
    }
    if (i < n) excl[i] = sh[tid] - v;
    if (tid == 511) blk[blockIdx.x] = sh[511];
}

// scan3 with block-total scan fused; ALSO re-zeroes deg for the next graph replay
// (deg was consumed by k_scan1_wt; __device__ globals start zeroed at load).
__global__ void __launch_bounds__(512)
k_scan3b(int* __restrict__ off, int* __restrict__ pos,
         const int* __restrict__ blk, int nb, int n,
         int* __restrict__ deg) {
    __shared__ int sh[256];
    __shared__ int sh_ex[256];
    int tid = threadIdx.x;
    if (tid < 256) {
        int v = (tid < nb) ? blk[tid] : 0;
        sh[tid] = v;
        sh_ex[tid] = v;
    }
    __syncthreads();
    #pragma unroll
    for (int ofs = 1; ofs < 256; ofs <<= 1) {
        int t = 0;
        if (tid < 256 && tid >= ofs) t = sh[tid - ofs];
        __syncthreads();
        if (tid < 256) sh[tid] += t;
        __syncthreads();
    }
    if (tid < 256) sh_ex[tid] = sh[tid] - sh_ex[tid];
    __syncthreads();

    int i = blockIdx.x * 512 + tid;
    if (i < n) {
        int o = off[i] + sh_ex[blockIdx.x];
        off[i] = o;
        pos[i] = o;
        deg[i] = 0;                       // reset for next replay
    }
    if (blockIdx.x == 0 && tid == 0) off[n] = sh[255];
}

// 2 edges per thread, loads front-batched (MLP=2 on the atomic chain)
__global__ void k_bucket(const int* __restrict__ src, const int* __restrict__ dst, int ne,
                         int* __restrict__ pos, int* __restrict__ csrc) {
    int e = (blockIdx.x * blockDim.x + threadIdx.x) * 2;
    if (e + 1 < ne) {
        int d0 = dst[e],     d1 = dst[e + 1];
        int s0 = src[e],     s1 = src[e + 1];
        int p0 = atomicAdd(&pos[d0], 1);
        int p1 = atomicAdd(&pos[d1], 1);
        csrc[p0] = s0;
        csrc[p1] = s1;
    } else if (e < ne) {
        int p = atomicAdd(&pos[dst[e]], 1);
        csrc[p] = src[e];
    }
}

// ======================= pure A_hat application =======================
// Xout[v] = (sum_{s in N(v)} Xin[s]*dinv[s]) * dinv[v]   — warp per node, 4-way unrolled
__global__ void __launch_bounds__(256)
k_ahat(const float* __restrict__ Xin,
       const float* __restrict__ dinv,
       const int* __restrict__ off, const int* __restrict__ csrc,
       float* __restrict__ Xout, int n) {
    int v = blockIdx.x * 8 + (threadIdx.x >> 5);
    if (v >= n) return;
    int lane = threadIdx.x & 31;
    int beg = __ldg(&off[v]);
    int end = __ldg(&off[v + 1]);

    float4 acc = make_float4(0.f, 0.f, 0.f, 0.f);
    int j = beg;
    for (; j + 4 <= end; j += 4) {
        int s0 = __ldg(&csrc[j]);
        int s1 = __ldg(&csrc[j + 1]);
        int s2 = __ldg(&csrc[j + 2]);
        int s3 = __ldg(&csrc[j + 3]);
        float c0 = __ldg(&dinv[s0]);
        float c1 = __ldg(&dinv[s1]);
        float c2 = __ldg(&dinv[s2]);
        float c3 = __ldg(&dinv[s3]);
        float4 x0 = *(const float4*)(Xin + (size_t)s0 * FDIM + lane * 4);
        float4 x1 = *(const float4*)(Xin + (size_t)s1 * FDIM + lane * 4);
        float4 x2 = *(const float4*)(Xin + (size_t)s2 * FDIM + lane * 4);
        float4 x3 = *(const float4*)(Xin + (size_t)s3 * FDIM + lane * 4);
        acc.x += x0.x * c0 + x1.x * c1 + x2.x * c2 + x3.x * c3;
        acc.y += x0.y * c0 + x1.y * c1 + x2.y * c2 + x3.y * c3;
        acc.z += x0.z * c0 + x1.z * c1 + x2.z * c2 + x3.z * c3;
        acc.w += x0.w * c0 + x1.w * c1 + x2.w * c2 + x3.w * c3;
    }
    if (j + 2 <= end) {
        int s0 = __ldg(&csrc[j]);
        int s1 = __ldg(&csrc[j + 1]);
        float c0 = __ldg(&dinv[s0]);
        float c1 = __ldg(&dinv[s1]);
        float4 x0 = *(const float4*)(Xin + (size_t)s0 * FDIM + lane * 4);
        float4 x1 = *(const float4*)(Xin + (size_t)s1 * FDIM + lane * 4);
        acc.x += x0.x * c0 + x1.x * c1;
        acc.y += x0.y * c0 + x1.y * c1;
        acc.z += x0.z * c0 + x1.z * c1;
        acc.w += x0.w * c0 + x1.w * c1;
        j += 2;
    }
    if (j < end) {
        int s = __ldg(&csrc[j]);
        float c = __ldg(&dinv[s]);
        float4 x = *(const float4*)(Xin + (size_t)s * FDIM + lane * 4);
        acc.x += x.x * c;
        acc.y += x.y * c;
        acc.z += x.z * c;
        acc.w += x.w * c;
    }
    float dv = __ldg(&dinv[v]);
    float4 r = make_float4(acc.x * dv, acc.y * dv, acc.z * dv, acc.w * dv);
    *(float4*)(Xout + (size_t)v * FDIM + lane * 4) = r;
}

// ============== tf32 mma.sync GEMM: C[256-tile, NT] = [A0|A1|A2] @ W[NT,K]^T + epilogue ==============
#define EPI_BIAS     0
#define EPI_RELU_BN  1
#define EPI_RELU_RES 2
#define EPI_RELU     3

__device__ __forceinline__ void mma8(float c[4], const uint32_t a[4], uint32_t b0, uint32_t b1) {
    asm volatile(
        "mma.sync.aligned.m16n8k8.row.col.f32.tf32.tf32.f32 "
        "{%0,%1,%2,%3}, {%4,%5,%6,%7}, {%8,%9}, {%0,%1,%2,%3};"
        : "+f"(c[0]), "+f"(c[1]), "+f"(c[2]), "+f"(c[3])
        : "r"(a[0]), "r"(a[1]), "r"(a[2]), "r"(a[3]), "r"(b0), "r"(b1));
}

template<int NT, int EPI>
__global__ void __launch_bounds__(256, 1)
k_gemm_tc(const float* __restrict__ A0, const float* __restrict__ A1, const float* __restrict__ A2,
          int M, int K,
          const float* __restrict__ W,
          const float* __restrict__ bias,
          const float* __restrict__ gmm, const float* __restrict__ bet,
          const float* __restrict__ mu,  const float* __restrict__ var,
          const float* __restrict__ res,
          float* __restrict__ C, int ldc) {
    extern __shared__ float sm[];
    float* const AsBase = sm;                     // 2 * 256 * 36
    float* const BsBase = sm + 2 * 256 * 36;      // 2 * NT * 36

    const int tid  = threadIdx.x;
    const int wid  = tid >> 5;
    const int lane = tid & 31;
    const int gID  = lane >> 2;
    const int tig  = lane & 3;
    const int m0   = blockIdx.x * 256;

    const int wm = (wid & 3) * 64;
    const int wn = (wid >> 2) * (NT / 2);
    constexpr int NTILES = NT / 16;
    constexpr int BITER  = NT / 32;

    float c[4][NTILES][4];
    #pragma unroll
    for (int i = 0; i < 4; i++)
        #pragma unroll
        for (int j = 0; j < NTILES; j++)
            #pragma unroll
            for (int q = 0; q < 4; q++) c[i][j][q] = 0.0f;

    const int nch = K >> 5;

    float4 ra[8];
    float4 rb[BITER];

    auto load_regs = [&](int kt) {
        const float* Ap = (kt < 128) ? A0 : ((kt < 256) ? A1 : A2);
        const int kk = kt & 127;
        #pragma unroll
        for (int it = 0; it < 8; it++) {
            int i = tid + it * 256;
            int row = i >> 3, q = i & 7;
            int gm = m0 + row;
            ra[it] = (gm < M) ? *(const float4*)(Ap + (size_t)gm * FDIM + kk + q * 4)
                              : make_float4(0.f, 0.f, 0.f, 0.f);
        }
        #pragma unroll
        for (int it = 0; it < BITER; it++) {
            int i = tid + it * 256;
            int row = i >> 3, q = i & 7;
            rb[it] = *(const float4*)(W + (size_t)row * K + kt + q * 4);
        }
    };
    auto store_tiles = [&](int buf) {
        float* As = AsBase + buf * (256 * 36);
        float* Bs = BsBase + buf * (NT * 36);
        #pragma unroll
        for (int it = 0; it < 8; it++) {
            int i = tid + it * 256;
            int row = i >> 3, q = i & 7;
            uint4 t = make_uint4(f2tf32(ra[it].x), f2tf32(ra[it].y), f2tf32(ra[it].z), f2tf32(ra[it].w));
            *(uint4*)(As + row * 36 + q * 4) = t;
        }
        #pragma unroll
        for (int it = 0; it < BITER; it++) {
            int i = tid + it * 256;
            int row = i >> 3, q = i & 7;
            uint4 t = make_uint4(f2tf32(rb[it].x), f2tf32(rb[it].y), f2tf32(rb[it].z), f2tf32(rb[it].w));
            *(uint4*)(Bs + row * 36 + q * 4) = t;
        }
    };

    load_regs(0);
    store_tiles(0);
    __syncthreads();

    for (int ch = 0; ch < nch; ch++) {
        const int buf = ch & 1;
        const bool more = (ch + 1 < nch);
        if (more) load_regs((ch + 1) << 5);

        const float* As = AsBase + buf * (256 * 36);
        const float* Bs = BsBase + buf * (NT * 36);

        #pragma unroll
        for (int ks = 0; ks < 32; ks += 8) {
            uint32_t a[4][4];
            #pragma unroll
            for (int mt = 0; mt < 4; mt++) {
                const int r = wm + mt * 16 + gID;
                a[mt][0] = __float_as_uint(As[r * 36 + ks + tig]);
                a[mt][1] = __float_as_uint(As[(r + 8) * 36 + ks + tig]);
                a[mt][2] = __float_as_uint(As[r * 36 + ks + tig + 4]);
                a[mt][3] = __float_as_uint(As[(r + 8) * 36 + ks + tig + 4]);
            }
            #pragma unroll
            for (int nt = 0; nt < NTILES; nt++) {
                const int nr = wn + nt * 8 + gID;
                uint32_t b0 = __float_as_uint(Bs[nr * 36 + ks + tig]);
                uint32_t b1 = __float_as_uint(Bs[nr * 36 + ks + tig + 4]);
                #pragma unroll
                for (int mt = 0; mt < 4; mt++)
                    mma8(c[mt][nt], a[mt], b0, b1);
            }
        }
        if (more) store_tiles(buf ^ 1);
        __syncthreads();
    }

    // ---- epilogue ----
    #pragma unroll
    for (int mt = 0; mt < 4; mt++) {
        #pragma unroll
        for (int nt = 0; nt < NTILES; nt++) {
            const int col = wn + nt * 8 + tig * 2;
            #pragma unroll
            for (int half = 0; half < 2; half++) {
                const int m = m0 + wm + mt * 16 + gID + half * 8;
                if (m >= M) continue;
                float v0 = c[mt][nt][half * 2 + 0];
                float v1 = c[mt][nt][half * 2 + 1];
                v0 += __ldg(&bias[col]);
                v1 += __ldg(&bias[col + 1]);
                if (EPI == EPI_RELU_BN) {
                    v0 = fmaxf(v0, 0.0f);
                    v1 = fmaxf(v1, 0.0f);
                    v0 = (v0 - __ldg(&mu[col]))     * rsqrtf(__ldg(&var[col])     + 1e-5f) * __ldg(&gmm[col])     + __ldg(&bet[col]);
                    v1 = (v1 - __ldg(&mu[col + 1])) * rsqrtf(__ldg(&var[col + 1]) + 1e-5f) * __ldg(&gmm[col + 1]) + __ldg(&bet[col + 1]);
                } else if (EPI == EPI_RELU_RES) {
                    float2 rr = *(const float2*)(res + (size_t)m * FDIM + col);
                    v0 = fmaxf(v0, 0.0f) + rr.x;
                    v1 = fmaxf(v1, 0.0f) + rr.y;
                } else if (EPI == EPI_RELU) {
                    v0 = fmaxf(v0, 0.0f);
                    v1 = fmaxf(v1, 0.0f);
                }
                *(float2*)(C + (size_t)m * ldc + col) = make_float2(v0, v1);
            }
        }
    }
}

// ============== fused MLP head: out[M,64] = relu(A@Wm1^T + bm1) @ Wm2^T + bm2 ==============
__global__ void __launch_bounds__(256, 1)
k_gemm_head(const float* __restrict__ A, int M,
            const float* __restrict__ Wm1, const float* __restrict__ bm1,
            const float* __restrict__ Wm2, const float* __restrict__ bm2,
            float* __restrict__ out) {
    extern __shared__ float sm[];
    float* const AsBase = sm;                       // phase1: 2 * 256 * 36
    float* const BsBase = sm + 2 * 256 * 36;        // phase1: 2 * 128 * 36
    float* const Hs     = sm;                       // phase2: 256 * 132 (aliases As/Bs)
    float* const Ws     = sm + 256 * 132;           // phase2: 64 * 132 (disjoint)

    const int tid  = threadIdx.x;
    const int wid  = tid >> 5;
    const int lane = tid & 31;
    const int gID  = lane >> 2;
    const int tig  = lane & 3;
    const int m0   = blockIdx.x * 256;

    const int wm = (wid & 3) * 64;
    const int wn = (wid >> 2) * 64;    // phase1 NT=128

    // ---- stage Wm2 into Ws ----
    #pragma unroll
    for (int it = 0; it < 8; it++) {
        int i = tid + it * 256;
        int row = i >> 5, q = i & 31;
        float4 v = *(const float4*)(Wm2 + (size_t)row * 128 + q * 4);
        uint4 t = make_uint4(f2tf32(v.x), f2tf32(v.y), f2tf32(v.z), f2tf32(v.w));
        *(uint4*)(Ws + row * 132 + q * 4) = t;
    }

    // ================= phase 1: H = relu(A @ Wm1^T + bm1) =================
    float c[4][8][4];
    #pragma unroll
    for (int i = 0; i < 4; i++)
        #pragma unroll
        for (int j = 0; j < 8; j++)
            #pragma unroll
            for (int q = 0; q < 4; q++) c[i][j][q] = 0.0f;

    float4 ra[8];
    float4 rb[4];
    auto load_regs = [&](int kt) {
        #pragma unroll
        for (int it = 0; it < 8; it++) {
            int i = tid + it * 256;
            int row = i >> 3, q = i & 7;
            int gm = m0 + row;
            ra[it] = (gm < M) ? *(const float4*)(A + (size_t)gm * FDIM + kt + q * 4)
                              : make_float4(0.f, 0.f, 0.f, 0.f);
        }
        #pragma unroll
        for (int it = 0; it < 4; it++) {
            int i = tid + it * 256;
            int row = i >> 3, q = i & 7;
            rb[it] = *(const float4*)(Wm1 + (size_t)row * 128 + kt + q * 4);
        }
    };
    auto store_tiles = [&](int buf) {
        float* As = AsBase + buf * (256 * 36);
        float* Bs = BsBase + buf * (128 * 36);
        #pragma unroll
        for (int it = 0; it < 8; it++) {
            int i = tid + it * 256;
            int row = i >> 3, q = i & 7;
            uint4 t = make_uint4(f2tf32(ra[it].x), f2tf32(ra[it].y), f2tf32(ra[it].z), f2tf32(ra[it].w));
            *(uint4*)(As + row * 36 + q * 4) = t;
        }
        #pragma unroll
        for (int it = 0; it < 4; it++) {
            int i = tid + it * 256;
            int row = i >> 3, q = i & 7;
            uint4 t = make_uint4(f2tf32(rb[it].x), f2tf32(rb[it].y), f2tf32(rb[it].z), f2tf32(rb[it].w));
            *(uint4*)(Bs + row * 36 + q * 4) = t;
        }
    };

    load_regs(0);
    store_tiles(0);
    __syncthreads();

    #pragma unroll
    for (int ch = 0; ch < 4; ch++) {
        const int buf = ch & 1;
        const bool more = (ch < 3);
        if (more) load_regs((ch + 1) << 5);

        const float* As = AsBase + buf * (256 * 36);
        const float* Bs = BsBase + buf * (128 * 36);

        #pragma unroll
        for (int ks = 0; ks < 32; ks += 8) {
            uint32_t a[4][4];
            #pragma unroll
            for (int mt = 0; mt < 4; mt++) {
                const int r = wm + mt * 16 + gID;
                a[mt][0] = __float_as_uint(As[r * 36 + ks + tig]);
                a[mt][1] = __float_as_uint(As[(r + 8) * 36 + ks + tig]);
                a[mt][2] = __float_as_uint(As[r * 36 + ks + tig + 4]);
                a[mt][3] = __float_as_uint(As[(r + 8) * 36 + ks + tig + 4]);
            }
            #pragma unroll
            for (int nt = 0; nt < 8; nt++) {
                const int nr = wn + nt * 8 + gID;
                uint32_t b0 = __float_as_uint(Bs[nr * 36 + ks + tig]);
                uint32_t b1 = __float_as_uint(Bs[nr * 36 + ks + tig + 4]);
                #pragma unroll
                for (int mt = 0; mt < 4; mt++)
                    mma8(c[mt][nt], a[mt], b0, b1);
            }
        }
        if (more) store_tiles(buf ^ 1);
        __syncthreads();
    }

    // ---- epilogue 1: relu+bias, write tf32 hidden tile to Hs ----
    #pragma unroll
    for (int mt = 0; mt < 4; mt++) {
        #pragma unroll
        for (int nt = 0; nt < 8; nt++) {
            const int col = wn + nt * 8 + tig * 2;
            #pragma unroll
            for (int half = 0; half < 2; half++) {
                const int ml = wm + mt * 16 + gID + half * 8;
                float v0 = fmaxf(c[mt][nt][half * 2 + 0] + __ldg(&bm1[col]),     0.0f);
                float v1 = fmaxf(c[mt][nt][half * 2 + 1] + __ldg(&bm1[col + 1]), 0.0f);
                Hs[ml * 132 + col]     = __uint_as_float(f2tf32(v0));
                Hs[ml * 132 + col + 1] = __uint_as_float(f2tf32(v1));
            }
        }
    }
    __syncthreads();

    // ================= phase 2: out = H @ Wm2^T + bm2 =================
    const int wn2 = (wid >> 2) * 32;   // NT=64
    float c2[4][4][4];
    #pragma unroll
    for (int i = 0; i < 4; i++)
        #pragma unroll
        for (int j = 0; j < 4; j++)
            #pragma unroll
            for (int q = 0; q < 4; q++) c2[i][j][q] = 0.0f;

    #pragma unroll
    for (int ks = 0; ks < 128; ks += 8) {
        uint32_t a[4][4];
        #pragma unroll
        for (int mt = 0; mt < 4; mt++) {
            const int r = wm + mt * 16 + gID;
            a[mt][0] = __float_as_uint(Hs[r * 132 + ks + tig]);
            a[mt][1] = __float_as_uint(Hs[(r + 8) * 132 + ks + tig]);
            a[mt][2] = __float_as_uint(Hs[r * 132 + ks + tig + 4]);
            a[mt][3] = __float_as_uint(Hs[(r + 8) * 132 + ks + tig + 4]);
        }
        #pragma unroll
        for (int nt = 0; nt < 4; nt++) {
            const int nr = wn2 + nt * 8 + gID;
            uint32_t b0 = __float_as_uint(Ws[nr * 132 + ks + tig]);
            uint32_t b1 = __float_as_uint(Ws[nr * 132 + ks + tig + 4]);
            #pragma unroll
            for (int mt = 0; mt < 4; mt++)
                mma8(c2[mt][nt], a[mt], b0, b1);
        }
    }

    // ---- epilogue 2: bias, write to out ----
    #pragma unroll
    for (int mt = 0; mt < 4; mt++) {
        #pragma unroll
        for (int nt = 0; nt < 4; nt++) {
            const int col = wn2 + nt * 8 + tig * 2;
            #pragma unroll
            for (int half = 0; half < 2; half++) {
                const int m = m0 + wm + mt * 16 + gID + half * 8;
                if (m >= M) continue;
                float v0 = c2[mt][nt][half * 2 + 0] + __ldg(&bm2[col]);
                float v1 = c2[mt][nt][half * 2 + 1] + __ldg(&bm2[col + 1]);
                *(float2*)(out + (size_t)m * 64 + col) = make_float2(v0, v1);
            }
        }
    }
}

// ======================= launch =======================
extern "C" void kernel_launch(void* const* d_in, const int* in_sizes, int n_in,
                              void* d_out, int out_size) {
    const float* feat  = (const float*)d_in[0];
    const int*   esrc  = (const int*)d_in[1];
    const int*   edst  = (const int*)d_in[2];
    const float* W1    = (const float*)d_in[3];
    const float* b1    = (const float*)d_in[4];
    const float* gamma = (const float*)d_in[5];
    const float* beta  = (const float*)d_in[6];
    const float* mean  = (const float*)d_in[7];
    const float* var   = (const float*)d_in[8];
    const float* W3    = (const float*)d_in[9];
    const float* b3    = (const float*)d_in[10];
    const float* Wm1   = (const float*)d_in[11];
    const float* bm1   = (const float*)d_in[12];
    const float* Wm2   = (const float*)d_in[13];
    const float* bm2   = (const float*)d_in[14];

    const int n  = in_sizes[0] / FDIM;
    const int ne = in_sizes[1];

    int *deg, *off, *pos, *blk, *csrc;
    float *dinv, *b0, *bb1, *b2, *b3buf, *w1t, *w3t;
    cudaGetSymbolAddress((void**)&deg,  g_deg);
    cudaGetSymbolAddress((void**)&off,  g_off);
    cudaGetSymbolAddress((void**)&pos,  g_pos);
    cudaGetSymbolAddress((void**)&blk,  g_blk);
    cudaGetSymbolAddress((void**)&csrc, g_csrc);
    cudaGetSymbolAddress((void**)&dinv, g_dinv);
    cudaGetSymbolAddress((void**)&b0,   g_b0);
    cudaGetSymbolAddress((void**)&bb1,  g_b1);
    cudaGetSymbolAddress((void**)&b2,   g_b2);
    cudaGetSymbolAddress((void**)&b3buf, g_b3);
    cudaGetSymbolAddress((void**)&w1t,  g_w1t);
    cudaGetSymbolAddress((void**)&w3t,  g_w3t);

    const int nb    = (n + 511) / 512;
    const int agrid = (n + 7) / 8;
    const int ggrid = (n + 255) / 256;

    const int SMEM_N128 = (2 * 256 * 36 + 2 * 128 * 36) * 4;  // 110592
    const int SMEM_HEAD = (256 * 132 + 64 * 132) * 4;          // 168960
    cudaFuncSetAttribute(k_gemm_tc<128, EPI_RELU_BN>,  cudaFuncAttributeMaxDynamicSharedMemorySize, SMEM_N128);
    cudaFuncSetAttribute(k_gemm_tc<128, EPI_RELU_RES>, cudaFuncAttributeMaxDynamicSharedMemorySize, SMEM_N128);
    cudaFuncSetAttribute(k_gemm_head,                  cudaFuncAttributeMaxDynamicSharedMemorySize, SMEM_HEAD);

    // ---- CSR build + weight transforms (no memset: deg zeroed by prior k_scan3b / load init) ----
    k_degi<<<(ne + 255) / 256, 256>>>(edst, ne, deg);
    k_scan1_wt<<<nb + 64, 512>>>(deg, n, nb, off, blk, dinv, W1, w1t, W3, w3t);
    k_scan3b<<<nb, 512>>>(off, pos, blk, nb, n, deg);
    k_bucket<<<(ne / 2 + 255) / 256, 256>>>(esrc, edst, ne, pos, csrc);

    // ---- Cheb layer 1: G0 = Ahat(feat), G1 = Ahat(G0) ----
    k_ahat<<<agrid, 256>>>(feat, dinv, off, csrc, bb1, n);
    k_ahat<<<agrid, 256>>>(bb1,  dinv, off, csrc, b2,  n);
    k_gemm_tc<128, EPI_RELU_BN><<<ggrid, 256, SMEM_N128>>>(feat, bb1, b2, n, 384, w1t, b1,
                                                           gamma, beta, mean, var,
                                                           (const float*)nullptr, b0, 128);

    // ---- Cheb layer 2 ----
    k_ahat<<<agrid, 256>>>(b0,  dinv, off, csrc, bb1, n);
    k_ahat<<<agrid, 256>>>(bb1, dinv, off, csrc, b2,  n);
    k_gemm_tc<128, EPI_RELU_RES><<<ggrid, 256, SMEM_N128>>>(b0, bb1, b2, n, 384, w3t, b3,
                                                            (const float*)nullptr, (const float*)nullptr,
                                                            (const float*)nullptr, (const float*)nullptr,
                                                            b0, b3buf, 128);

    // ---- fused MLP head ----
    k_gemm_head<<<ggrid, 256, SMEM_HEAD>>>(b3buf, n, Wm1, bm1, Wm2, bm2, (float*)d_out);
}

// round 16
// speedup vs baseline: 1.7996x; 1.1567x over previous
#include <cuda_runtime.h>
#include <cuda_fp16.h>
#include <cstdint>
#include <cstddef>

#define NMAX 100000
#define NEMAX 600000
#define FDIM 128

// ---- static device scratch (no allocations allowed) ----
__device__ int    g_deg[NMAX];        // zero-initialized at load; re-zeroed by k_scan3b each run
__device__ int    g_off[NMAX + 1];
__device__ int    g_pos[NMAX];
__device__ int    g_blk[256];
__device__ int    g_csrc[NEMAX];
__device__ float  g_dinv[NMAX];
__device__ __half g_hb0[NMAX * FDIM];   // y (layer1 out / residual)  fp16
__device__ __half g_hb1[NMAX * FDIM];   // G0 / reuse                 fp16
__device__ __half g_hb2[NMAX * FDIM];   // G1                         fp16
__device__ __half g_hb3[NMAX * FDIM];   // m1                         fp16
__device__ float  g_w1t[128 * 384];
__device__ float  g_w3t[128 * 384];

__device__ __forceinline__ uint32_t f2tf32(float x) {
    uint32_t r;
    asm("cvt.rna.tf32.f32 %0, %1;" : "=r"(r) : "f"(x));
    return r;
}

// ======================= CSR build =======================
__global__ void k_degi(const int* __restrict__ dst, int ne, int* __restrict__ deg) {
    int i = blockIdx.x * blockDim.x + threadIdx.x;
    if (i < ne) atomicAdd(&deg[dst[i]], 1);
}

// block-local inclusive scan + dinv  PLUS  weight transform in extra blocks.
__global__ void __launch_bounds__(512)
k_scan1_wt(const int* __restrict__ deg, int n, int nb,
           int* __restrict__ excl, int* __restrict__ blk,
           float* __restrict__ dinv,
           const float* __restrict__ WA, float* __restrict__ WtA,
           const float* __restrict__ WB, float* __restrict__ WtB) {
    if (blockIdx.x >= (unsigned)nb) {
        int i = (blockIdx.x - nb) * 512 + threadIdx.x;   // 0 .. 32767
        const float* W = (i < 128 * 128) ? WA : WB;
        float* Wt      = (i < 128 * 128) ? WtA : WtB;
        i &= (128 * 128 - 1);
        int o = i >> 7, k = i & 127;
        float w0 = W[o * 384 + k];
        float w1 = W[o * 384 + 128 + k];
        float w2 = W[o * 384 + 256 + k];
        Wt[o * 384 + k]       = w0 - w1 + w2;
        Wt[o * 384 + 128 + k] = w1 - 4.0f * w2;
        Wt[o * 384 + 256 + k] = 2.0f * w2;
        return;
    }
    __shared__ int sh[512];
    int tid = threadIdx.x;
    int i = blockIdx.x * 512 + tid;
    int v = (i < n) ? deg[i] : 0;
    if (i < n) dinv[i] = rsqrtf((float)(v > 1 ? v : 1));
    sh[tid] = v;
    __syncthreads();
    #pragma unroll
    for (int ofs = 1; ofs < 512; ofs <<= 1) {
        int t = (tid >= ofs) ? sh[tid - ofs] : 0;
        __syncthreads();
        sh[tid] += t;
        __syncthreads();
    }
    if (i < n) excl[i] = sh[tid] - v;
    if (tid == 511) blk[blockIdx.x] = sh[511];
}

// scan3 with block-total scan fused; re-zeroes deg for the next graph replay.
__global__ void __launch_bounds__(512)
k_scan3b(int* __restrict__ off, int* __restrict__ pos,
         const int* __restrict__ blk, int nb, int n,
         int* __restrict__ deg) {
    __shared__ int sh[256];
    __shared__ int sh_ex[256];
    int tid = threadIdx.x;
    if (tid < 256) {
        int v = (tid < nb) ? blk[tid] : 0;
        sh[tid] = v;
        sh_ex[tid] = v;
    }
    __syncthreads();
    #pragma unroll
    for (int ofs = 1; ofs < 256; ofs <<= 1) {
        int t = 0;
        if (tid < 256 && tid >= ofs) t = sh[tid - ofs];
        __syncthreads();
        if (tid < 256) sh[tid] += t;
        __syncthreads();
    }
    if (tid < 256) sh_ex[tid] = sh[tid] - sh_ex[tid];
    __syncthreads();

    int i = blockIdx.x * 512 + tid;
    if (i < n) {
        int o = off[i] + sh_ex[blockIdx.x];
        off[i] = o;
        pos[i] = o;
        deg[i] = 0;
    }
    if (blockIdx.x == 0 && tid == 0) off[n] = sh[255];
}

// 1 edge per thread (R15's 2-edge variant regressed per profile)
__global__ void k_bucket(const int* __restrict__ src, const int* __restrict__ dst, int ne,
                         int* __restrict__ pos, int* __restrict__ csrc) {
    int e = blockIdx.x * blockDim.x + threadIdx.x;
    if (e < ne) {
        int p = atomicAdd(&pos[dst[e]], 1);
        csrc[p] = src[e];
    }
}

// ======================= A_hat application =======================
// pass 1: fp32 input (feat), fp16 output
__global__ void __launch_bounds__(256)
k_ahat_f32(const float* __restrict__ Xin,
           const float* __restrict__ dinv,
           const int* __restrict__ off, const int* __restrict__ csrc,
           __half* __restrict__ Xout, int n) {
    int v = blockIdx.x * 8 + (threadIdx.x >> 5);
    if (v >= n) return;
    int lane = threadIdx.x & 31;
    int beg = __ldg(&off[v]);
    int end = __ldg(&off[v + 1]);

    float4 acc = make_float4(0.f, 0.f, 0.f, 0.f);
    int j = beg;
    for (; j + 4 <= end; j += 4) {
        int s0 = __ldg(&csrc[j]);
        int s1 = __ldg(&csrc[j + 1]);
        int s2 = __ldg(&csrc[j + 2]);
        int s3 = __ldg(&csrc[j + 3]);
        float c0 = __ldg(&dinv[s0]);
        float c1 = __ldg(&dinv[s1]);
        float c2 = __ldg(&dinv[s2]);
        float c3 = __ldg(&dinv[s3]);
        float4 x0 = *(const float4*)(Xin + (size_t)s0 * FDIM + lane * 4);
        float4 x1 = *(const float4*)(Xin + (size_t)s1 * FDIM + lane * 4);
        float4 x2 = *(const float4*)(Xin + (size_t)s2 * FDIM + lane * 4);
        float4 x3 = *(const float4*)(Xin + (size_t)s3 * FDIM + lane * 4);
        acc.x += x0.x * c0 + x1.x * c1 + x2.x * c2 + x3.x * c3;
        acc.y += x0.y * c0 + x1.y * c1 + x2.y * c2 + x3.y * c3;
        acc.z += x0.z * c0 + x1.z * c1 + x2.z * c2 + x3.z * c3;
        acc.w += x0.w * c0 + x1.w * c1 + x2.w * c2 + x3.w * c3;
    }
    for (; j < end; j++) {
        int s = __ldg(&csrc[j]);
        float c = __ldg(&dinv[s]);
        float4 x = *(const float4*)(Xin + (size_t)s * FDIM + lane * 4);
        acc.x += x.x * c;
        acc.y += x.y * c;
        acc.z += x.z * c;
        acc.w += x.w * c;
    }
    float dv = __ldg(&dinv[v]);
    union { __half2 h[2]; uint2 u; } cv;
    cv.h[0] = __floats2half2_rn(acc.x * dv, acc.y * dv);
    cv.h[1] = __floats2half2_rn(acc.z * dv, acc.w * dv);
    *(uint2*)(Xout + (size_t)v * FDIM + lane * 4) = cv.u;
}

// passes 2-4: fp16 input, fp16 output (gather traffic halved)
__global__ void __launch_bounds__(256)
k_ahat_f16(const __half* __restrict__ Xin,
           const float* __restrict__ dinv,
           const int* __restrict__ off, const int* __restrict__ csrc,
           __half* __restrict__ Xout, int n) {
    int v = blockIdx.x * 8 + (threadIdx.x >> 5);
    if (v >= n) return;
    int lane = threadIdx.x & 31;
    int beg = __ldg(&off[v]);
    int end = __ldg(&off[v + 1]);

    float4 acc = make_float4(0.f, 0.f, 0.f, 0.f);
    int j = beg;
    for (; j + 4 <= end; j += 4) {
        int s0 = __ldg(&csrc[j]);
        int s1 = __ldg(&csrc[j + 1]);
        int s2 = __ldg(&csrc[j + 2]);
        int s3 = __ldg(&csrc[j + 3]);
        float c0 = __ldg(&dinv[s0]);
        float c1 = __ldg(&dinv[s1]);
        float c2 = __ldg(&dinv[s2]);
        float c3 = __ldg(&dinv[s3]);
        uint2 r0 = *(const uint2*)(Xin + (size_t)s0 * FDIM + lane * 4);
        uint2 r1 = *(const uint2*)(Xin + (size_t)s1 * FDIM + lane * 4);
        uint2 r2 = *(const uint2*)(Xin + (size_t)s2 * FDIM + lane * 4);
        uint2 r3 = *(const uint2*)(Xin + (size_t)s3 * FDIM + lane * 4);
        float2 a0 = __half22float2(*(__half2*)&r0.x), b0 = __half22float2(*(__half2*)&r0.y);
        float2 a1 = __half22float2(*(__half2*)&r1.x), b1 = __half22float2(*(__half2*)&r1.y);
        float2 a2 = __half22float2(*(__half2*)&r2.x), b2 = __half22float2(*(__half2*)&r2.y);
        float2 a3 = __half22float2(*(__half2*)&r3.x), b3 = __half22float2(*(__half2*)&r3.y);
        acc.x += a0.x * c0 + a1.x * c1 + a2.x * c2 + a3.x * c3;
        acc.y += a0.y * c0 + a1.y * c1 + a2.y * c2 + a3.y * c3;
        acc.z += b0.x * c0 + b1.x * c1 + b2.x * c2 + b3.x * c3;
        acc.w += b0.y * c0 + b1.y * c1 + b2.y * c2 + b3.y * c3;
    }
    for (; j < end; j++) {
        int s = __ldg(&csrc[j]);
        float c = __ldg(&dinv[s]);
        uint2 r = *(const uint2*)(Xin + (size_t)s * FDIM + lane * 4);
        float2 a = __half22float2(*(__half2*)&r.x), b = __half22float2(*(__half2*)&r.y);
        acc.x += a.x * c;
        acc.y += a.y * c;
        acc.z += b.x * c;
        acc.w += b.y * c;
    }
    float dv = __ldg(&dinv[v]);
    union { __half2 h[2]; uint2 u; } cv;
    cv.h[0] = __floats2half2_rn(acc.x * dv, acc.y * dv);
    cv.h[1] = __floats2half2_rn(acc.z * dv, acc.w * dv);
    *(uint2*)(Xout + (size_t)v * FDIM + lane * 4) = cv.u;
}

// ============== tf32 mma.sync GEMM: C[256-tile, NT] = [A0|A1|A2] @ W[NT,K]^T + epilogue ==============
// A1/A2 always fp16; A0 fp32 if A0F32 (feat) else fp16. C/res are fp16.
#define EPI_RELU_BN  1
#define EPI_RELU_RES 2

__device__ __forceinline__ void mma8(float c[4], const uint32_t a[4], uint32_t b0, uint32_t b1) {
    asm volatile(
        "mma.sync.aligned.m16n8k8.row.col.f32.tf32.tf32.f32 "
        "{%0,%1,%2,%3}, {%4,%5,%6,%7}, {%8,%9}, {%0,%1,%2,%3};"
        : "+f"(c[0]), "+f"(c[1]), "+f"(c[2]), "+f"(c[3])
        : "r"(a[0]), "r"(a[1]), "r"(a[2]), "r"(a[3]), "r"(b0), "r"(b1));
}

template<int NT, int EPI, bool A0F32>
__global__ void __launch_bounds__(256, 1)
k_gemm_tc(const void* __restrict__ A0, const __half* __restrict__ A1, const __half* __restrict__ A2,
          int M, int K,
          const float* __restrict__ W,
          const float* __restrict__ bias,
          const float* __restrict__ gmm, const float* __restrict__ bet,
          const float* __restrict__ mu,  const float* __restrict__ var,
          const __half* __restrict__ res,
          __half* __restrict__ C) {
    extern __shared__ float sm[];
    float* const AsBase = sm;                     // 2 * 256 * 36
    float* const BsBase = sm + 2 * 256 * 36;      // 2 * NT * 36

    const int tid  = threadIdx.x;
    const int wid  = tid >> 5;
    const int lane = tid & 31;
    const int gID  = lane >> 2;
    const int tig  = lane & 3;
    const int m0   = blockIdx.x * 256;

    const int wm = (wid & 3) * 64;
    const int wn = (wid >> 2) * (NT / 2);
    constexpr int NTILES = NT / 16;
    constexpr int BITER  = NT / 32;

    float c[4][NTILES][4];
    #pragma unroll
    for (int i = 0; i < 4; i++)
        #pragma unroll
        for (int j = 0; j < NTILES; j++)
            #pragma unroll
            for (int q = 0; q < 4; q++) c[i][j][q] = 0.0f;

    const int nch = K >> 5;

    uint4  ra[8];       // fp32 path: 8 x float4; fp16 path: 4 x (8 halves)
    float4 rb[BITER];

    auto load_regs = [&](int kt) {
        const int kk = kt & 127;
        if (A0F32 && kt < 128) {
            const float* Ap = (const float*)A0;
            #pragma unroll
            for (int it = 0; it < 8; it++) {
                int i = tid + it * 256;
                int row = i >> 3, q = i & 7;
                int gm = m0 + row;
                float4 v = (gm < M) ? *(const float4*)(Ap + (size_t)gm * FDIM + kk + q * 4)
                                    : make_float4(0.f, 0.f, 0.f, 0.f);
                ra[it] = *(uint4*)&v;
            }
        } else {
            const __half* Ap = (kt < 128) ? (const __half*)A0 : ((kt < 256) ? A1 : A2);
            #pragma unroll
            for (int it = 0; it < 4; it++) {
                int i = tid + it * 256;
                int row = i >> 2, q = i & 3;     // 4 x 16B (8 halves) per 32-half row
                int gm = m0 + row;
                ra[it] = (gm < M) ? *(const uint4*)(Ap + (size_t)gm * FDIM + kk + q * 8)
                                  : make_uint4(0, 0, 0, 0);
            }
        }
        #pragma unroll
        for (int it = 0; it < BITER; it++) {
            int i = tid + it * 256;
            int row = i >> 3, q = i & 7;
            rb[it] = *(const float4*)(W + (size_t)row * K + kt + q * 4);
        }
    };
    auto store_tiles = [&](int buf, bool a_was_f32) {
        float* As = AsBase + buf * (256 * 36);
        float* Bs = BsBase + buf * (NT * 36);
        if (a_was_f32) {
            #pragma unroll
            for (int it = 0; it < 8; it++) {
                int i = tid + it * 256;
                int row = i >> 3, q = i & 7;
                float4 v = *(float4*)&ra[it];
                uint4 t = make_uint4(f2tf32(v.x), f2tf32(v.y), f2tf32(v.z), f2tf32(v.w));
                *(uint4*)(As + row * 36 + q * 4) = t;
            }
        } else {
            #pragma unroll
            for (int it = 0; it < 4; it++) {
                int i = tid + it * 256;
                int row = i >> 2, q = i & 3;
                const __half2* h = (const __half2*)&ra[it];
                float* dst = As + row * 36 + q * 8;
                uint4 t0, t1;
                float2 f0 = __half22float2(h[0]);
                float2 f1 = __half22float2(h[1]);
                float2 f2 = __half22float2(h[2]);
                float2 f3 = __half22float2(h[3]);
                t0 = make_uint4(__float_as_uint(f0.x), __float_as_uint(f0.y),
                                __float_as_uint(f1.x), __float_as_uint(f1.y));
                t1 = make_uint4(__float_as_uint(f2.x), __float_as_uint(f2.y),
                                __float_as_uint(f3.x), __float_as_uint(f3.y));
                *(uint4*)(dst)     = t0;
                *(uint4*)(dst + 4) = t1;
            }
        }
        #pragma unroll
        for (int it = 0; it < BITER; it++) {
            int i = tid + it * 256;
            int row = i >> 3, q = i & 7;
            uint4 t = make_uint4(f2tf32(rb[it].x), f2tf32(rb[it].y), f2tf32(rb[it].z), f2tf32(rb[it].w));
            *(uint4*)(Bs + row * 36 + q * 4) = t;
        }
    };

    load_regs(0);
    store_tiles(0, A0F32);
    __syncthreads();

    for (int ch = 0; ch < nch; ch++) {
        const int buf = ch & 1;
        const bool more = (ch + 1 < nch);
        const bool next_f32 = A0F32 && (((ch + 1) << 5) < 128);
        if (more) load_regs((ch + 1) << 5);

        const float* As = AsBase + buf * (256 * 36);
        const float* Bs = BsBase + buf * (NT * 36);

        #pragma unroll
        for (int ks = 0; ks < 32; ks += 8) {
            uint32_t a[4][4];
            #pragma unroll
            for (int mt = 0; mt < 4; mt++) {
                const int r = wm + mt * 16 + gID;
                a[mt][0] = __float_as_uint(As[r * 36 + ks + tig]);
                a[mt][1] = __float_as_uint(As[(r + 8) * 36 + ks + tig]);
                a[mt][2] = __float_as_uint(As[r * 36 + ks + tig + 4]);
                a[mt][3] = __float_as_uint(As[(r + 8) * 36 + ks + tig + 4]);
            }
            #pragma unroll
            for (int nt = 0; nt < NTILES; nt++) {
                const int nr = wn + nt * 8 + gID;
                uint32_t b0 = __float_as_uint(Bs[nr * 36 + ks + tig]);
                uint32_t b1 = __float_as_uint(Bs[nr * 36 + ks + tig + 4]);
                #pragma unroll
                for (int mt = 0; mt < 4; mt++)
                    mma8(c[mt][nt], a[mt], b0, b1);
            }
        }
        if (more) store_tiles(buf ^ 1, next_f32);
        __syncthreads();
    }

    // ---- epilogue (fp16 output) ----
    #pragma unroll
    for (int mt = 0; mt < 4; mt++) {
        #pragma unroll
        for (int nt = 0; nt < NTILES; nt++) {
            const int col = wn + nt * 8 + tig * 2;
            #pragma unroll
            for (int half = 0; half < 2; half++) {
                const int m = m0 + wm + mt * 16 + gID + half * 8;
                if (m >= M) continue;
                float v0 = c[mt][nt][half * 2 + 0];
                float v1 = c[mt][nt][half * 2 + 1];
                v0 += __ldg(&bias[col]);
                v1 += __ldg(&bias[col + 1]);
                if (EPI == EPI_RELU_BN) {
                    v0 = fmaxf(v0, 0.0f);
                    v1 = fmaxf(v1, 0.0f);
                    v0 = (v0 - __ldg(&mu[col]))     * rsqrtf(__ldg(&var[col])     + 1e-5f) * __ldg(&gmm[col])     + __ldg(&bet[col]);
                    v1 = (v1 - __ldg(&mu[col + 1])) * rsqrtf(__ldg(&var[col + 1]) + 1e-5f) * __ldg(&gmm[col + 1]) + __ldg(&bet[col + 1]);
                } else if (EPI == EPI_RELU_RES) {
                    float2 rr = __half22float2(*(const __half2*)(res + (size_t)m * FDIM + col));
                    v0 = fmaxf(v0, 0.0f) + rr.x;
                    v1 = fmaxf(v1, 0.0f) + rr.y;
                }
                *(__half2*)(C + (size_t)m * FDIM + col) = __floats2half2_rn(v0, v1);
            }
        }
    }
}

// ============== fused MLP head: out[M,64] = relu(A@Wm1^T + bm1) @ Wm2^T + bm2 ==============
// A is fp16 (hb3); out fp32.
__global__ void __launch_bounds__(256, 1)
k_gemm_head(const __half* __restrict__ A, int M,
            const float* __restrict__ Wm1, const float* __restrict__ bm1,
            const float* __restrict__ Wm2, const float* __restrict__ bm2,
            float* __restrict__ out) {
    extern __shared__ float sm[];
    float* const AsBase = sm;                       // phase1: 2 * 256 * 36
    float* const BsBase = sm + 2 * 256 * 36;        // phase1: 2 * 128 * 36
    float* const Hs     = sm;                       // phase2: 256 * 132 (aliases As/Bs)
    float* const Ws     = sm + 256 * 132;           // phase2: 64 * 132 (disjoint)

    const int tid  = threadIdx.x;
    const int wid  = tid >> 5;
    const int lane = tid & 31;
    const int gID  = lane >> 2;
    const int tig  = lane & 3;
    const int m0   = blockIdx.x * 256;

    const int wm = (wid & 3) * 64;
    const int wn = (wid >> 2) * 64;

    // ---- stage Wm2 into Ws ----
    #pragma unroll
    for (int it = 0; it < 8; it++) {
        int i = tid + it * 256;
        int row = i >> 5, q = i & 31;
        float4 v = *(const float4*)(Wm2 + (size_t)row * 128 + q * 4);
        uint4 t = make_uint4(f2tf32(v.x), f2tf32(v.y), f2tf32(v.z), f2tf32(v.w));
        *(uint4*)(Ws + row * 132 + q * 4) = t;
    }

    // ================= phase 1: H = relu(A @ Wm1^T + bm1) =================
    float c[4][8][4];
    #pragma unroll
    for (int i = 0; i < 4; i++)
        #pragma unroll
        for (int j = 0; j < 8; j++)
            #pragma unroll
            for (int q = 0; q < 4; q++) c[i][j][q] = 0.0f;

    uint4  ra[4];
    float4 rb[4];
    auto load_regs = [&](int kt) {
        #pragma unroll
        for (int it = 0; it < 4; it++) {
            int i = tid + it * 256;
            int row = i >> 2, q = i & 3;
            int gm = m0 + row;
            ra[it] = (gm < M) ? *(const uint4*)(A + (size_t)gm * FDIM + kt + q * 8)
                              : make_uint4(0, 0, 0, 0);
        }
        #pragma unroll
        for (int it = 0; it < 4; it++) {
            int i = tid + it * 256;
            int row = i >> 3, q = i & 7;
            rb[it] = *(const float4*)(Wm1 + (size_t)row * 128 + kt + q * 4);
        }
    };
    auto store_tiles = [&](int buf) {
        float* As = AsBase + buf * (256 * 36);
        float* Bs = BsBase + buf * (128 * 36);
        #pragma unroll
        for (int it = 0; it < 4; it++) {
            int i = tid + it * 256;
            int row = i >> 2, q = i & 3;
            const __half2* h = (const __half2*)&ra[it];
            float* dst = As + row * 36 + q * 8;
            float2 f0 = __half22float2(h[0]);
            float2 f1 = __half22float2(h[1]);
            float2 f2 = __half22float2(h[2]);
            float2 f3 = __half22float2(h[3]);
            *(uint4*)(dst)     = make_uint4(__float_as_uint(f0.x), __float_as_uint(f0.y),
                                            __float_as_uint(f1.x), __float_as_uint(f1.y));
            *(uint4*)(dst + 4) = make_uint4(__float_as_uint(f2.x), __float_as_uint(f2.y),
                                            __float_as_uint(f3.x), __float_as_uint(f3.y));
        }
        #pragma unroll
        for (int it = 0; it < 4; it++) {
            int i = tid + it * 256;
            int row = i >> 3, q = i & 7;
            uint4 t = make_uint4(f2tf32(rb[it].x), f2tf32(rb[it].y), f2tf32(rb[it].z), f2tf32(rb[it].w));
            *(uint4*)(Bs + row * 36 + q * 4) = t;
        }
    };

    load_regs(0);
    store_tiles(0);
    __syncthreads();

    #pragma unroll
    for (int ch = 0; ch < 4; ch++) {
        const int buf = ch & 1;
        const bool more = (ch < 3);
        if (more) load_regs((ch + 1) << 5);

        const float* As = AsBase + buf * (256 * 36);
        const float* Bs = BsBase + buf * (128 * 36);

        #pragma unroll
        for (int ks = 0; ks < 32; ks += 8) {
            uint32_t a[4][4];
            #pragma unroll
            for (int mt = 0; mt < 4; mt++) {
                const int r = wm + mt * 16 + gID;
                a[mt][0] = __float_as_uint(As[r * 36 + ks + tig]);
                a[mt][1] = __float_as_uint(As[(r + 8) * 36 + ks + tig]);
                a[mt][2] = __float_as_uint(As[r * 36 + ks + tig + 4]);
                a[mt][3] = __float_as_uint(As[(r + 8) * 36 + ks + tig + 4]);
            }
            #pragma unroll
            for (int nt = 0; nt < 8; nt++) {
                const int nr = wn + nt * 8 + gID;
                uint32_t b0 = __float_as_uint(Bs[nr * 36 + ks + tig]);
                uint32_t b1 = __float_as_uint(Bs[nr * 36 + ks + tig + 4]);
                #pragma unroll
                for (int mt = 0; mt < 4; mt++)
                    mma8(c[mt][nt], a[mt], b0, b1);
            }
        }
        if (more) store_tiles(buf ^ 1);
        __syncthreads();
    }

    // ---- epilogue 1: relu+bias, write tf32 hidden tile to Hs ----
    #pragma unroll
    for (int mt = 0; mt < 4; mt++) {
        #pragma unroll
        for (int nt = 0; nt < 8; nt++) {
            const int col = wn + nt * 8 + tig * 2;
            #pragma unroll
            for (int half = 0; half < 2; half++) {
                const int ml = wm + mt * 16 + gID + half * 8;
                float v0 = fmaxf(c[mt][nt][half * 2 + 0] + __ldg(&bm1[col]),     0.0f);
                float v1 = fmaxf(c[mt][nt][half * 2 + 1] + __ldg(&bm1[col + 1]), 0.0f);
                Hs[ml * 132 + col]     = __uint_as_float(f2tf32(v0));
                Hs[ml * 132 + col + 1] = __uint_as_float(f2tf32(v1));
            }
        }
    }
    __syncthreads();

    // ================= phase 2: out = H @ Wm2^T + bm2 =================
    const int wn2 = (wid >> 2) * 32;
    float c2[4][4][4];
    #pragma unroll
    for (int i = 0; i < 4; i++)
        #pragma unroll
        for (int j = 0; j < 4; j++)
            #pragma unroll
            for (int q = 0; q < 4; q++) c2[i][j][q] = 0.0f;

    #pragma unroll
    for (int ks = 0; ks < 128; ks += 8) {
        uint32_t a[4][4];
        #pragma unroll
        for (int mt = 0; mt < 4; mt++) {
            const int r = wm + mt * 16 + gID;
            a[mt][0] = __float_as_uint(Hs[r * 132 + ks + tig]);
            a[mt][1] = __float_as_uint(Hs[(r + 8) * 132 + ks + tig]);
            a[mt][2] = __float_as_uint(Hs[r * 132 + ks + tig + 4]);
            a[mt][3] = __float_as_uint(Hs[(r + 8) * 132 + ks + tig + 4]);
        }
        #pragma unroll
        for (int nt = 0; nt < 4; nt++) {
            const int nr = wn2 + nt * 8 + gID;
            uint32_t b0 = __float_as_uint(Ws[nr * 132 + ks + tig]);
            uint32_t b1 = __float_as_uint(Ws[nr * 132 + ks + tig + 4]);
            #pragma unroll
            for (int mt = 0; mt < 4; mt++)
                mma8(c2[mt][nt], a[mt], b0, b1);
        }
    }

    // ---- epilogue 2: bias, write fp32 out ----
    #pragma unroll
    for (int mt = 0; mt < 4; mt++) {
        #pragma unroll
        for (int nt = 0; nt < 4; nt++) {
            const int col = wn2 + nt * 8 + tig * 2;
            #pragma unroll
            for (int half = 0; half < 2; half++) {
                const int m = m0 + wm + mt * 16 + gID + half * 8;
                if (m >= M) continue;
                float v0 = c2[mt][nt][half * 2 + 0] + __ldg(&bm2[col]);
                float v1 = c2[mt][nt][half * 2 + 1] + __ldg(&bm2[col + 1]);
                *(float2*)(out + (size_t)m * 64 + col) = make_float2(v0, v1);
            }
        }
    }
}

// ======================= launch =======================
extern "C" void kernel_launch(void* const* d_in, const int* in_sizes, int n_in,
                              void* d_out, int out_size) {
    const float* feat  = (const float*)d_in[0];
    const int*   esrc  = (const int*)d_in[1];
    const int*   edst  = (const int*)d_in[2];
    const float* W1    = (const float*)d_in[3];
    const float* b1    = (const float*)d_in[4];
    const float* gamma = (const float*)d_in[5];
    const float* beta  = (const float*)d_in[6];
    const float* mean  = (const float*)d_in[7];
    const float* var   = (const float*)d_in[8];
    const float* W3    = (const float*)d_in[9];
    const float* b3    = (const float*)d_in[10];
    const float* Wm1   = (const float*)d_in[11];
    const float* bm1   = (const float*)d_in[12];
    const float* Wm2   = (const float*)d_in[13];
    const float* bm2   = (const float*)d_in[14];

    const int n  = in_sizes[0] / FDIM;
    const int ne = in_sizes[1];

    int *deg, *off, *pos, *blk, *csrc;
    float *dinv, *w1t, *w3t;
    __half *hb0, *hb1, *hb2, *hb3;
    cudaGetSymbolAddress((void**)&deg,  g_deg);
    cudaGetSymbolAddress((void**)&off,  g_off);
    cudaGetSymbolAddress((void**)&pos,  g_pos);
    cudaGetSymbolAddress((void**)&blk,  g_blk);
    cudaGetSymbolAddress((void**)&csrc, g_csrc);
    cudaGetSymbolAddress((void**)&dinv, g_dinv);
    cudaGetSymbolAddress((void**)&hb0,  g_hb0);
    cudaGetSymbolAddress((void**)&hb1,  g_hb1);
    cudaGetSymbolAddress((void**)&hb2,  g_hb2);
    cudaGetSymbolAddress((void**)&hb3,  g_hb3);
    cudaGetSymbolAddress((void**)&w1t,  g_w1t);
    cudaGetSymbolAddress((void**)&w3t,  g_w3t);

    const int nb    = (n + 511) / 512;
    const int agrid = (n + 7) / 8;
    const int ggrid = (n + 255) / 256;

    const int SMEM_N128 = (2 * 256 * 36 + 2 * 128 * 36) * 4;  // 110592
    const int SMEM_HEAD = (256 * 132 + 64 * 132) * 4;          // 168960
    cudaFuncSetAttribute(k_gemm_tc<128, EPI_RELU_BN,  true>,  cudaFuncAttributeMaxDynamicSharedMemorySize, SMEM_N128);
    cudaFuncSetAttribute(k_gemm_tc<128, EPI_RELU_RES, false>, cudaFuncAttributeMaxDynamicSharedMemorySize, SMEM_N128);
    cudaFuncSetAttribute(k_gemm_head,                         cudaFuncAttributeMaxDynamicSharedMemorySize, SMEM_HEAD);

    // ---- CSR build + weight transforms ----
    k_degi<<<(ne + 255) / 256, 256>>>(edst, ne, deg);
    k_scan1_wt<<<nb + 64, 512>>>(deg, n, nb, off, blk, dinv, W1, w1t, W3, w3t);
    k_scan3b<<<nb, 512>>>(off, pos, blk, nb, n, deg);
    k_bucket<<<(ne + 255) / 256, 256>>>(esrc, edst, ne, pos, csrc);

    // ---- Cheb layer 1: G0 = Ahat(feat) [fp16], G1 = Ahat(G0) ----
    k_ahat_f32<<<agrid, 256>>>(feat, dinv, off, csrc, hb1, n);
    k_ahat_f16<<<agrid, 256>>>(hb1,  dinv, off, csrc, hb2, n);
    k_gemm_tc<128, EPI_RELU_BN, true><<<ggrid, 256, SMEM_N128>>>(
        feat, hb1, hb2, n, 384, w1t, b1, gamma, beta, mean, var,
        (const __half*)nullptr, hb0);

    // ---- Cheb layer 2 ----
    k_ahat_f16<<<agrid, 256>>>(hb0, dinv, off, csrc, hb1, n);
    k_ahat_f16<<<agrid, 256>>>(hb1, dinv, off, csrc, hb2, n);
    k_gemm_tc<128, EPI_RELU_RES, false><<<ggrid, 256, SMEM_N128>>>(
        hb0, hb1, hb2, n, 384, w3t, b3,
        (const float*)nullptr, (const float*)nullptr, (const float*)nullptr, (const float*)nullptr,
        hb0, hb3);

    // ---- fused MLP head ----
    k_gemm_head<<<ggrid, 256, SMEM_HEAD>>>(hb3, n, Wm1, bm1, Wm2, bm2, (float*)d_out);
}

// round 17
// speedup vs baseline: 1.8100x; 1.0058x over previous
#include <cuda_runtime.h>
#include <cuda_fp16.h>
#include <cstdint>
#include <cstddef>

#define NMAX 100000
#define NEMAX 600000
#define FDIM 128

// ---- static device scratch (no allocations allowed) ----
__device__ int    g_deg[NMAX];        // zero-initialized at load; re-zeroed by k_scan3b each run
__device__ int    g_off[NMAX + 1];
__device__ int    g_pos[NMAX];
__device__ int    g_blk[256];
__device__ int    g_csrc[NEMAX];
__device__ float  g_dinv[NMAX];
__device__ __half g_hfeat[NMAX * FDIM]; // feat converted to fp16
__device__ __half g_hb0[NMAX * FDIM];   // y (layer1 out / residual)
__device__ __half g_hb1[NMAX * FDIM];   // G0 / reuse
__device__ __half g_hb2[NMAX * FDIM];   // G1
__device__ __half g_hb3[NMAX * FDIM];   // m1
__device__ float  g_w1t[128 * 384];
__device__ float  g_w3t[128 * 384];

__device__ __forceinline__ uint32_t f2tf32(float x) {
    uint32_t r;
    asm("cvt.rna.tf32.f32 %0, %1;" : "=r"(r) : "f"(x));
    return r;
}

// ======================= CSR build =======================
// blocks [0, dblocks): degree atomics.  blocks [dblocks, ...): feat fp32->fp16 (8 elems/thread).
__global__ void k_degi_cvt(const int* __restrict__ dst, int ne, int* __restrict__ deg,
                           int dblocks,
                           const float* __restrict__ feat, __half* __restrict__ hfeat,
                           int nelem) {
    if ((int)blockIdx.x >= dblocks) {
        int i = ((int)blockIdx.x - dblocks) * 256 + threadIdx.x;
        int idx = i * 8;
        if (idx < nelem) {
            float4 a = *(const float4*)(feat + idx);
            float4 b = *(const float4*)(feat + idx + 4);
            union { __half2 h[4]; uint4 u; } cv;
            cv.h[0] = __floats2half2_rn(a.x, a.y);
            cv.h[1] = __floats2half2_rn(a.z, a.w);
            cv.h[2] = __floats2half2_rn(b.x, b.y);
            cv.h[3] = __floats2half2_rn(b.z, b.w);
            *(uint4*)(hfeat + idx) = cv.u;
        }
        return;
    }
    int i = blockIdx.x * blockDim.x + threadIdx.x;
    if (i < ne) atomicAdd(&deg[dst[i]], 1);
}

// block-local inclusive scan + dinv  PLUS  weight transform in extra blocks.
__global__ void __launch_bounds__(512)
k_scan1_wt(const int* __restrict__ deg, int n, int nb,
           int* __restrict__ excl, int* __restrict__ blk,
           float* __restrict__ dinv,
           const float* __restrict__ WA, float* __restrict__ WtA,
           const float* __restrict__ WB, float* __restrict__ WtB) {
    if (blockIdx.x >= (unsigned)nb) {
        int i = (blockIdx.x - nb) * 512 + threadIdx.x;   // 0 .. 32767
        const float* W = (i < 128 * 128) ? WA : WB;
        float* Wt      = (i < 128 * 128) ? WtA : WtB;
        i &= (128 * 128 - 1);
        int o = i >> 7, k = i & 127;
        float w0 = W[o * 384 + k];
        float w1 = W[o * 384 + 128 + k];
        float w2 = W[o * 384 + 256 + k];
        Wt[o * 384 + k]       = w0 - w1 + w2;
        Wt[o * 384 + 128 + k] = w1 - 4.0f * w2;
        Wt[o * 384 + 256 + k] = 2.0f * w2;
        return;
    }
    __shared__ int sh[512];
    int tid = threadIdx.x;
    int i = blockIdx.x * 512 + tid;
    int v = (i < n) ? deg[i] : 0;
    if (i < n) dinv[i] = rsqrtf((float)(v > 1 ? v : 1));
    sh[tid] = v;
    __syncthreads();
    #pragma unroll
    for (int ofs = 1; ofs < 512; ofs <<= 1) {
        int t = (tid >= ofs) ? sh[tid - ofs] : 0;
        __syncthreads();
        sh[tid] += t;
        __syncthreads();
    }
    if (i < n) excl[i] = sh[tid] - v;
    if (tid == 511) blk[blockIdx.x] = sh[511];
}

// scan3 with block-total scan fused; re-zeroes deg for the next graph replay.
__global__ void __launch_bounds__(512)
k_scan3b(int* __restrict__ off, int* __restrict__ pos,
         const int* __restrict__ blk, int nb, int n,
         int* __restrict__ deg) {
    __shared__ int sh[256];
    __shared__ int sh_ex[256];
    int tid = threadIdx.x;
    if (tid < 256) {
        int v = (tid < nb) ? blk[tid] : 0;
        sh[tid] = v;
        sh_ex[tid] = v;
    }
    __syncthreads();
    #pragma unroll
    for (int ofs = 1; ofs < 256; ofs <<= 1) {
        int t = 0;
        if (tid < 256 && tid >= ofs) t = sh[tid - ofs];
        __syncthreads();
        if (tid < 256) sh[tid] += t;
        __syncthreads();
    }
    if (tid < 256) sh_ex[tid] = sh[tid] - sh_ex[tid];
    __syncthreads();

    int i = blockIdx.x * 512 + tid;
    if (i < n) {
        int o = off[i] + sh_ex[blockIdx.x];
        off[i] = o;
        pos[i] = o;
        deg[i] = 0;
    }
    if (blockIdx.x == 0 && tid == 0) off[n] = sh[255];
}

// 1 edge per thread
__global__ void k_bucket(const int* __restrict__ src, const int* __restrict__ dst, int ne,
                         int* __restrict__ pos, int* __restrict__ csrc) {
    int e = blockIdx.x * blockDim.x + threadIdx.x;
    if (e < ne) {
        int p = atomicAdd(&pos[dst[e]], 1);
        csrc[p] = src[e];
    }
}

// ======================= A_hat application (fp16 in/out) =======================
__global__ void __launch_bounds__(256)
k_ahat_f16(const __half* __restrict__ Xin,
           const float* __restrict__ dinv,
           const int* __restrict__ off, const int* __restrict__ csrc,
           __half* __restrict__ Xout, int n) {
    int v = blockIdx.x * 8 + (threadIdx.x >> 5);
    if (v >= n) return;
    int lane = threadIdx.x & 31;
    int beg = __ldg(&off[v]);
    int end = __ldg(&off[v + 1]);

    float4 acc = make_float4(0.f, 0.f, 0.f, 0.f);
    int j = beg;
    for (; j + 4 <= end; j += 4) {
        int s0 = __ldg(&csrc[j]);
        int s1 = __ldg(&csrc[j + 1]);
        int s2 = __ldg(&csrc[j + 2]);
        int s3 = __ldg(&csrc[j + 3]);
        float c0 = __ldg(&dinv[s0]);
        float c1 = __ldg(&dinv[s1]);
        float c2 = __ldg(&dinv[s2]);
        float c3 = __ldg(&dinv[s3]);
        uint2 r0 = *(const uint2*)(Xin + (size_t)s0 * FDIM + lane * 4);
        uint2 r1 = *(const uint2*)(Xin + (size_t)s1 * FDIM + lane * 4);
        uint2 r2 = *(const uint2*)(Xin + (size_t)s2 * FDIM + lane * 4);
        uint2 r3 = *(const uint2*)(Xin + (size_t)s3 * FDIM + lane * 4);
        float2 a0 = __half22float2(*(__half2*)&r0.x), b0 = __half22float2(*(__half2*)&r0.y);
        float2 a1 = __half22float2(*(__half2*)&r1.x), b1 = __half22float2(*(__half2*)&r1.y);
        float2 a2 = __half22float2(*(__half2*)&r2.x), b2 = __half22float2(*(__half2*)&r2.y);
        float2 a3 = __half22float2(*(__half2*)&r3.x), b3 = __half22float2(*(__half2*)&r3.y);
        acc.x += a0.x * c0 + a1.x * c1 + a2.x * c2 + a3.x * c3;
        acc.y += a0.y * c0 + a1.y * c1 + a2.y * c2 + a3.y * c3;
        acc.z += b0.x * c0 + b1.x * c1 + b2.x * c2 + b3.x * c3;
        acc.w += b0.y * c0 + b1.y * c1 + b2.y * c2 + b3.y * c3;
    }
    for (; j < end; j++) {
        int s = __ldg(&csrc[j]);
        float c = __ldg(&dinv[s]);
        uint2 r = *(const uint2*)(Xin + (size_t)s * FDIM + lane * 4);
        float2 a = __half22float2(*(__half2*)&r.x), b = __half22float2(*(__half2*)&r.y);
        acc.x += a.x * c;
        acc.y += a.y * c;
        acc.z += b.x * c;
        acc.w += b.y * c;
    }
    float dv = __ldg(&dinv[v]);
    union { __half2 h[2]; uint2 u; } cv;
    cv.h[0] = __floats2half2_rn(acc.x * dv, acc.y * dv);
    cv.h[1] = __floats2half2_rn(acc.z * dv, acc.w * dv);
    *(uint2*)(Xout + (size_t)v * FDIM + lane * 4) = cv.u;
}

// ============== tf32 mma.sync GEMM: C[256-tile, NT] = [A0|A1|A2] @ W[NT,K]^T + epilogue ==============
// A0/A1/A2 fp16 (128 cols each); C/res fp16.
#define EPI_RELU_BN  1
#define EPI_RELU_RES 2

__device__ __forceinline__ void mma8(float c[4], const uint32_t a[4], uint32_t b0, uint32_t b1) {
    asm volatile(
        "mma.sync.aligned.m16n8k8.row.col.f32.tf32.tf32.f32 "
        "{%0,%1,%2,%3}, {%4,%5,%6,%7}, {%8,%9}, {%0,%1,%2,%3};"
        : "+f"(c[0]), "+f"(c[1]), "+f"(c[2]), "+f"(c[3])
        : "r"(a[0]), "r"(a[1]), "r"(a[2]), "r"(a[3]), "r"(b0), "r"(b1));
}

template<int NT, int EPI>
__global__ void __launch_bounds__(256, 1)
k_gemm_tc(const __half* __restrict__ A0, const __half* __restrict__ A1, const __half* __restrict__ A2,
          int M, int K,
          const float* __restrict__ W,
          const float* __restrict__ bias,
          const float* __restrict__ gmm, const float* __restrict__ bet,
          const float* __restrict__ mu,  const float* __restrict__ var,
          const __half* __restrict__ res,
          __half* __restrict__ C) {
    extern __shared__ float sm[];
    float* const AsBase = sm;                     // 2 * 256 * 36
    float* const BsBase = sm + 2 * 256 * 36;      // 2 * NT * 36

    const int tid  = threadIdx.x;
    const int wid  = tid >> 5;
    const int lane = tid & 31;
    const int gID  = lane >> 2;
    const int tig  = lane & 3;
    const int m0   = blockIdx.x * 256;

    const int wm = (wid & 3) * 64;
    const int wn = (wid >> 2) * (NT / 2);
    constexpr int NTILES = NT / 16;
    constexpr int BITER  = NT / 32;

    float c[4][NTILES][4];
    #pragma unroll
    for (int i = 0; i < 4; i++)
        #pragma unroll
        for (int j = 0; j < NTILES; j++)
            #pragma unroll
            for (int q = 0; q < 4; q++) c[i][j][q] = 0.0f;

    const int nch = K >> 5;

    uint4  ra[4];       // 8 halves per entry
    float4 rb[BITER];

    auto load_regs = [&](int kt) {
        const int kk = kt & 127;
        const __half* Ap = (kt < 128) ? A0 : ((kt < 256) ? A1 : A2);
        #pragma unroll
        for (int it = 0; it < 4; it++) {
            int i = tid + it * 256;
            int row = i >> 2, q = i & 3;     // 4 x 16B (8 halves) per 32-half row
            int gm = m0 + row;
            ra[it] = (gm < M) ? *(const uint4*)(Ap + (size_t)gm * FDIM + kk + q * 8)
                              : make_uint4(0, 0, 0, 0);
        }
        #pragma unroll
        for (int it = 0; it < BITER; it++) {
            int i = tid + it * 256;
            int row = i >> 3, q = i & 7;
            rb[it] = *(const float4*)(W + (size_t)row * K + kt + q * 4);
        }
    };
    auto store_tiles = [&](int buf) {
        float* As = AsBase + buf * (256 * 36);
        float* Bs = BsBase + buf * (NT * 36);
        #pragma unroll
        for (int it = 0; it < 4; it++) {
            int i = tid + it * 256;
            int row = i >> 2, q = i & 3;
            const __half2* h = (const __half2*)&ra[it];
            float* dst = As + row * 36 + q * 8;
            float2 f0 = __half22float2(h[0]);
            float2 f1 = __half22float2(h[1]);
            float2 f2 = __half22float2(h[2]);
            float2 f3 = __half22float2(h[3]);
            *(uint4*)(dst)     = make_uint4(__float_as_uint(f0.x), __float_as_uint(f0.y),
                                            __float_as_uint(f1.x), __float_as_uint(f1.y));
            *(uint4*)(dst + 4) = make_uint4(__float_as_uint(f2.x), __float_as_uint(f2.y),
                                            __float_as_uint(f3.x), __float_as_uint(f3.y));
        }
        #pragma unroll
        for (int it = 0; it < BITER; it++) {
            int i = tid + it * 256;
            int row = i >> 3, q = i & 7;
            uint4 t = make_uint4(f2tf32(rb[it].x), f2tf32(rb[it].y), f2tf32(rb[it].z), f2tf32(rb[it].w));
            *(uint4*)(Bs + row * 36 + q * 4) = t;
        }
    };

    load_regs(0);
    store_tiles(0);
    __syncthreads();

    for (int ch = 0; ch < nch; ch++) {
        const int buf = ch & 1;
        const bool more = (ch + 1 < nch);
        if (more) load_regs((ch + 1) << 5);

        const float* As = AsBase + buf * (256 * 36);
        const float* Bs = BsBase + buf * (NT * 36);

        #pragma unroll
        for (int ks = 0; ks < 32; ks += 8) {
            uint32_t a[4][4];
            #pragma unroll
            for (int mt = 0; mt < 4; mt++) {
                const int r = wm + mt * 16 + gID;
                a[mt][0] = __float_as_uint(As[r * 36 + ks + tig]);
                a[mt][1] = __float_as_uint(As[(r + 8) * 36 + ks + tig]);
                a[mt][2] = __float_as_uint(As[r * 36 + ks + tig + 4]);
                a[mt][3] = __float_as_uint(As[(r + 8) * 36 + ks + tig + 4]);
            }
            #pragma unroll
            for (int nt = 0; nt < NTILES; nt++) {
                const int nr = wn + nt * 8 + gID;
                uint32_t b0 = __float_as_uint(Bs[nr * 36 + ks + tig]);
                uint32_t b1 = __float_as_uint(Bs[nr * 36 + ks + tig + 4]);
                #pragma unroll
                for (int mt = 0; mt < 4; mt++)
                    mma8(c[mt][nt], a[mt], b0, b1);
            }
        }
        if (more) store_tiles(buf ^ 1);
        __syncthreads();
    }

    // ---- epilogue (fp16 output) ----
    #pragma unroll
    for (int mt = 0; mt < 4; mt++) {
        #pragma unroll
        for (int nt = 0; nt < NTILES; nt++) {
            const int col = wn + nt * 8 + tig * 2;
            #pragma unroll
            for (int half = 0; half < 2; half++) {
                const int m = m0 + wm + mt * 16 + gID + half * 8;
                if (m >= M) continue;
                float v0 = c[mt][nt][half * 2 + 0];
                float v1 = c[mt][nt][half * 2 + 1];
                v0 += __ldg(&bias[col]);
                v1 += __ldg(&bias[col + 1]);
                if (EPI == EPI_RELU_BN) {
                    v0 = fmaxf(v0, 0.0f);
                    v1 = fmaxf(v1, 0.0f);
                    v0 = (v0 - __ldg(&mu[col]))     * rsqrtf(__ldg(&var[col])     + 1e-5f) * __ldg(&gmm[col])     + __ldg(&bet[col]);
                    v1 = (v1 - __ldg(&mu[col + 1])) * rsqrtf(__ldg(&var[col + 1]) + 1e-5f) * __ldg(&gmm[col + 1]) + __ldg(&bet[col + 1]);
                } else if (EPI == EPI_RELU_RES) {
                    float2 rr = __half22float2(*(const __half2*)(res + (size_t)m * FDIM + col));
                    v0 = fmaxf(v0, 0.0f) + rr.x;
                    v1 = fmaxf(v1, 0.0f) + rr.y;
                }
                *(__half2*)(C + (size_t)m * FDIM + col) = __floats2half2_rn(v0, v1);
            }
        }
    }
}

// ============== fused MLP head: out[M,64] = relu(A@Wm1^T + bm1) @ Wm2^T + bm2 ==============
__global__ void __launch_bounds__(256, 1)
k_gemm_head(const __half* __restrict__ A, int M,
            const float* __restrict__ Wm1, const float* __restrict__ bm1,
            const float* __restrict__ Wm2, const float* __restrict__ bm2,
            float* __restrict__ out) {
    extern __shared__ float sm[];
    float* const AsBase = sm;                       // phase1: 2 * 256 * 36
    float* const BsBase = sm + 2 * 256 * 36;        // phase1: 2 * 128 * 36
    float* const Hs     = sm;                       // phase2: 256 * 132 (aliases As/Bs)
    float* const Ws     = sm + 256 * 132;           // phase2: 64 * 132 (disjoint)

    const int tid  = threadIdx.x;
    const int wid  = tid >> 5;
    const int lane = tid & 31;
    const int gID  = lane >> 2;
    const int tig  = lane & 3;
    const int m0   = blockIdx.x * 256;

    const int wm = (wid & 3) * 64;
    const int wn = (wid >> 2) * 64;

    // ---- stage Wm2 into Ws ----
    #pragma unroll
    for (int it = 0; it < 8; it++) {
        int i = tid + it * 256;
        int row = i >> 5, q = i & 31;
        float4 v = *(const float4*)(Wm2 + (size_t)row * 128 + q * 4);
        uint4 t = make_uint4(f2tf32(v.x), f2tf32(v.y), f2tf32(v.z), f2tf32(v.w));
        *(uint4*)(Ws + row * 132 + q * 4) = t;
    }

    // ================= phase 1: H = relu(A @ Wm1^T + bm1) =================
    float c[4][8][4];
    #pragma unroll
    for (int i = 0; i < 4; i++)
        #pragma unroll
        for (int j = 0; j < 8; j++)
            #pragma unroll
            for (int q = 0; q < 4; q++) c[i][j][q] = 0.0f;

    uint4  ra[4];
    float4 rb[4];
    auto load_regs = [&](int kt) {
        #pragma unroll
        for (int it = 0; it < 4; it++) {
            int i = tid + it * 256;
            int row = i >> 2, q = i & 3;
            int gm = m0 + row;
            ra[it] = (gm < M) ? *(const uint4*)(A + (size_t)gm * FDIM + kt + q * 8)
                              : make_uint4(0, 0, 0, 0);
        }
        #pragma unroll
        for (int it = 0; it < 4; it++) {
            int i = tid + it * 256;
            int row = i >> 3, q = i & 7;
            rb[it] = *(const float4*)(Wm1 + (size_t)row * 128 + kt + q * 4);
        }
    };
    auto store_tiles = [&](int buf) {
        float* As = AsBase + buf * (256 * 36);
        float* Bs = BsBase + buf * (128 * 36);
        #pragma unroll
        for (int it = 0; it < 4; it++) {
            int i = tid + it * 256;
            int row = i >> 2, q = i & 3;
            const __half2* h = (const __half2*)&ra[it];
            float* dst = As + row * 36 + q * 8;
            float2 f0 = __half22float2(h[0]);
            float2 f1 = __half22float2(h[1]);
            float2 f2 = __half22float2(h[2]);
            float2 f3 = __half22float2(h[3]);
            *(uint4*)(dst)     = make_uint4(__float_as_uint(f0.x), __float_as_uint(f0.y),
                                            __float_as_uint(f1.x), __float_as_uint(f1.y));
            *(uint4*)(dst + 4) = make_uint4(__float_as_uint(f2.x), __float_as_uint(f2.y),
                                            __float_as_uint(f3.x), __float_as_uint(f3.y));
        }
        #pragma unroll
        for (int it = 0; it < 4; it++) {
            int i = tid + it * 256;
            int row = i >> 3, q = i & 7;
            uint4 t = make_uint4(f2tf32(rb[it].x), f2tf32(rb[it].y), f2tf32(rb[it].z), f2tf32(rb[it].w));
            *(uint4*)(Bs + row * 36 + q * 4) = t;
        }
    };

    load_regs(0);
    store_tiles(0);
    __syncthreads();

    #pragma unroll
    for (int ch = 0; ch < 4; ch++) {
        const int buf = ch & 1;
        const bool more = (ch < 3);
        if (more) load_regs((ch + 1) << 5);

        const float* As = AsBase + buf * (256 * 36);
        const float* Bs = BsBase + buf * (128 * 36);

        #pragma unroll
        for (int ks = 0; ks < 32; ks += 8) {
            uint32_t a[4][4];
            #pragma unroll
            for (int mt = 0; mt < 4; mt++) {
                const int r = wm + mt * 16 + gID;
                a[mt][0] = __float_as_uint(As[r * 36 + ks + tig]);
                a[mt][1] = __float_as_uint(As[(r + 8) * 36 + ks + tig]);
                a[mt][2] = __float_as_uint(As[r * 36 + ks + tig + 4]);
                a[mt][3] = __float_as_uint(As[(r + 8) * 36 + ks + tig + 4]);
            }
            #pragma unroll
            for (int nt = 0; nt < 8; nt++) {
                const int nr = wn + nt * 8 + gID;
                uint32_t b0 = __float_as_uint(Bs[nr * 36 + ks + tig]);
                uint32_t b1 = __float_as_uint(Bs[nr * 36 + ks + tig + 4]);
                #pragma unroll
                for (int mt = 0; mt < 4; mt++)
                    mma8(c[mt][nt], a[mt], b0, b1);
            }
        }
        if (more) store_tiles(buf ^ 1);
        __syncthreads();
    }

    // ---- epilogue 1: relu+bias, write tf32 hidden tile to Hs ----
    #pragma unroll
    for (int mt = 0; mt < 4; mt++) {
        #pragma unroll
        for (int nt = 0; nt < 8; nt++) {
            const int col = wn + nt * 8 + tig * 2;
            #pragma unroll
            for (int half = 0; half < 2; half++) {
                const int ml = wm + mt * 16 + gID + half * 8;
                float v0 = fmaxf(c[mt][nt][half * 2 + 0] + __ldg(&bm1[col]),     0.0f);
                float v1 = fmaxf(c[mt][nt][half * 2 + 1] + __ldg(&bm1[col + 1]), 0.0f);
                Hs[ml * 132 + col]     = __uint_as_float(f2tf32(v0));
                Hs[ml * 132 + col + 1] = __uint_as_float(f2tf32(v1));
            }
        }
    }
    __syncthreads();

    // ================= phase 2: out = H @ Wm2^T + bm2 =================
    const int wn2 = (wid >> 2) * 32;
    float c2[4][4][4];
    #pragma unroll
    for (int i = 0; i < 4; i++)
        #pragma unroll
        for (int j = 0; j < 4; j++)
            #pragma unroll
            for (int q = 0; q < 4; q++) c2[i][j][q] = 0.0f;

    #pragma unroll
    for (int ks = 0; ks < 128; ks += 8) {
        uint32_t a[4][4];
        #pragma unroll
        for (int mt = 0; mt < 4; mt++) {
            const int r = wm + mt * 16 + gID;
            a[mt][0] = __float_as_uint(Hs[r * 132 + ks + tig]);
            a[mt][1] = __float_as_uint(Hs[(r + 8) * 132 + ks + tig]);
            a[mt][2] = __float_as_uint(Hs[r * 132 + ks + tig + 4]);
            a[mt][3] = __float_as_uint(Hs[(r + 8) * 132 + ks + tig + 4]);
        }
        #pragma unroll
        for (int nt = 0; nt < 4; nt++) {
            const int nr = wn2 + nt * 8 + gID;
            uint32_t b0 = __float_as_uint(Ws[nr * 132 + ks + tig]);
            uint32_t b1 = __float_as_uint(Ws[nr * 132 + ks + tig + 4]);
            #pragma unroll
            for (int mt = 0; mt < 4; mt++)
                mma8(c2[mt][nt], a[mt], b0, b1);
        }
    }

    // ---- epilogue 2: bias, write fp32 out ----
    #pragma unroll
    for (int mt = 0; mt < 4; mt++) {
        #pragma unroll
        for (int nt = 0; nt < 4; nt++) {
            const int col = wn2 + nt * 8 + tig * 2;
            #pragma unroll
            for (int half = 0; half < 2; half++) {
                const int m = m0 + wm + mt * 16 + gID + half * 8;
                if (m >= M) continue;
                float v0 = c2[mt][nt][half * 2 + 0] + __ldg(&bm2[col]);
                float v1 = c2[mt][nt][half * 2 + 1] + __ldg(&bm2[col + 1]);
                *(float2*)(out + (size_t)m * 64 + col) = make_float2(v0, v1);
            }
        }
    }
}

// ======================= launch =======================
extern "C" void kernel_launch(void* const* d_in, const int* in_sizes, int n_in,
                              void* d_out, int out_size) {
    const float* feat  = (const float*)d_in[0];
    const int*   esrc  = (const int*)d_in[1];
    const int*   edst  = (const int*)d_in[2];
    const float* W1    = (const float*)d_in[3];
    const float* b1    = (const float*)d_in[4];
    const float* gamma = (const float*)d_in[5];
    const float* beta  = (const float*)d_in[6];
    const float* mean  = (const float*)d_in[7];
    const float* var   = (const float*)d_in[8];
    const float* W3    = (const float*)d_in[9];
    const float* b3    = (const float*)d_in[10];
    const float* Wm1   = (const float*)d_in[11];
    const float* bm1   = (const float*)d_in[12];
    const float* Wm2   = (const float*)d_in[13];
    const float* bm2   = (const float*)d_in[14];

    const int n  = in_sizes[0] / FDIM;
    const int ne = in_sizes[1];

    int *deg, *off, *pos, *blk, *csrc;
    float *dinv, *w1t, *w3t;
    __half *hfeat, *hb0, *hb1, *hb2, *hb3;
    cudaGetSymbolAddress((void**)&deg,   g_deg);
    cudaGetSymbolAddress((void**)&off,   g_off);
    cudaGetSymbolAddress((void**)&pos,   g_pos);
    cudaGetSymbolAddress((void**)&blk,   g_blk);
    cudaGetSymbolAddress((void**)&csrc,  g_csrc);
    cudaGetSymbolAddress((void**)&dinv,  g_dinv);
    cudaGetSymbolAddress((void**)&hfeat, g_hfeat);
    cudaGetSymbolAddress((void**)&hb0,   g_hb0);
    cudaGetSymbolAddress((void**)&hb1,   g_hb1);
    cudaGetSymbolAddress((void**)&hb2,   g_hb2);
    cudaGetSymbolAddress((void**)&hb3,   g_hb3);
    cudaGetSymbolAddress((void**)&w1t,   g_w1t);
    cudaGetSymbolAddress((void**)&w3t,   g_w3t);

    const int nb      = (n + 511) / 512;
    const int agrid   = (n + 7) / 8;
    const int ggrid   = (n + 255) / 256;
    const int dblocks = (ne + 255) / 256;
    const int nelem   = n * FDIM;
    const int cblocks = (nelem / 8 + 255) / 256;

    const int SMEM_N128 = (2 * 256 * 36 + 2 * 128 * 36) * 4;  // 110592
    const int SMEM_HEAD = (256 * 132 + 64 * 132) * 4;          // 168960
    cudaFuncSetAttribute(k_gemm_tc<128, EPI_RELU_BN>,  cudaFuncAttributeMaxDynamicSharedMemorySize, SMEM_N128);
    cudaFuncSetAttribute(k_gemm_tc<128, EPI_RELU_RES>, cudaFuncAttributeMaxDynamicSharedMemorySize, SMEM_N128);
    cudaFuncSetAttribute(k_gemm_head,                  cudaFuncAttributeMaxDynamicSharedMemorySize, SMEM_HEAD);

    // ---- CSR build + feat conversion + weight transforms ----
    k_degi_cvt<<<dblocks + cblocks, 256>>>(edst, ne, deg, dblocks, feat, hfeat, nelem);
    k_scan1_wt<<<nb + 64, 512>>>(deg, n, nb, off, blk, dinv, W1, w1t, W3, w3t);
    k_scan3b<<<nb, 512>>>(off, pos, blk, nb, n, deg);
    k_bucket<<<(ne + 255) / 256, 256>>>(esrc, edst, ne, pos, csrc);

    // ---- Cheb layer 1: G0 = Ahat(feat), G1 = Ahat(G0) ----
    k_ahat_f16<<<agrid, 256>>>(hfeat, dinv, off, csrc, hb1, n);
    k_ahat_f16<<<agrid, 256>>>(hb1,   dinv, off, csrc, hb2, n);
    k_gemm_tc<128, EPI_RELU_BN><<<ggrid, 256, SMEM_N128>>>(
        hfeat, hb1, hb2, n, 384, w1t, b1, gamma, beta, mean, var,
        (const __half*)nullptr, hb0);

    // ---- Cheb layer 2 ----
    k_ahat_f16<<<agrid, 256>>>(hb0, dinv, off, csrc, hb1, n);
    k_ahat_f16<<<agrid, 256>>>(hb1, dinv, off, csrc, hb2, n);
    k_gemm_tc<128, EPI_RELU_RES><<<ggrid, 256, SMEM_N128>>>(
        hb0, hb1, hb2, n, 384, w3t, b3,
        (const float*)nullptr, (const float*)nullptr, (const float*)nullptr, (const float*)nullptr,
        hb0, hb3);

    // ---- fused MLP head ----
    k_gemm_head<<<ggrid, 256, SMEM_HEAD>>>(hb3, n, Wm1, bm1, Wm2, bm2, (float*)d_out);
}